// round 1
// baseline (speedup 1.0000x reference)
#include <cuda_runtime.h>
#include <cstdint>

#define BATCH 2
#define LSEQ 4096
#define DMODEL 768
#define HDIM 128
#define FLEN 2049
#define INV_SQRT_DK 0.08838834764831845f
#define GEPS 1e-9f

// ---------------- scratch ----------------
__device__ float  g_q [BATCH*HDIM*LSEQ];   // projected q, layout [b][d][l]
__device__ float  g_k [BATCH*HDIM*LSEQ];
__device__ float2 g_Qf[BATCH*HDIM*FLEN];   // rfft of q rows
__device__ float2 g_Kf[BATCH*HDIM*FLEN];
__device__ float  g_zq[BATCH*FLEN];        // selector gains
__device__ float  g_zk[BATCH*FLEN];
__device__ float  g_qf[BATCH*HDIM*LSEQ];   // filtered (irfft) q
__device__ float  g_kf[BATCH*HDIM*LSEQ];

// ---------------- projection GEMM: [8192 x 768] @ [768 x 128] -> [b][d][l] ----------------
// block: 128 l x 128 d tile, 256 threads, 8x8 microtile. ty -> d, tx -> l.
__global__ __launch_bounds__(256) void proj_kernel(
    const float* __restrict__ query, const float* __restrict__ key,
    const float* __restrict__ Wq, const float* __restrict__ bq,
    const float* __restrict__ Wk, const float* __restrict__ bk)
{
    const int tensor = blockIdx.y;
    const float* X  = tensor ? key : query;     // [8192][768]
    const float* W  = tensor ? Wk  : Wq;        // [128][768]
    const float* bi = tensor ? bk  : bq;        // [128]
    float* dst = tensor ? g_k : g_q;            // [(b*128+d)*4096 + l]

    const int l0 = blockIdx.x * 128;            // global row (b,l fused)
    __shared__ float Xs[16][128];               // [k][l]
    __shared__ float Ws[16][128];               // [k][d]

    const int tid = threadIdx.x;
    const int tx = tid & 15, ty = tid >> 4;

    float acc[8][8];
    #pragma unroll
    for (int i = 0; i < 8; i++)
        #pragma unroll
        for (int j = 0; j < 8; j++) acc[i][j] = 0.f;

    for (int k0 = 0; k0 < DMODEL; k0 += 16) {
        #pragma unroll
        for (int ii = 0; ii < 2; ii++) {
            int idx = tid * 2 + ii;              // 0..511
            int ll  = idx >> 2;
            int kq  = (idx & 3) << 2;
            float4 v = *(const float4*)(X + (size_t)(l0 + ll) * DMODEL + k0 + kq);
            Xs[kq + 0][ll] = v.x; Xs[kq + 1][ll] = v.y;
            Xs[kq + 2][ll] = v.z; Xs[kq + 3][ll] = v.w;
        }
        #pragma unroll
        for (int ii = 0; ii < 8; ii++) {
            int idx = tid + 256 * ii;            // 0..2047
            int kk = idx >> 7;
            int d  = idx & 127;
            Ws[kk][d] = W[(size_t)d * DMODEL + k0 + kk];
        }
        __syncthreads();

        #pragma unroll
        for (int kk = 0; kk < 16; kk++) {
            float rl[8], rd[8];
            #pragma unroll
            for (int j = 0; j < 8; j++) rl[j] = Xs[kk][tx * 8 + j];
            #pragma unroll
            for (int i = 0; i < 8; i++) rd[i] = Ws[kk][ty * 8 + i];
            #pragma unroll
            for (int i = 0; i < 8; i++)
                #pragma unroll
                for (int j = 0; j < 8; j++) acc[i][j] += rd[i] * rl[j];
        }
        __syncthreads();
    }

    const int gl = l0 + tx * 8;
    const int b  = gl >> 12;
    const int l  = gl & 4095;
    #pragma unroll
    for (int i = 0; i < 8; i++) {
        int d = ty * 8 + i;
        float bv = bi[d];
        float* o = dst + (size_t)((b << 7) + d) * LSEQ + l;
        float4 v0 = make_float4(acc[i][0]+bv, acc[i][1]+bv, acc[i][2]+bv, acc[i][3]+bv);
        float4 v1 = make_float4(acc[i][4]+bv, acc[i][5]+bv, acc[i][6]+bv, acc[i][7]+bv);
        *(float4*)(o)     = v0;
        *(float4*)(o + 4) = v1;
    }
}

// ---------------- in-shared 4096-pt complex FFT (radix-2 DIT, bit-reversed input) ----------------
__device__ __forceinline__ void fft4096(float2* s, int tid, float sign)
{
    #pragma unroll 1
    for (int half = 1; half < 4096; half <<= 1) {
        float step = sign * 3.14159265358979323846f / (float)half;
        #pragma unroll 1
        for (int t = tid; t < 2048; t += 256) {
            int pos = t & (half - 1);
            int i0  = 2 * t - pos;
            int i1  = i0 + half;
            float c, sn;
            sincosf(step * (float)pos, &sn, &c);
            float2 a = s[i0];
            float2 bb = s[i1];
            float br = bb.x * c - bb.y * sn;
            float bi = bb.x * sn + bb.y * c;
            s[i0] = make_float2(a.x + br, a.y + bi);
            s[i1] = make_float2(a.x - br, a.y - bi);
        }
        __syncthreads();
    }
}

__global__ __launch_bounds__(256) void fft_fwd_kernel()
{
    __shared__ float2 s[4096];
    const int blk = blockIdx.x;                 // 0..511
    const int tensor = blk >> 8;
    const int row = blk & 255;                  // b*128 + d
    const float* src = (tensor ? g_k : g_q) + (size_t)row * LSEQ;
    float2* dst = (tensor ? g_Kf : g_Qf) + (size_t)row * FLEN;
    const int tid = threadIdx.x;

    for (int i = tid; i < 4096; i += 256) {
        int r = __brev((unsigned)i) >> 20;
        s[r] = make_float2(src[i], 0.f);
    }
    __syncthreads();
    fft4096(s, tid, -1.f);
    for (int f = tid; f < FLEN; f += 256) dst[f] = s[f];
}

// ---------------- selector MLP: z[b,f] for q and k ----------------
__global__ void selector_kernel(
    const float* __restrict__ qW1, const float* __restrict__ qb1,
    const float* __restrict__ qW2, const float* __restrict__ qb2,
    const float* __restrict__ kW1, const float* __restrict__ kb1,
    const float* __restrict__ kW2, const float* __restrict__ kb2,
    const float* __restrict__ q_noise, const float* __restrict__ k_noise)
{
    const int f = blockIdx.x;
    const int b = blockIdx.y;
    const int tensor = blockIdx.z;
    const float2* Freq = tensor ? g_Kf : g_Qf;
    const float* W1 = tensor ? kW1 : qW1;
    const float* b1 = tensor ? kb1 : qb1;
    const float* W2 = tensor ? kW2 : qW2;
    const float* b2 = tensor ? kb2 : qb2;
    const float* nz = tensor ? k_noise : q_noise;
    float* z = tensor ? g_zk : g_zq;

    __shared__ float xr[128];
    __shared__ float h1[64];
    __shared__ float lg[2];
    const int tid = threadIdx.x;

    xr[tid] = Freq[(size_t)(b * 128 + tid) * FLEN + f].x;
    __syncthreads();

    if (tid < 64) {
        float acc = b1[tid];
        const float* w = W1 + (size_t)tid * 128;
        #pragma unroll 8
        for (int d = 0; d < 128; d++) acc += xr[d] * w[d];
        h1[tid] = fmaxf(acc, 0.f);
    }
    __syncthreads();
    if (tid < 2) {
        float acc = b2[tid];
        const float* w = W2 + tid * 64;
        #pragma unroll 8
        for (int j = 0; j < 64; j++) acc += h1[j] * w[j];
        float n = nz[((size_t)b * FLEN + f) * 2 + tid];
        float g = -logf(-logf(n + GEPS) + GEPS);
        lg[tid] = acc + g;                    // TEMP = 1
    }
    __syncthreads();
    if (tid == 0) z[b * FLEN + f] = 1.f / (1.f + expf(lg[0] - lg[1]));
}

// ---------------- inverse: Hermitian reconstruct * z, ifft, take real ----------------
__global__ __launch_bounds__(256) void fft_inv_kernel()
{
    __shared__ float2 s[4096];
    const int blk = blockIdx.x;
    const int tensor = blk >> 8;
    const int row = blk & 255;
    const int b = row >> 7;
    const float2* src = (tensor ? g_Kf : g_Qf) + (size_t)row * FLEN;
    const float* z = (tensor ? g_zk : g_zq) + (size_t)b * FLEN;
    float* dst = (tensor ? g_kf : g_qf) + (size_t)row * LSEQ;
    const int tid = threadIdx.x;

    for (int i = tid; i < 4096; i += 256) {
        int f = (i <= 2048) ? i : (4096 - i);
        float2 v = src[f];
        float zz = z[f];
        float2 y;
        y.x = v.x * zz;
        y.y = (i <= 2048) ? v.y * zz : -v.y * zz;
        s[__brev((unsigned)i) >> 20] = y;
    }
    __syncthreads();
    fft4096(s, tid, +1.f);
    const float inv = 1.f / 4096.f;
    for (int i = tid; i < 4096; i += 256) dst[i] = s[i].x * inv;
}

// ---------------- scores GEMM: C[b][l][m] = scale * sum_d qf[b][d][l]*kf[b][d][m] ----------------
__global__ __launch_bounds__(256) void gemm_scores_kernel(float* __restrict__ out)
{
    __shared__ float As[16][128];   // [k][l]
    __shared__ float Bs[16][128];   // [k][m]
    const int b  = blockIdx.z;
    const int l0 = blockIdx.y * 128;
    const int m0 = blockIdx.x * 128;
    const float* A = g_qf + (size_t)b * HDIM * LSEQ;   // A[d][l]
    const float* Bm = g_kf + (size_t)b * HDIM * LSEQ;  // B[d][m]

    const int tid = threadIdx.x;
    const int tx = tid & 15, ty = tid >> 4;            // ty -> l, tx -> m

    float acc[8][8];
    #pragma unroll
    for (int i = 0; i < 8; i++)
        #pragma unroll
        for (int j = 0; j < 8; j++) acc[i][j] = 0.f;

    for (int k0 = 0; k0 < HDIM; k0 += 16) {
        #pragma unroll
        for (int ii = 0; ii < 2; ii++) {
            int idx = tid * 2 + ii;          // 0..511
            int kk = idx >> 5;
            int c4 = (idx & 31) << 2;
            *(float4*)(&As[kk][c4]) = *(const float4*)(A  + (size_t)(k0 + kk) * LSEQ + l0 + c4);
            *(float4*)(&Bs[kk][c4]) = *(const float4*)(Bm + (size_t)(k0 + kk) * LSEQ + m0 + c4);
        }
        __syncthreads();
        #pragma unroll
        for (int kk = 0; kk < 16; kk++) {
            float ra[8], rb[8];
            #pragma unroll
            for (int i = 0; i < 8; i++) ra[i] = As[kk][ty * 8 + i];
            #pragma unroll
            for (int j = 0; j < 8; j++) rb[j] = Bs[kk][tx * 8 + j];
            #pragma unroll
            for (int i = 0; i < 8; i++)
                #pragma unroll
                for (int j = 0; j < 8; j++) acc[i][j] += ra[i] * rb[j];
        }
        __syncthreads();
    }

    #pragma unroll
    for (int i = 0; i < 8; i++) {
        float* o = out + (size_t)((size_t)b * LSEQ + l0 + ty * 8 + i) * LSEQ + m0 + tx * 8;
        float4 v0 = make_float4(acc[i][0]*INV_SQRT_DK, acc[i][1]*INV_SQRT_DK,
                                acc[i][2]*INV_SQRT_DK, acc[i][3]*INV_SQRT_DK);
        float4 v1 = make_float4(acc[i][4]*INV_SQRT_DK, acc[i][5]*INV_SQRT_DK,
                                acc[i][6]*INV_SQRT_DK, acc[i][7]*INV_SQRT_DK);
        *(float4*)(o)     = v0;
        *(float4*)(o + 4) = v1;
    }
}

// ---------------- masked row softmax, in place over d_out ----------------
__device__ __forceinline__ float warpMax(float v) {
    #pragma unroll
    for (int o = 16; o; o >>= 1) v = fmaxf(v, __shfl_xor_sync(0xffffffffu, v, o));
    return v;
}
__device__ __forceinline__ float warpSum(float v) {
    #pragma unroll
    for (int o = 16; o; o >>= 1) v += __shfl_xor_sync(0xffffffffu, v, o);
    return v;
}

__global__ __launch_bounds__(256) void softmax_kernel(float* __restrict__ out,
                                                      const int* __restrict__ mask)
{
    const int row = blockIdx.x;                 // b*4096 + l
    const int b = row >> 12;
    float* p = out + (size_t)row * LSEQ;
    const int* mrow = mask + (size_t)b * LSEQ;
    const int tid = threadIdx.x;

    __shared__ float red[8];
    __shared__ float bc;

    float v[16];
    float mx = -3.0e38f;
    #pragma unroll
    for (int i = 0; i < 16; i++) {
        int c = tid + 256 * i;
        float s = p[c];
        s = (mrow[c] == 0) ? -1.0e9f : s;
        v[i] = s;
        mx = fmaxf(mx, s);
    }
    mx = warpMax(mx);
    if ((tid & 31) == 0) red[tid >> 5] = mx;
    __syncthreads();
    if (tid < 32) {
        float m2 = (tid < 8) ? red[tid] : -3.0e38f;
        m2 = warpMax(m2);
        if (tid == 0) bc = m2;
    }
    __syncthreads();
    mx = bc;

    float sum = 0.f;
    #pragma unroll
    for (int i = 0; i < 16; i++) {
        v[i] = expf(v[i] - mx);
        sum += v[i];
    }
    sum = warpSum(sum);
    if ((tid & 31) == 0) red[tid >> 5] = sum;
    __syncthreads();
    if (tid < 32) {
        float s2 = (tid < 8) ? red[tid] : 0.f;
        s2 = warpSum(s2);
        if (tid == 0) bc = s2;
    }
    __syncthreads();
    const float inv = 1.f / bc;

    #pragma unroll
    for (int i = 0; i < 16; i++) p[tid + 256 * i] = v[i] * inv;
}

// ---------------- launch ----------------
extern "C" void kernel_launch(void* const* d_in, const int* in_sizes, int n_in,
                              void* d_out, int out_size)
{
    const float* query   = (const float*)d_in[0];
    const float* key     = (const float*)d_in[1];
    const int*   mask    = (const int*)  d_in[2];
    const float* Wq      = (const float*)d_in[3];
    const float* bq      = (const float*)d_in[4];
    const float* Wk      = (const float*)d_in[5];
    const float* bk      = (const float*)d_in[6];
    const float* qW1     = (const float*)d_in[7];
    const float* qb1     = (const float*)d_in[8];
    const float* qW2     = (const float*)d_in[9];
    const float* qb2     = (const float*)d_in[10];
    const float* kW1     = (const float*)d_in[11];
    const float* kb1     = (const float*)d_in[12];
    const float* kW2     = (const float*)d_in[13];
    const float* kb2     = (const float*)d_in[14];
    const float* q_noise = (const float*)d_in[15];
    const float* k_noise = (const float*)d_in[16];
    float* out = (float*)d_out;

    // 1. projection (q and k via blockIdx.y)
    proj_kernel<<<dim3(64, 2), 256>>>(query, key, Wq, bq, Wk, bk);
    // 2. forward FFT of all 512 rows
    fft_fwd_kernel<<<512, 256>>>();
    // 3. selector MLP gains
    selector_kernel<<<dim3(FLEN, BATCH, 2), 128>>>(qW1, qb1, qW2, qb2,
                                                   kW1, kb1, kW2, kb2,
                                                   q_noise, k_noise);
    // 4. filtered inverse FFT
    fft_inv_kernel<<<512, 256>>>();
    // 5. scores GEMM (includes 1/sqrt(dk) scale)
    gemm_scores_kernel<<<dim3(32, 32, BATCH), 256>>>(out);
    // 6. masked softmax in place
    softmax_kernel<<<BATCH * LSEQ, 256>>>(out, mask);
}

// round 2
// speedup vs baseline: 2.3821x; 2.3821x over previous
#include <cuda_runtime.h>
#include <cstdint>

#define BATCH 2
#define LSEQ 4096
#define DMODEL 768
#define HDIM 128
#define FLEN 2049
#define INV_SQRT_DK 0.08838834764831845f
#define GEPS 1e-9f
#define PI_F 3.14159265358979323846f

// ---------------- scratch ----------------
__device__ float  g_q [BATCH*HDIM*LSEQ];   // projected q, layout [b][d][l]
__device__ float  g_k [BATCH*HDIM*LSEQ];
__device__ float2 g_Qf[BATCH*HDIM*FLEN];   // rfft of q rows
__device__ float2 g_Kf[BATCH*HDIM*FLEN];
__device__ float  g_zq[BATCH*FLEN];        // selector gains
__device__ float  g_zk[BATCH*FLEN];
__device__ float  g_qf[BATCH*HDIM*LSEQ];   // filtered (irfft) q
__device__ float  g_kf[BATCH*HDIM*LSEQ];

// ---------------- projection GEMM: [8192 x 768] @ [768 x 128] -> [b][d][l] ----------------
__global__ __launch_bounds__(256) void proj_kernel(
    const float* __restrict__ query, const float* __restrict__ key,
    const float* __restrict__ Wq, const float* __restrict__ bq,
    const float* __restrict__ Wk, const float* __restrict__ bk)
{
    const int tensor = blockIdx.y;
    const float* X  = tensor ? key : query;     // [8192][768]
    const float* W  = tensor ? Wk  : Wq;        // [128][768]
    const float* bi = tensor ? bk  : bq;        // [128]
    float* dst = tensor ? g_k : g_q;            // [(b*128+d)*4096 + l]

    const int l0 = blockIdx.x * 128;
    __shared__ float Xs[16][128];               // [k][l]
    __shared__ float Ws[16][128];               // [k][d]

    const int tid = threadIdx.x;
    const int tx = tid & 15, ty = tid >> 4;

    float acc[8][8];
    #pragma unroll
    for (int i = 0; i < 8; i++)
        #pragma unroll
        for (int j = 0; j < 8; j++) acc[i][j] = 0.f;

    for (int k0 = 0; k0 < DMODEL; k0 += 16) {
        #pragma unroll
        for (int ii = 0; ii < 2; ii++) {
            int idx = tid * 2 + ii;
            int ll  = idx >> 2;
            int kq  = (idx & 3) << 2;
            float4 v = *(const float4*)(X + (size_t)(l0 + ll) * DMODEL + k0 + kq);
            Xs[kq + 0][ll] = v.x; Xs[kq + 1][ll] = v.y;
            Xs[kq + 2][ll] = v.z; Xs[kq + 3][ll] = v.w;
        }
        #pragma unroll
        for (int ii = 0; ii < 8; ii++) {
            int idx = tid + 256 * ii;
            int kk = idx >> 7;
            int d  = idx & 127;
            Ws[kk][d] = W[(size_t)d * DMODEL + k0 + kk];
        }
        __syncthreads();

        #pragma unroll
        for (int kk = 0; kk < 16; kk++) {
            float rl[8], rd[8];
            #pragma unroll
            for (int j = 0; j < 8; j++) rl[j] = Xs[kk][tx * 8 + j];
            #pragma unroll
            for (int i = 0; i < 8; i++) rd[i] = Ws[kk][ty * 8 + i];
            #pragma unroll
            for (int i = 0; i < 8; i++)
                #pragma unroll
                for (int j = 0; j < 8; j++) acc[i][j] += rd[i] * rl[j];
        }
        __syncthreads();
    }

    const int gl = l0 + tx * 8;
    const int b  = gl >> 12;
    const int l  = gl & 4095;
    #pragma unroll
    for (int i = 0; i < 8; i++) {
        int d = ty * 8 + i;
        float bv = bi[d];
        float* o = dst + (size_t)((b << 7) + d) * LSEQ + l;
        float4 v0 = make_float4(acc[i][0]+bv, acc[i][1]+bv, acc[i][2]+bv, acc[i][3]+bv);
        float4 v1 = make_float4(acc[i][4]+bv, acc[i][5]+bv, acc[i][6]+bv, acc[i][7]+bv);
        *(float4*)(o)     = v0;
        *(float4*)(o + 4) = v1;
    }
}

// ---------------- 4096-pt complex FFT with shared twiddle table ----------------
// tw[j] = exp(-2*pi*i*j/4096), j in [0,2048)
__device__ __forceinline__ void fill_tw(float2* tw, int tid)
{
    for (int j = tid; j < 2048; j += 256) {
        float ang = -PI_F * (float)j / 2048.0f;
        float s, c;
        __sincosf(ang, &s, &c);
        tw[j] = make_float2(c, s);
    }
}

__device__ __forceinline__ void fft4096_tw(float2* s, const float2* tw, int tid, bool inv)
{
    #pragma unroll 1
    for (int st = 0; st < 12; st++) {
        const int half = 1 << st;
        const int shift = 11 - st;
        #pragma unroll 1
        for (int t = tid; t < 2048; t += 256) {
            int pos = t & (half - 1);
            int i0  = 2 * t - pos;
            int i1  = i0 + half;
            float2 w = tw[pos << shift];
            float wy = inv ? -w.y : w.y;
            float2 a = s[i0];
            float2 bb = s[i1];
            float br = bb.x * w.x - bb.y * wy;
            float bi = bb.x * wy + bb.y * w.x;
            s[i0] = make_float2(a.x + br, a.y + bi);
            s[i1] = make_float2(a.x - br, a.y - bi);
        }
        __syncthreads();
    }
}

__global__ __launch_bounds__(256) void fft_fwd_kernel()
{
    __shared__ float2 s[4096];
    __shared__ float2 tw[2048];
    const int blk = blockIdx.x;                 // 0..511
    const int tensor = blk >> 8;
    const int row = blk & 255;                  // b*128 + d
    const float* src = (tensor ? g_k : g_q) + (size_t)row * LSEQ;
    float2* dst = (tensor ? g_Kf : g_Qf) + (size_t)row * FLEN;
    const int tid = threadIdx.x;

    fill_tw(tw, tid);
    for (int i = tid; i < 4096; i += 256) {
        int r = __brev((unsigned)i) >> 20;
        s[r] = make_float2(src[i], 0.f);
    }
    __syncthreads();
    fft4096_tw(s, tw, tid, false);
    for (int f = tid; f < FLEN; f += 256) dst[f] = s[f];
}

// ---------------- selector MLP: z[b,f], 16 freqs per block, W1 cached in smem ----------------
#define SEL_TF 16
__global__ __launch_bounds__(128) void selector_kernel(
    const float* __restrict__ qW1, const float* __restrict__ qb1,
    const float* __restrict__ qW2, const float* __restrict__ qb2,
    const float* __restrict__ kW1, const float* __restrict__ kb1,
    const float* __restrict__ kW2, const float* __restrict__ kb2,
    const float* __restrict__ q_noise, const float* __restrict__ k_noise)
{
    const int chunk = blockIdx.x;
    const int b = blockIdx.y;
    const int tensor = blockIdx.z;
    const float2* Freq = tensor ? g_Kf : g_Qf;
    const float* W1 = tensor ? kW1 : qW1;
    const float* b1 = tensor ? kb1 : qb1;
    const float* W2 = tensor ? kW2 : qW2;
    const float* b2 = tensor ? kb2 : qb2;
    const float* nz = tensor ? k_noise : q_noise;
    float* z = tensor ? g_zk : g_zq;

    __shared__ float W1s[64 * 128];
    __shared__ float xr[128];
    __shared__ float h1[64];
    __shared__ float lg[2];
    const int tid = threadIdx.x;

    for (int i = tid; i < 64 * 128; i += 128) W1s[i] = W1[i];
    __syncthreads();

    const int f0 = chunk * SEL_TF;
    for (int f = f0; f < f0 + SEL_TF && f < FLEN; f++) {
        xr[tid] = Freq[(size_t)(b * 128 + tid) * FLEN + f].x;
        __syncthreads();

        if (tid < 64) {
            float acc = b1[tid];
            const float* w = W1s + tid * 128;
            #pragma unroll 16
            for (int d = 0; d < 128; d++) acc += xr[d] * w[d];
            h1[tid] = fmaxf(acc, 0.f);
        }
        __syncthreads();
        if (tid < 2) {
            float acc = b2[tid];
            const float* w = W2 + tid * 64;
            #pragma unroll 8
            for (int j = 0; j < 64; j++) acc += h1[j] * w[j];
            float n = nz[((size_t)b * FLEN + f) * 2 + tid];
            float g = -logf(-logf(n + GEPS) + GEPS);
            lg[tid] = acc + g;
        }
        __syncthreads();
        if (tid == 0) z[b * FLEN + f] = 1.f / (1.f + expf(lg[0] - lg[1]));
        __syncthreads();
    }
}

// ---------------- inverse: Hermitian reconstruct * z, ifft, take real ----------------
__global__ __launch_bounds__(256) void fft_inv_kernel()
{
    __shared__ float2 s[4096];
    __shared__ float2 tw[2048];
    const int blk = blockIdx.x;
    const int tensor = blk >> 8;
    const int row = blk & 255;
    const int b = row >> 7;
    const float2* src = (tensor ? g_Kf : g_Qf) + (size_t)row * FLEN;
    const float* z = (tensor ? g_zk : g_zq) + (size_t)b * FLEN;
    float* dst = (tensor ? g_kf : g_qf) + (size_t)row * LSEQ;
    const int tid = threadIdx.x;

    fill_tw(tw, tid);
    for (int i = tid; i < 4096; i += 256) {
        int f = (i <= 2048) ? i : (4096 - i);
        float2 v = src[f];
        float zz = z[f];
        float2 y;
        y.x = v.x * zz;
        y.y = (i <= 2048) ? v.y * zz : -v.y * zz;
        s[__brev((unsigned)i) >> 20] = y;
    }
    __syncthreads();
    fft4096_tw(s, tw, tid, true);
    const float inv = 1.f / 4096.f;
    for (int i = tid; i < 4096; i += 256) dst[i] = s[i].x * inv;
}

// ---------------- scores GEMM via tf32 mma.sync ----------------
// C[b][l][m] = scale * sum_d qf[b][d][l] * kf[b][d][m]
// 128x128 block tile, BK=32, 8 warps: 2 (l) x 4 (n), warp tile 64x32.
__device__ __forceinline__ uint32_t f2tf32(float f) {
    uint32_t r;
    asm("cvt.rna.tf32.f32 %0, %1;" : "=r"(r) : "f"(f));
    return r;
}

__global__ __launch_bounds__(256) void gemm_scores_tc(float* __restrict__ out)
{
    __shared__ float As[32][136];   // [k][l], pad 136 -> conflict-free frag loads
    __shared__ float Bs[32][136];   // [k][m]
    const int b  = blockIdx.z;
    const int l0 = blockIdx.y * 128;
    const int m0 = blockIdx.x * 128;
    const float* A  = g_qf + (size_t)b * HDIM * LSEQ;
    const float* Bm = g_kf + (size_t)b * HDIM * LSEQ;

    const int tid  = threadIdx.x;
    const int warp = tid >> 5, lane = tid & 31;
    const int g = lane >> 2, tg = lane & 3;
    const int wl = (warp & 1) * 64;    // l offset of warp tile
    const int wn = (warp >> 1) * 32;   // n offset of warp tile

    float acc[4][4][4];
    #pragma unroll
    for (int i = 0; i < 4; i++)
        #pragma unroll
        for (int j = 0; j < 4; j++)
            #pragma unroll
            for (int c = 0; c < 4; c++) acc[i][j][c] = 0.f;

    for (int k0 = 0; k0 < HDIM; k0 += 32) {
        #pragma unroll
        for (int i = 0; i < 4; i++) {
            int linear = tid + 256 * i;          // 0..1023
            int row = linear >> 5;               // 0..31
            int col = (linear & 31) << 2;        // 0..124
            float4 va = *(const float4*)(A  + (size_t)(k0 + row) * LSEQ + l0 + col);
            float4 vb = *(const float4*)(Bm + (size_t)(k0 + row) * LSEQ + m0 + col);
            As[row][col+0] = __uint_as_float(f2tf32(va.x));
            As[row][col+1] = __uint_as_float(f2tf32(va.y));
            As[row][col+2] = __uint_as_float(f2tf32(va.z));
            As[row][col+3] = __uint_as_float(f2tf32(va.w));
            Bs[row][col+0] = __uint_as_float(f2tf32(vb.x));
            Bs[row][col+1] = __uint_as_float(f2tf32(vb.y));
            Bs[row][col+2] = __uint_as_float(f2tf32(vb.z));
            Bs[row][col+3] = __uint_as_float(f2tf32(vb.w));
        }
        __syncthreads();

        #pragma unroll
        for (int ks = 0; ks < 4; ks++) {
            const int k = ks * 8;
            uint32_t a[4][4], bf[4][2];
            #pragma unroll
            for (int i = 0; i < 4; i++) {
                int l = wl + i * 16 + g;
                a[i][0] = __float_as_uint(As[k + tg    ][l    ]);
                a[i][1] = __float_as_uint(As[k + tg    ][l + 8]);
                a[i][2] = __float_as_uint(As[k + tg + 4][l    ]);
                a[i][3] = __float_as_uint(As[k + tg + 4][l + 8]);
            }
            #pragma unroll
            for (int j = 0; j < 4; j++) {
                int n = wn + j * 8 + g;
                bf[j][0] = __float_as_uint(Bs[k + tg    ][n]);
                bf[j][1] = __float_as_uint(Bs[k + tg + 4][n]);
            }
            #pragma unroll
            for (int i = 0; i < 4; i++)
                #pragma unroll
                for (int j = 0; j < 4; j++) {
                    asm volatile(
                        "mma.sync.aligned.m16n8k8.row.col.f32.tf32.tf32.f32 "
                        "{%0,%1,%2,%3},{%4,%5,%6,%7},{%8,%9},{%0,%1,%2,%3};"
                        : "+f"(acc[i][j][0]), "+f"(acc[i][j][1]),
                          "+f"(acc[i][j][2]), "+f"(acc[i][j][3])
                        : "r"(a[i][0]), "r"(a[i][1]), "r"(a[i][2]), "r"(a[i][3]),
                          "r"(bf[j][0]), "r"(bf[j][1]));
                }
        }
        __syncthreads();
    }

    #pragma unroll
    for (int i = 0; i < 4; i++) {
        int row0 = l0 + wl + i * 16 + g;
        #pragma unroll
        for (int j = 0; j < 4; j++) {
            int col = m0 + wn + j * 8 + 2 * tg;
            float2 v0 = make_float2(acc[i][j][0] * INV_SQRT_DK, acc[i][j][1] * INV_SQRT_DK);
            float2 v1 = make_float2(acc[i][j][2] * INV_SQRT_DK, acc[i][j][3] * INV_SQRT_DK);
            *(float2*)(out + ((size_t)b * LSEQ + row0    ) * LSEQ + col) = v0;
            *(float2*)(out + ((size_t)b * LSEQ + row0 + 8) * LSEQ + col) = v1;
        }
    }
}

// ---------------- masked row softmax, in place over d_out ----------------
__device__ __forceinline__ float warpMax(float v) {
    #pragma unroll
    for (int o = 16; o; o >>= 1) v = fmaxf(v, __shfl_xor_sync(0xffffffffu, v, o));
    return v;
}
__device__ __forceinline__ float warpSum(float v) {
    #pragma unroll
    for (int o = 16; o; o >>= 1) v += __shfl_xor_sync(0xffffffffu, v, o);
    return v;
}

__global__ __launch_bounds__(256) void softmax_kernel(float* __restrict__ out,
                                                      const int* __restrict__ mask)
{
    const int row = blockIdx.x;                 // b*4096 + l
    const int b = row >> 12;
    float* p = out + (size_t)row * LSEQ;
    const int* mrow = mask + (size_t)b * LSEQ;
    const int tid = threadIdx.x;

    __shared__ float red[8];
    __shared__ float bc;

    float4 v[4];
    float mx = -3.0e38f;
    #pragma unroll
    for (int i = 0; i < 4; i++) {
        int c4 = tid + 256 * i;                 // float4 index
        float4 s = ((const float4*)p)[c4];
        int4 m = ((const int4*)mrow)[c4];
        s.x = (m.x == 0) ? -1.0e9f : s.x;
        s.y = (m.y == 0) ? -1.0e9f : s.y;
        s.z = (m.z == 0) ? -1.0e9f : s.z;
        s.w = (m.w == 0) ? -1.0e9f : s.w;
        v[i] = s;
        mx = fmaxf(mx, fmaxf(fmaxf(s.x, s.y), fmaxf(s.z, s.w)));
    }
    mx = warpMax(mx);
    if ((tid & 31) == 0) red[tid >> 5] = mx;
    __syncthreads();
    if (tid < 32) {
        float m2 = (tid < 8) ? red[tid] : -3.0e38f;
        m2 = warpMax(m2);
        if (tid == 0) bc = m2;
    }
    __syncthreads();
    mx = bc;

    float sum = 0.f;
    #pragma unroll
    for (int i = 0; i < 4; i++) {
        v[i].x = expf(v[i].x - mx);
        v[i].y = expf(v[i].y - mx);
        v[i].z = expf(v[i].z - mx);
        v[i].w = expf(v[i].w - mx);
        sum += v[i].x + v[i].y + v[i].z + v[i].w;
    }
    sum = warpSum(sum);
    if ((tid & 31) == 0) red[tid >> 5] = sum;
    __syncthreads();
    if (tid < 32) {
        float s2 = (tid < 8) ? red[tid] : 0.f;
        s2 = warpSum(s2);
        if (tid == 0) bc = s2;
    }
    __syncthreads();
    const float inv = 1.f / bc;

    #pragma unroll
    for (int i = 0; i < 4; i++) {
        float4 o = make_float4(v[i].x * inv, v[i].y * inv, v[i].z * inv, v[i].w * inv);
        ((float4*)p)[tid + 256 * i] = o;
    }
}

// ---------------- launch ----------------
extern "C" void kernel_launch(void* const* d_in, const int* in_sizes, int n_in,
                              void* d_out, int out_size)
{
    const float* query   = (const float*)d_in[0];
    const float* key     = (const float*)d_in[1];
    const int*   mask    = (const int*)  d_in[2];
    const float* Wq      = (const float*)d_in[3];
    const float* bq      = (const float*)d_in[4];
    const float* Wk      = (const float*)d_in[5];
    const float* bk      = (const float*)d_in[6];
    const float* qW1     = (const float*)d_in[7];
    const float* qb1     = (const float*)d_in[8];
    const float* qW2     = (const float*)d_in[9];
    const float* qb2     = (const float*)d_in[10];
    const float* kW1     = (const float*)d_in[11];
    const float* kb1     = (const float*)d_in[12];
    const float* kW2     = (const float*)d_in[13];
    const float* kb2     = (const float*)d_in[14];
    const float* q_noise = (const float*)d_in[15];
    const float* k_noise = (const float*)d_in[16];
    float* out = (float*)d_out;

    proj_kernel<<<dim3(64, 2), 256>>>(query, key, Wq, bq, Wk, bk);
    fft_fwd_kernel<<<512, 256>>>();
    selector_kernel<<<dim3((FLEN + SEL_TF - 1) / SEL_TF, BATCH, 2), 128>>>(
        qW1, qb1, qW2, qb2, kW1, kb1, kW2, kb2, q_noise, k_noise);
    fft_inv_kernel<<<512, 256>>>();
    gemm_scores_tc<<<dim3(32, 32, BATCH), 256>>>(out);
    softmax_kernel<<<BATCH * LSEQ, 256>>>(out, mask);
}

// round 3
// speedup vs baseline: 3.2755x; 1.3750x over previous
#include <cuda_runtime.h>
#include <cstdint>

#define BATCH 2
#define LSEQ 4096
#define DMODEL 768
#define HDIM 128
#define FLEN 2049
#define INV_SQRT_DK 0.08838834764831845f
#define GEPS 1e-9f
#define PI_F 3.14159265358979323846f

// ---------------- scratch ----------------
__device__ float  g_q [BATCH*HDIM*LSEQ];   // projected q, layout [b][d][l]
__device__ float  g_k [BATCH*HDIM*LSEQ];
__device__ float2 g_Qf[BATCH*HDIM*FLEN];   // rfft of q rows
__device__ float2 g_Kf[BATCH*HDIM*FLEN];
__device__ float  g_zq[BATCH*FLEN];        // selector gains
__device__ float  g_zk[BATCH*FLEN];
__device__ float  g_qf[BATCH*HDIM*LSEQ];   // filtered (irfft) q
__device__ float  g_kf[BATCH*HDIM*LSEQ];

__device__ __forceinline__ uint32_t f2tf32(float f) {
    uint32_t r;
    asm("cvt.rna.tf32.f32 %0, %1;" : "=r"(r) : "f"(f));
    return r;
}

// ---------------- projection GEMM (tf32 tensor cores) ----------------
// C[l][d] = X[l][:] . W[d][:] + b[d], stored as dst[b][d][l].
// Block tile: 128 l x 128 d, K=768. 8 warps: m(=d) 2 x n(=l) 4, warp tile 64d x 32l.
__global__ __launch_bounds__(256) void proj_tc(
    const float* __restrict__ query, const float* __restrict__ key,
    const float* __restrict__ Wq, const float* __restrict__ bq,
    const float* __restrict__ Wk, const float* __restrict__ bk)
{
    const int tensor = blockIdx.y;
    const float* X  = tensor ? key : query;     // [8192][768]
    const float* W  = tensor ? Wk  : Wq;        // [128][768]
    const float* bi = tensor ? bk  : bq;        // [128]
    float* dst = tensor ? g_k : g_q;

    const int l0 = blockIdx.x * 128;

    __shared__ float Ds[32][136];   // [k][d]  (A operand, m = d)
    __shared__ float Ls[32][136];   // [k][l]  (B operand, n = l)

    const int tid  = threadIdx.x;
    const int warp = tid >> 5, lane = tid & 31;
    const int g = lane >> 2, tg = lane & 3;
    const int wd = (warp & 1) * 64;    // d offset of warp tile
    const int wn = (warp >> 1) * 32;   // l offset of warp tile

    float acc[4][4][4];
    #pragma unroll
    for (int i = 0; i < 4; i++)
        #pragma unroll
        for (int j = 0; j < 4; j++)
            #pragma unroll
            for (int c = 0; c < 4; c++) acc[i][j][c] = 0.f;

    for (int k0 = 0; k0 < DMODEL; k0 += 32) {
        // fill Ds: W[d][k0+kk]  and Ls: X[l0+l][k0+kk], float4 along k
        #pragma unroll
        for (int ii = 0; ii < 4; ii++) {
            int idx = tid + 256 * ii;            // 0..1023
            int r   = idx >> 3;                  // 0..127 (d or l)
            int kq  = (idx & 7) << 2;            // 0..28
            float4 w = *(const float4*)(W + (size_t)r * DMODEL + k0 + kq);
            Ds[kq+0][r] = __uint_as_float(f2tf32(w.x));
            Ds[kq+1][r] = __uint_as_float(f2tf32(w.y));
            Ds[kq+2][r] = __uint_as_float(f2tf32(w.z));
            Ds[kq+3][r] = __uint_as_float(f2tf32(w.w));
            float4 x = *(const float4*)(X + (size_t)(l0 + r) * DMODEL + k0 + kq);
            Ls[kq+0][r] = __uint_as_float(f2tf32(x.x));
            Ls[kq+1][r] = __uint_as_float(f2tf32(x.y));
            Ls[kq+2][r] = __uint_as_float(f2tf32(x.z));
            Ls[kq+3][r] = __uint_as_float(f2tf32(x.w));
        }
        __syncthreads();

        #pragma unroll
        for (int ks = 0; ks < 4; ks++) {
            const int k = ks * 8;
            uint32_t a[4][4], bf[4][2];
            #pragma unroll
            for (int i = 0; i < 4; i++) {
                int d = wd + i * 16 + g;
                a[i][0] = __float_as_uint(Ds[k + tg    ][d    ]);
                a[i][1] = __float_as_uint(Ds[k + tg    ][d + 8]);
                a[i][2] = __float_as_uint(Ds[k + tg + 4][d    ]);
                a[i][3] = __float_as_uint(Ds[k + tg + 4][d + 8]);
            }
            #pragma unroll
            for (int j = 0; j < 4; j++) {
                int n = wn + j * 8 + g;
                bf[j][0] = __float_as_uint(Ls[k + tg    ][n]);
                bf[j][1] = __float_as_uint(Ls[k + tg + 4][n]);
            }
            #pragma unroll
            for (int i = 0; i < 4; i++)
                #pragma unroll
                for (int j = 0; j < 4; j++) {
                    asm volatile(
                        "mma.sync.aligned.m16n8k8.row.col.f32.tf32.tf32.f32 "
                        "{%0,%1,%2,%3},{%4,%5,%6,%7},{%8,%9},{%0,%1,%2,%3};"
                        : "+f"(acc[i][j][0]), "+f"(acc[i][j][1]),
                          "+f"(acc[i][j][2]), "+f"(acc[i][j][3])
                        : "r"(a[i][0]), "r"(a[i][1]), "r"(a[i][2]), "r"(a[i][3]),
                          "r"(bf[j][0]), "r"(bf[j][1]));
                }
        }
        __syncthreads();
    }

    // epilogue: c0,c1 -> row d=wd+i*16+g, cols l=..2tg,2tg+1 ; c2,c3 -> d+8
    #pragma unroll
    for (int i = 0; i < 4; i++) {
        int d0 = wd + i * 16 + g;
        float bv0 = bi[d0], bv1 = bi[d0 + 8];
        #pragma unroll
        for (int j = 0; j < 4; j++) {
            int gl = l0 + wn + j * 8 + 2 * tg;
            int b  = gl >> 12;
            int l  = gl & 4095;
            float* o0 = dst + (size_t)((b << 7) + d0    ) * LSEQ + l;
            float* o1 = dst + (size_t)((b << 7) + d0 + 8) * LSEQ + l;
            *(float2*)o0 = make_float2(acc[i][j][0] + bv0, acc[i][j][1] + bv0);
            *(float2*)o1 = make_float2(acc[i][j][2] + bv1, acc[i][j][3] + bv1);
        }
    }
}

// ---------------- 4096-pt complex FFT with shared twiddle table ----------------
__device__ __forceinline__ void fill_tw(float2* tw, int tid)
{
    for (int j = tid; j < 2048; j += 256) {
        float ang = -PI_F * (float)j / 2048.0f;
        float s, c;
        __sincosf(ang, &s, &c);
        tw[j] = make_float2(c, s);
    }
}

__device__ __forceinline__ void fft4096_tw(float2* s, const float2* tw, int tid, bool inv)
{
    #pragma unroll 1
    for (int st = 0; st < 12; st++) {
        const int half = 1 << st;
        const int shift = 11 - st;
        #pragma unroll 1
        for (int t = tid; t < 2048; t += 256) {
            int pos = t & (half - 1);
            int i0  = 2 * t - pos;
            int i1  = i0 + half;
            float2 w = tw[pos << shift];
            float wy = inv ? -w.y : w.y;
            float2 a = s[i0];
            float2 bb = s[i1];
            float br = bb.x * w.x - bb.y * wy;
            float bi = bb.x * wy + bb.y * w.x;
            s[i0] = make_float2(a.x + br, a.y + bi);
            s[i1] = make_float2(a.x - br, a.y - bi);
        }
        __syncthreads();
    }
}

// forward: pack 2 real rows (2j, 2j+1) as one complex FFT, Hermitian unpack.
__global__ __launch_bounds__(256) void fft_fwd_kernel()
{
    __shared__ float2 s[4096];
    __shared__ float2 tw[2048];
    const int blk = blockIdx.x;                 // 0..255
    const int tensor = blk >> 7;
    const int pr = blk & 127;                   // b*64 + j
    const int b = pr >> 6;
    const int j = pr & 63;
    const int row0 = b * 128 + 2 * j;
    const float* src0 = (tensor ? g_k : g_q) + (size_t)row0 * LSEQ;
    const float* src1 = src0 + LSEQ;
    float2* dst0 = (tensor ? g_Kf : g_Qf) + (size_t)row0 * FLEN;
    float2* dst1 = dst0 + FLEN;
    const int tid = threadIdx.x;

    fill_tw(tw, tid);
    for (int i = tid; i < 4096; i += 256) {
        int r = __brev((unsigned)i) >> 20;
        s[r] = make_float2(src0[i], src1[i]);
    }
    __syncthreads();
    fft4096_tw(s, tw, tid, false);

    for (int f = tid; f < FLEN; f += 256) {
        float2 cf = s[f];
        float2 cn = s[(4096 - f) & 4095];
        dst0[f] = make_float2(0.5f * (cf.x + cn.x), 0.5f * (cf.y - cn.y));
        dst1[f] = make_float2(0.5f * (cf.y + cn.y), 0.5f * (cn.x - cf.x));
    }
}

// ---------------- selector MLP: z[b,f], 16 freqs per block, W1 cached in smem ----------------
#define SEL_TF 16
__global__ __launch_bounds__(128) void selector_kernel(
    const float* __restrict__ qW1, const float* __restrict__ qb1,
    const float* __restrict__ qW2, const float* __restrict__ qb2,
    const float* __restrict__ kW1, const float* __restrict__ kb1,
    const float* __restrict__ kW2, const float* __restrict__ kb2,
    const float* __restrict__ q_noise, const float* __restrict__ k_noise)
{
    const int chunk = blockIdx.x;
    const int b = blockIdx.y;
    const int tensor = blockIdx.z;
    const float2* Freq = tensor ? g_Kf : g_Qf;
    const float* W1 = tensor ? kW1 : qW1;
    const float* b1 = tensor ? kb1 : qb1;
    const float* W2 = tensor ? kW2 : qW2;
    const float* b2 = tensor ? kb2 : qb2;
    const float* nz = tensor ? k_noise : q_noise;
    float* z = tensor ? g_zk : g_zq;

    __shared__ float W1s[64 * 128];
    __shared__ float xr[128];
    __shared__ float h1[64];
    __shared__ float lg[2];
    const int tid = threadIdx.x;

    for (int i = tid; i < 64 * 128; i += 128) W1s[i] = W1[i];
    __syncthreads();

    const int f0 = chunk * SEL_TF;
    for (int f = f0; f < f0 + SEL_TF && f < FLEN; f++) {
        xr[tid] = Freq[(size_t)(b * 128 + tid) * FLEN + f].x;
        __syncthreads();

        if (tid < 64) {
            float acc = b1[tid];
            const float* w = W1s + tid * 128;
            #pragma unroll 16
            for (int d = 0; d < 128; d++) acc += xr[d] * w[d];
            h1[tid] = fmaxf(acc, 0.f);
        }
        __syncthreads();
        if (tid < 2) {
            float acc = b2[tid];
            const float* w = W2 + tid * 64;
            #pragma unroll 8
            for (int j = 0; j < 64; j++) acc += h1[j] * w[j];
            float n = nz[((size_t)b * FLEN + f) * 2 + tid];
            float g = -logf(-logf(n + GEPS) + GEPS);
            lg[tid] = acc + g;
        }
        __syncthreads();
        if (tid == 0) z[b * FLEN + f] = 1.f / (1.f + expf(lg[0] - lg[1]));
        __syncthreads();
    }
}

// inverse: pack 2 filtered rows per complex iFFT. C[n] = A'[n] + i B'[n].
__global__ __launch_bounds__(256) void fft_inv_kernel()
{
    __shared__ float2 s[4096];
    __shared__ float2 tw[2048];
    const int blk = blockIdx.x;                 // 0..255
    const int tensor = blk >> 7;
    const int pr = blk & 127;
    const int b = pr >> 6;
    const int j = pr & 63;
    const int row0 = b * 128 + 2 * j;
    const float2* src0 = (tensor ? g_Kf : g_Qf) + (size_t)row0 * FLEN;
    const float2* src1 = src0 + FLEN;
    const float* z = (tensor ? g_zk : g_zq) + (size_t)b * FLEN;
    float* dst0 = (tensor ? g_kf : g_qf) + (size_t)row0 * LSEQ;
    float* dst1 = dst0 + LSEQ;
    const int tid = threadIdx.x;

    fill_tw(tw, tid);
    for (int i = tid; i < 4096; i += 256) {
        int f = (i <= 2048) ? i : (4096 - i);
        float zz = z[f];
        float2 a = src0[f];
        float2 bb = src1[f];
        if (i > 2048) { a.y = -a.y; bb.y = -bb.y; }
        a.x *= zz; a.y *= zz; bb.x *= zz; bb.y *= zz;
        s[__brev((unsigned)i) >> 20] = make_float2(a.x - bb.y, a.y + bb.x);
    }
    __syncthreads();
    fft4096_tw(s, tw, tid, true);
    const float inv = 1.f / 4096.f;
    for (int i = tid; i < 4096; i += 256) {
        float2 v = s[i];
        dst0[i] = v.x * inv;
        dst1[i] = v.y * inv;
    }
}

// ---------------- scores GEMM via tf32 mma.sync ----------------
__global__ __launch_bounds__(256) void gemm_scores_tc(float* __restrict__ out)
{
    __shared__ float As[32][136];   // [k][l]
    __shared__ float Bs[32][136];   // [k][m]
    const int b  = blockIdx.z;
    const int l0 = blockIdx.y * 128;
    const int m0 = blockIdx.x * 128;
    const float* A  = g_qf + (size_t)b * HDIM * LSEQ;
    const float* Bm = g_kf + (size_t)b * HDIM * LSEQ;

    const int tid  = threadIdx.x;
    const int warp = tid >> 5, lane = tid & 31;
    const int g = lane >> 2, tg = lane & 3;
    const int wl = (warp & 1) * 64;
    const int wn = (warp >> 1) * 32;

    float acc[4][4][4];
    #pragma unroll
    for (int i = 0; i < 4; i++)
        #pragma unroll
        for (int j = 0; j < 4; j++)
            #pragma unroll
            for (int c = 0; c < 4; c++) acc[i][j][c] = 0.f;

    for (int k0 = 0; k0 < HDIM; k0 += 32) {
        #pragma unroll
        for (int i = 0; i < 4; i++) {
            int linear = tid + 256 * i;
            int row = linear >> 5;
            int col = (linear & 31) << 2;
            float4 va = *(const float4*)(A  + (size_t)(k0 + row) * LSEQ + l0 + col);
            float4 vb = *(const float4*)(Bm + (size_t)(k0 + row) * LSEQ + m0 + col);
            As[row][col+0] = __uint_as_float(f2tf32(va.x));
            As[row][col+1] = __uint_as_float(f2tf32(va.y));
            As[row][col+2] = __uint_as_float(f2tf32(va.z));
            As[row][col+3] = __uint_as_float(f2tf32(va.w));
            Bs[row][col+0] = __uint_as_float(f2tf32(vb.x));
            Bs[row][col+1] = __uint_as_float(f2tf32(vb.y));
            Bs[row][col+2] = __uint_as_float(f2tf32(vb.z));
            Bs[row][col+3] = __uint_as_float(f2tf32(vb.w));
        }
        __syncthreads();

        #pragma unroll
        for (int ks = 0; ks < 4; ks++) {
            const int k = ks * 8;
            uint32_t a[4][4], bf[4][2];
            #pragma unroll
            for (int i = 0; i < 4; i++) {
                int l = wl + i * 16 + g;
                a[i][0] = __float_as_uint(As[k + tg    ][l    ]);
                a[i][1] = __float_as_uint(As[k + tg    ][l + 8]);
                a[i][2] = __float_as_uint(As[k + tg + 4][l    ]);
                a[i][3] = __float_as_uint(As[k + tg + 4][l + 8]);
            }
            #pragma unroll
            for (int j = 0; j < 4; j++) {
                int n = wn + j * 8 + g;
                bf[j][0] = __float_as_uint(Bs[k + tg    ][n]);
                bf[j][1] = __float_as_uint(Bs[k + tg + 4][n]);
            }
            #pragma unroll
            for (int i = 0; i < 4; i++)
                #pragma unroll
                for (int j = 0; j < 4; j++) {
                    asm volatile(
                        "mma.sync.aligned.m16n8k8.row.col.f32.tf32.tf32.f32 "
                        "{%0,%1,%2,%3},{%4,%5,%6,%7},{%8,%9},{%0,%1,%2,%3};"
                        : "+f"(acc[i][j][0]), "+f"(acc[i][j][1]),
                          "+f"(acc[i][j][2]), "+f"(acc[i][j][3])
                        : "r"(a[i][0]), "r"(a[i][1]), "r"(a[i][2]), "r"(a[i][3]),
                          "r"(bf[j][0]), "r"(bf[j][1]));
                }
        }
        __syncthreads();
    }

    #pragma unroll
    for (int i = 0; i < 4; i++) {
        int row0 = l0 + wl + i * 16 + g;
        #pragma unroll
        for (int j = 0; j < 4; j++) {
            int col = m0 + wn + j * 8 + 2 * tg;
            float2 v0 = make_float2(acc[i][j][0] * INV_SQRT_DK, acc[i][j][1] * INV_SQRT_DK);
            float2 v1 = make_float2(acc[i][j][2] * INV_SQRT_DK, acc[i][j][3] * INV_SQRT_DK);
            *(float2*)(out + ((size_t)b * LSEQ + row0    ) * LSEQ + col) = v0;
            *(float2*)(out + ((size_t)b * LSEQ + row0 + 8) * LSEQ + col) = v1;
        }
    }
}

// ---------------- masked row softmax, in place over d_out ----------------
__device__ __forceinline__ float warpMax(float v) {
    #pragma unroll
    for (int o = 16; o; o >>= 1) v = fmaxf(v, __shfl_xor_sync(0xffffffffu, v, o));
    return v;
}
__device__ __forceinline__ float warpSum(float v) {
    #pragma unroll
    for (int o = 16; o; o >>= 1) v += __shfl_xor_sync(0xffffffffu, v, o);
    return v;
}

__global__ __launch_bounds__(256) void softmax_kernel(float* __restrict__ out,
                                                      const int* __restrict__ mask)
{
    const int row = blockIdx.x;
    const int b = row >> 12;
    float* p = out + (size_t)row * LSEQ;
    const int* mrow = mask + (size_t)b * LSEQ;
    const int tid = threadIdx.x;

    __shared__ float red[8];
    __shared__ float bc;

    float4 v[4];
    float mx = -3.0e38f;
    #pragma unroll
    for (int i = 0; i < 4; i++) {
        int c4 = tid + 256 * i;
        float4 s = ((const float4*)p)[c4];
        int4 m = ((const int4*)mrow)[c4];
        s.x = (m.x == 0) ? -1.0e9f : s.x;
        s.y = (m.y == 0) ? -1.0e9f : s.y;
        s.z = (m.z == 0) ? -1.0e9f : s.z;
        s.w = (m.w == 0) ? -1.0e9f : s.w;
        v[i] = s;
        mx = fmaxf(mx, fmaxf(fmaxf(s.x, s.y), fmaxf(s.z, s.w)));
    }
    mx = warpMax(mx);
    if ((tid & 31) == 0) red[tid >> 5] = mx;
    __syncthreads();
    if (tid < 32) {
        float m2 = (tid < 8) ? red[tid] : -3.0e38f;
        m2 = warpMax(m2);
        if (tid == 0) bc = m2;
    }
    __syncthreads();
    mx = bc;

    float sum = 0.f;
    #pragma unroll
    for (int i = 0; i < 4; i++) {
        v[i].x = expf(v[i].x - mx);
        v[i].y = expf(v[i].y - mx);
        v[i].z = expf(v[i].z - mx);
        v[i].w = expf(v[i].w - mx);
        sum += v[i].x + v[i].y + v[i].z + v[i].w;
    }
    sum = warpSum(sum);
    if ((tid & 31) == 0) red[tid >> 5] = sum;
    __syncthreads();
    if (tid < 32) {
        float s2 = (tid < 8) ? red[tid] : 0.f;
        s2 = warpSum(s2);
        if (tid == 0) bc = s2;
    }
    __syncthreads();
    const float inv = 1.f / bc;

    #pragma unroll
    for (int i = 0; i < 4; i++) {
        float4 o = make_float4(v[i].x * inv, v[i].y * inv, v[i].z * inv, v[i].w * inv);
        ((float4*)p)[tid + 256 * i] = o;
    }
}

// ---------------- launch ----------------
extern "C" void kernel_launch(void* const* d_in, const int* in_sizes, int n_in,
                              void* d_out, int out_size)
{
    const float* query   = (const float*)d_in[0];
    const float* key     = (const float*)d_in[1];
    const int*   mask    = (const int*)  d_in[2];
    const float* Wq      = (const float*)d_in[3];
    const float* bq      = (const float*)d_in[4];
    const float* Wk      = (const float*)d_in[5];
    const float* bk      = (const float*)d_in[6];
    const float* qW1     = (const float*)d_in[7];
    const float* qb1     = (const float*)d_in[8];
    const float* qW2     = (const float*)d_in[9];
    const float* qb2     = (const float*)d_in[10];
    const float* kW1     = (const float*)d_in[11];
    const float* kb1     = (const float*)d_in[12];
    const float* kW2     = (const float*)d_in[13];
    const float* kb2     = (const float*)d_in[14];
    const float* q_noise = (const float*)d_in[15];
    const float* k_noise = (const float*)d_in[16];
    float* out = (float*)d_out;

    proj_tc<<<dim3(64, 2), 256>>>(query, key, Wq, bq, Wk, bk);
    fft_fwd_kernel<<<256, 256>>>();
    selector_kernel<<<dim3((FLEN + SEL_TF - 1) / SEL_TF, BATCH, 2), 128>>>(
        qW1, qb1, qW2, qb2, kW1, kb1, kW2, kb2, q_noise, k_noise);
    fft_inv_kernel<<<256, 256>>>();
    gemm_scores_tc<<<dim3(32, 32, BATCH), 256>>>(out);
    softmax_kernel<<<BATCH * LSEQ, 256>>>(out, mask);
}

// round 4
// speedup vs baseline: 3.6142x; 1.1034x over previous
#include <cuda_runtime.h>
#include <cuda_bf16.h>
#include <cstdint>

#define BATCH 2
#define LSEQ 4096
#define DMODEL 768
#define HDIM 128
#define FLEN 2049
#define INV_SQRT_DK 0.08838834764831845f
#define GEPS 1e-9f
#define PI_F 3.14159265358979323846f

// ---------------- scratch ----------------
__device__ float  g_q [BATCH*HDIM*LSEQ];   // projected q, layout [b][d][l]
__device__ float  g_k [BATCH*HDIM*LSEQ];
__device__ float2 g_Qf[BATCH*HDIM*FLEN];   // rfft of q rows
__device__ float2 g_Kf[BATCH*HDIM*FLEN];
__device__ float  g_zq[BATCH*FLEN];        // selector gains
__device__ float  g_zk[BATCH*FLEN];
__device__ float  g_qf[BATCH*HDIM*LSEQ];   // filtered (irfft) q
__device__ float  g_kf[BATCH*HDIM*LSEQ];

__device__ __forceinline__ uint32_t f2tf32(float f) {
    uint32_t r;
    asm("cvt.rna.tf32.f32 %0, %1;" : "=r"(r) : "f"(f));
    return r;
}
__device__ __forceinline__ uint32_t sptr(const void* p) {
    return (uint32_t)__cvta_generic_to_shared(p);
}

// ---------------- projection GEMM (tf32 tensor cores) ----------------
__global__ __launch_bounds__(256) void proj_tc(
    const float* __restrict__ query, const float* __restrict__ key,
    const float* __restrict__ Wq, const float* __restrict__ bq,
    const float* __restrict__ Wk, const float* __restrict__ bk)
{
    const int tensor = blockIdx.y;
    const float* X  = tensor ? key : query;     // [8192][768]
    const float* W  = tensor ? Wk  : Wq;        // [128][768]
    const float* bi = tensor ? bk  : bq;        // [128]
    float* dst = tensor ? g_k : g_q;

    const int l0 = blockIdx.x * 128;

    __shared__ float Ds[32][136];   // [k][d]
    __shared__ float Ls[32][136];   // [k][l]

    const int tid  = threadIdx.x;
    const int warp = tid >> 5, lane = tid & 31;
    const int g = lane >> 2, tg = lane & 3;
    const int wd = (warp & 1) * 64;
    const int wn = (warp >> 1) * 32;

    float acc[4][4][4];
    #pragma unroll
    for (int i = 0; i < 4; i++)
        #pragma unroll
        for (int j = 0; j < 4; j++)
            #pragma unroll
            for (int c = 0; c < 4; c++) acc[i][j][c] = 0.f;

    for (int k0 = 0; k0 < DMODEL; k0 += 32) {
        #pragma unroll
        for (int ii = 0; ii < 4; ii++) {
            int idx = tid + 256 * ii;
            int r   = idx >> 3;
            int kq  = (idx & 7) << 2;
            float4 w = *(const float4*)(W + (size_t)r * DMODEL + k0 + kq);
            Ds[kq+0][r] = __uint_as_float(f2tf32(w.x));
            Ds[kq+1][r] = __uint_as_float(f2tf32(w.y));
            Ds[kq+2][r] = __uint_as_float(f2tf32(w.z));
            Ds[kq+3][r] = __uint_as_float(f2tf32(w.w));
            float4 x = *(const float4*)(X + (size_t)(l0 + r) * DMODEL + k0 + kq);
            Ls[kq+0][r] = __uint_as_float(f2tf32(x.x));
            Ls[kq+1][r] = __uint_as_float(f2tf32(x.y));
            Ls[kq+2][r] = __uint_as_float(f2tf32(x.z));
            Ls[kq+3][r] = __uint_as_float(f2tf32(x.w));
        }
        __syncthreads();

        #pragma unroll
        for (int ks = 0; ks < 4; ks++) {
            const int k = ks * 8;
            uint32_t a[4][4], bf[4][2];
            #pragma unroll
            for (int i = 0; i < 4; i++) {
                int d = wd + i * 16 + g;
                a[i][0] = __float_as_uint(Ds[k + tg    ][d    ]);
                a[i][1] = __float_as_uint(Ds[k + tg    ][d + 8]);
                a[i][2] = __float_as_uint(Ds[k + tg + 4][d    ]);
                a[i][3] = __float_as_uint(Ds[k + tg + 4][d + 8]);
            }
            #pragma unroll
            for (int j = 0; j < 4; j++) {
                int n = wn + j * 8 + g;
                bf[j][0] = __float_as_uint(Ls[k + tg    ][n]);
                bf[j][1] = __float_as_uint(Ls[k + tg + 4][n]);
            }
            #pragma unroll
            for (int i = 0; i < 4; i++)
                #pragma unroll
                for (int j = 0; j < 4; j++) {
                    asm volatile(
                        "mma.sync.aligned.m16n8k8.row.col.f32.tf32.tf32.f32 "
                        "{%0,%1,%2,%3},{%4,%5,%6,%7},{%8,%9},{%0,%1,%2,%3};"
                        : "+f"(acc[i][j][0]), "+f"(acc[i][j][1]),
                          "+f"(acc[i][j][2]), "+f"(acc[i][j][3])
                        : "r"(a[i][0]), "r"(a[i][1]), "r"(a[i][2]), "r"(a[i][3]),
                          "r"(bf[j][0]), "r"(bf[j][1]));
                }
        }
        __syncthreads();
    }

    #pragma unroll
    for (int i = 0; i < 4; i++) {
        int d0 = wd + i * 16 + g;
        float bv0 = bi[d0], bv1 = bi[d0 + 8];
        #pragma unroll
        for (int j = 0; j < 4; j++) {
            int gl = l0 + wn + j * 8 + 2 * tg;
            int b  = gl >> 12;
            int l  = gl & 4095;
            float* o0 = dst + (size_t)((b << 7) + d0    ) * LSEQ + l;
            float* o1 = dst + (size_t)((b << 7) + d0 + 8) * LSEQ + l;
            *(float2*)o0 = make_float2(acc[i][j][0] + bv0, acc[i][j][1] + bv0);
            *(float2*)o1 = make_float2(acc[i][j][2] + bv1, acc[i][j][3] + bv1);
        }
    }
}

// ---------------- radix-4 4096-pt FFT with shared half twiddle table ----------------
// tw[j] = exp(-2*pi*i*j/4096), j in [0,2048)
__device__ __forceinline__ void fill_tw(float2* tw, int tid)
{
    for (int j = tid; j < 2048; j += 256) {
        float ang = -PI_F * (float)j / 2048.0f;
        float s, c;
        __sincosf(ang, &s, &c);
        tw[j] = make_float2(c, s);
    }
}

__device__ __forceinline__ float2 cmul(float2 a, float2 b) {
    return make_float2(a.x*b.x - a.y*b.y, a.x*b.y + a.y*b.x);
}

// base-4 digit reversal of 12-bit index = pair-swapped bit reversal
__device__ __forceinline__ int dr12(int i) {
    unsigned y = __brev((unsigned)i) >> 20;
    return (int)(((y & 0x555u) << 1) | ((y >> 1) & 0x555u));
}

__device__ __forceinline__ void fft4096_r4(float2* s, const float2* tw, int tid, bool inv)
{
    #pragma unroll 1
    for (int st = 0; st < 6; st++) {
        const int twoSt = 2 * st;
        const int L = 1 << twoSt;
        const int shift = 10 - twoSt;
        #pragma unroll 1
        for (int t = tid; t < 1024; t += 256) {
            int j  = t & (L - 1);
            int i0 = ((t >> twoSt) << (twoSt + 2)) + j;
            int e  = j << shift;                 // < 1024
            float2 w1 = tw[e];
            float2 w2 = tw[2 * e];               // < 2048
            int e3 = 3 * e;
            float2 w3 = (e3 < 2048) ? tw[e3]
                        : make_float2(-tw[e3 - 2048].x, -tw[e3 - 2048].y);
            if (inv) { w1.y = -w1.y; w2.y = -w2.y; w3.y = -w3.y; }

            float2 u0 = s[i0];
            float2 u1 = cmul(s[i0 + L],     w1);
            float2 u2 = cmul(s[i0 + 2*L],   w2);
            float2 u3 = cmul(s[i0 + 3*L],   w3);

            float2 v0 = make_float2(u0.x + u2.x, u0.y + u2.y);
            float2 v1 = make_float2(u0.x - u2.x, u0.y - u2.y);
            float2 v2 = make_float2(u1.x + u3.x, u1.y + u3.y);
            float2 v3 = make_float2(u1.x - u3.x, u1.y - u3.y);

            s[i0]       = make_float2(v0.x + v2.x, v0.y + v2.y);
            s[i0 + 2*L] = make_float2(v0.x - v2.x, v0.y - v2.y);
            if (!inv) {
                s[i0 + L]   = make_float2(v1.x + v3.y, v1.y - v3.x);
                s[i0 + 3*L] = make_float2(v1.x - v3.y, v1.y + v3.x);
            } else {
                s[i0 + L]   = make_float2(v1.x - v3.y, v1.y + v3.x);
                s[i0 + 3*L] = make_float2(v1.x + v3.y, v1.y - v3.x);
            }
        }
        __syncthreads();
    }
}

// forward: pack 2 real rows (2j, 2j+1) as one complex FFT, Hermitian unpack.
__global__ __launch_bounds__(256) void fft_fwd_kernel()
{
    __shared__ float2 s[4096];
    __shared__ float2 tw[2048];
    const int blk = blockIdx.x;                 // 0..255
    const int tensor = blk >> 7;
    const int pr = blk & 127;
    const int b = pr >> 6;
    const int j = pr & 63;
    const int row0 = b * 128 + 2 * j;
    const float* src0 = (tensor ? g_k : g_q) + (size_t)row0 * LSEQ;
    const float* src1 = src0 + LSEQ;
    float2* dst0 = (tensor ? g_Kf : g_Qf) + (size_t)row0 * FLEN;
    float2* dst1 = dst0 + FLEN;
    const int tid = threadIdx.x;

    fill_tw(tw, tid);
    for (int i = tid; i < 4096; i += 256) {
        s[dr12(i)] = make_float2(src0[i], src1[i]);
    }
    __syncthreads();
    fft4096_r4(s, tw, tid, false);

    for (int f = tid; f < FLEN; f += 256) {
        float2 cf = s[f];
        float2 cn = s[(4096 - f) & 4095];
        dst0[f] = make_float2(0.5f * (cf.x + cn.x), 0.5f * (cf.y - cn.y));
        dst1[f] = make_float2(0.5f * (cf.y + cn.y), 0.5f * (cn.x - cf.x));
    }
}

// ---------------- selector MLP ----------------
#define SEL_TF 16
__global__ __launch_bounds__(128) void selector_kernel(
    const float* __restrict__ qW1, const float* __restrict__ qb1,
    const float* __restrict__ qW2, const float* __restrict__ qb2,
    const float* __restrict__ kW1, const float* __restrict__ kb1,
    const float* __restrict__ kW2, const float* __restrict__ kb2,
    const float* __restrict__ q_noise, const float* __restrict__ k_noise)
{
    const int chunk = blockIdx.x;
    const int b = blockIdx.y;
    const int tensor = blockIdx.z;
    const float2* Freq = tensor ? g_Kf : g_Qf;
    const float* W1 = tensor ? kW1 : qW1;
    const float* b1 = tensor ? kb1 : qb1;
    const float* W2 = tensor ? kW2 : qW2;
    const float* b2 = tensor ? kb2 : qb2;
    const float* nz = tensor ? k_noise : q_noise;
    float* z = tensor ? g_zk : g_zq;

    __shared__ float W1s[64 * 128];
    __shared__ float xr[128];
    __shared__ float h1[64];
    __shared__ float lg[2];
    const int tid = threadIdx.x;

    for (int i = tid; i < 64 * 128; i += 128) W1s[i] = W1[i];
    __syncthreads();

    const int f0 = chunk * SEL_TF;
    for (int f = f0; f < f0 + SEL_TF && f < FLEN; f++) {
        xr[tid] = Freq[(size_t)(b * 128 + tid) * FLEN + f].x;
        __syncthreads();

        if (tid < 64) {
            float acc = b1[tid];
            const float* w = W1s + tid * 128;
            #pragma unroll 16
            for (int d = 0; d < 128; d++) acc += xr[d] * w[d];
            h1[tid] = fmaxf(acc, 0.f);
        }
        __syncthreads();
        if (tid < 2) {
            float acc = b2[tid];
            const float* w = W2 + tid * 64;
            #pragma unroll 8
            for (int j = 0; j < 64; j++) acc += h1[j] * w[j];
            float n = nz[((size_t)b * FLEN + f) * 2 + tid];
            float g = -logf(-logf(n + GEPS) + GEPS);
            lg[tid] = acc + g;
        }
        __syncthreads();
        if (tid == 0) z[b * FLEN + f] = 1.f / (1.f + expf(lg[0] - lg[1]));
        __syncthreads();
    }
}

// inverse: pack 2 filtered rows per complex iFFT.
__global__ __launch_bounds__(256) void fft_inv_kernel()
{
    __shared__ float2 s[4096];
    __shared__ float2 tw[2048];
    const int blk = blockIdx.x;
    const int tensor = blk >> 7;
    const int pr = blk & 127;
    const int b = pr >> 6;
    const int j = pr & 63;
    const int row0 = b * 128 + 2 * j;
    const float2* src0 = (tensor ? g_Kf : g_Qf) + (size_t)row0 * FLEN;
    const float2* src1 = src0 + FLEN;
    const float* z = (tensor ? g_zk : g_zq) + (size_t)b * FLEN;
    float* dst0 = (tensor ? g_kf : g_qf) + (size_t)row0 * LSEQ;
    float* dst1 = dst0 + LSEQ;
    const int tid = threadIdx.x;

    fill_tw(tw, tid);
    for (int i = tid; i < 4096; i += 256) {
        int f = (i <= 2048) ? i : (4096 - i);
        float zz = z[f];
        float2 a = src0[f];
        float2 bb = src1[f];
        if (i > 2048) { a.y = -a.y; bb.y = -bb.y; }
        a.x *= zz; a.y *= zz; bb.x *= zz; bb.y *= zz;
        s[dr12(i)] = make_float2(a.x - bb.y, a.y + bb.x);
    }
    __syncthreads();
    fft4096_r4(s, tw, tid, true);
    const float inv = 1.f / 4096.f;
    for (int i = tid; i < 4096; i += 256) {
        float2 v = s[i];
        dst0[i] = v.x * inv;
        dst1[i] = v.y * inv;
    }
}

// ---------------- scores GEMM via bf16 mma.m16n8k16 + ldmatrix ----------------
// C[b][l][m] = scale * sum_d qf[b][d][l] * kf[b][d][m]
// 128x128 block tile, K staged in two 64-chunks. 8 warps, warp tile 64l x 32m.
__global__ __launch_bounds__(256) void gemm_scores_bf16(float* __restrict__ out)
{
    __shared__ __align__(16) __nv_bfloat16 Qs[64][136];  // [k][l]
    __shared__ __align__(16) __nv_bfloat16 Ks[64][136];  // [k][m]

    const int b  = blockIdx.z;
    const int l0 = blockIdx.y * 128;
    const int m0 = blockIdx.x * 128;
    const float* A  = g_qf + (size_t)b * HDIM * LSEQ;
    const float* Bm = g_kf + (size_t)b * HDIM * LSEQ;

    const int tid  = threadIdx.x;
    const int warp = tid >> 5, lane = tid & 31;
    const int g = lane >> 2, tg = lane & 3;
    const int wl = (warp & 1) * 64;
    const int wn = (warp >> 1) * 32;

    // per-lane ldmatrix address components
    const int lr   = lane & 7;
    const int koff = lr + ((lane & 16) ? 8 : 0);  // A: row select
    const int coff = (lane & 8) ? 8 : 0;          // A: col select
    const int kb   = lr + ((lane & 8) ? 8 : 0);   // B: row select
    const int cb   = (lane & 16) ? 8 : 0;         // B: col select

    float acc[4][4][4];
    #pragma unroll
    for (int i = 0; i < 4; i++)
        #pragma unroll
        for (int j = 0; j < 4; j++)
            #pragma unroll
            for (int c = 0; c < 4; c++) acc[i][j][c] = 0.f;

    for (int kc = 0; kc < 2; kc++) {
        // fill 64 k-rows of Qs/Ks (bf16)
        #pragma unroll
        for (int it = 0; it < 8; it++) {
            int linear = tid + 256 * it;          // 0..2047
            int k  = linear >> 5;                 // 0..63
            int l4 = (linear & 31) << 2;          // 0..124
            const float* pa = A  + (size_t)(kc * 64 + k) * LSEQ + l0 + l4;
            const float* pb = Bm + (size_t)(kc * 64 + k) * LSEQ + m0 + l4;
            float4 va = *(const float4*)pa;
            float4 vb = *(const float4*)pb;
            *(__nv_bfloat162*)&Qs[k][l4    ] = __floats2bfloat162_rn(va.x, va.y);
            *(__nv_bfloat162*)&Qs[k][l4 + 2] = __floats2bfloat162_rn(va.z, va.w);
            *(__nv_bfloat162*)&Ks[k][l4    ] = __floats2bfloat162_rn(vb.x, vb.y);
            *(__nv_bfloat162*)&Ks[k][l4 + 2] = __floats2bfloat162_rn(vb.z, vb.w);
        }
        __syncthreads();

        #pragma unroll
        for (int ks = 0; ks < 4; ks++) {
            const int k0 = ks * 16;
            uint32_t a[4][4];
            #pragma unroll
            for (int i = 0; i < 4; i++) {
                uint32_t addr = sptr(&Qs[k0 + koff][wl + 16 * i + coff]);
                asm volatile(
                    "ldmatrix.sync.aligned.m8n8.x4.trans.shared.b16 {%0,%1,%2,%3}, [%4];"
                    : "=r"(a[i][0]), "=r"(a[i][1]), "=r"(a[i][2]), "=r"(a[i][3])
                    : "r"(addr));
            }
            uint32_t bfr[2][4];
            #pragma unroll
            for (int jj = 0; jj < 2; jj++) {
                uint32_t addr = sptr(&Ks[k0 + kb][wn + 16 * jj + cb]);
                asm volatile(
                    "ldmatrix.sync.aligned.m8n8.x4.trans.shared.b16 {%0,%1,%2,%3}, [%4];"
                    : "=r"(bfr[jj][0]), "=r"(bfr[jj][1]), "=r"(bfr[jj][2]), "=r"(bfr[jj][3])
                    : "r"(addr));
            }
            #pragma unroll
            for (int i = 0; i < 4; i++)
                #pragma unroll
                for (int j = 0; j < 4; j++) {
                    uint32_t b0 = bfr[j >> 1][2 * (j & 1)];
                    uint32_t b1 = bfr[j >> 1][2 * (j & 1) + 1];
                    asm volatile(
                        "mma.sync.aligned.m16n8k16.row.col.f32.bf16.bf16.f32 "
                        "{%0,%1,%2,%3},{%4,%5,%6,%7},{%8,%9},{%0,%1,%2,%3};"
                        : "+f"(acc[i][j][0]), "+f"(acc[i][j][1]),
                          "+f"(acc[i][j][2]), "+f"(acc[i][j][3])
                        : "r"(a[i][0]), "r"(a[i][1]), "r"(a[i][2]), "r"(a[i][3]),
                          "r"(b0), "r"(b1));
                }
        }
        __syncthreads();
    }

    #pragma unroll
    for (int i = 0; i < 4; i++) {
        int row0 = l0 + wl + i * 16 + g;
        #pragma unroll
        for (int j = 0; j < 4; j++) {
            int col = m0 + wn + j * 8 + 2 * tg;
            float2 v0 = make_float2(acc[i][j][0] * INV_SQRT_DK, acc[i][j][1] * INV_SQRT_DK);
            float2 v1 = make_float2(acc[i][j][2] * INV_SQRT_DK, acc[i][j][3] * INV_SQRT_DK);
            *(float2*)(out + ((size_t)b * LSEQ + row0    ) * LSEQ + col) = v0;
            *(float2*)(out + ((size_t)b * LSEQ + row0 + 8) * LSEQ + col) = v1;
        }
    }
}

// ---------------- masked row softmax ----------------
__device__ __forceinline__ float warpMax(float v) {
    #pragma unroll
    for (int o = 16; o; o >>= 1) v = fmaxf(v, __shfl_xor_sync(0xffffffffu, v, o));
    return v;
}
__device__ __forceinline__ float warpSum(float v) {
    #pragma unroll
    for (int o = 16; o; o >>= 1) v += __shfl_xor_sync(0xffffffffu, v, o);
    return v;
}

__global__ __launch_bounds__(256) void softmax_kernel(float* __restrict__ out,
                                                      const int* __restrict__ mask)
{
    const int row = blockIdx.x;
    const int b = row >> 12;
    float* p = out + (size_t)row * LSEQ;
    const int* mrow = mask + (size_t)b * LSEQ;
    const int tid = threadIdx.x;

    __shared__ float red[8];
    __shared__ float bc;

    float4 v[4];
    float mx = -3.0e38f;
    #pragma unroll
    for (int i = 0; i < 4; i++) {
        int c4 = tid + 256 * i;
        float4 s = ((const float4*)p)[c4];
        int4 m = ((const int4*)mrow)[c4];
        s.x = (m.x == 0) ? -1.0e9f : s.x;
        s.y = (m.y == 0) ? -1.0e9f : s.y;
        s.z = (m.z == 0) ? -1.0e9f : s.z;
        s.w = (m.w == 0) ? -1.0e9f : s.w;
        v[i] = s;
        mx = fmaxf(mx, fmaxf(fmaxf(s.x, s.y), fmaxf(s.z, s.w)));
    }
    mx = warpMax(mx);
    if ((tid & 31) == 0) red[tid >> 5] = mx;
    __syncthreads();
    if (tid < 32) {
        float m2 = (tid < 8) ? red[tid] : -3.0e38f;
        m2 = warpMax(m2);
        if (tid == 0) bc = m2;
    }
    __syncthreads();
    mx = bc;

    float sum = 0.f;
    #pragma unroll
    for (int i = 0; i < 4; i++) {
        v[i].x = __expf(v[i].x - mx);
        v[i].y = __expf(v[i].y - mx);
        v[i].z = __expf(v[i].z - mx);
        v[i].w = __expf(v[i].w - mx);
        sum += v[i].x + v[i].y + v[i].z + v[i].w;
    }
    sum = warpSum(sum);
    if ((tid & 31) == 0) red[tid >> 5] = sum;
    __syncthreads();
    if (tid < 32) {
        float s2 = (tid < 8) ? red[tid] : 0.f;
        s2 = warpSum(s2);
        if (tid == 0) bc = s2;
    }
    __syncthreads();
    const float inv = 1.f / bc;

    #pragma unroll
    for (int i = 0; i < 4; i++) {
        float4 o = make_float4(v[i].x * inv, v[i].y * inv, v[i].z * inv, v[i].w * inv);
        ((float4*)p)[tid + 256 * i] = o;
    }
}

// ---------------- launch ----------------
extern "C" void kernel_launch(void* const* d_in, const int* in_sizes, int n_in,
                              void* d_out, int out_size)
{
    const float* query   = (const float*)d_in[0];
    const float* key     = (const float*)d_in[1];
    const int*   mask    = (const int*)  d_in[2];
    const float* Wq      = (const float*)d_in[3];
    const float* bq      = (const float*)d_in[4];
    const float* Wk      = (const float*)d_in[5];
    const float* bk      = (const float*)d_in[6];
    const float* qW1     = (const float*)d_in[7];
    const float* qb1     = (const float*)d_in[8];
    const float* qW2     = (const float*)d_in[9];
    const float* qb2     = (const float*)d_in[10];
    const float* kW1     = (const float*)d_in[11];
    const float* kb1     = (const float*)d_in[12];
    const float* kW2     = (const float*)d_in[13];
    const float* kb2     = (const float*)d_in[14];
    const float* q_noise = (const float*)d_in[15];
    const float* k_noise = (const float*)d_in[16];
    float* out = (float*)d_out;

    proj_tc<<<dim3(64, 2), 256>>>(query, key, Wq, bq, Wk, bk);
    fft_fwd_kernel<<<256, 256>>>();
    selector_kernel<<<dim3((FLEN + SEL_TF - 1) / SEL_TF, BATCH, 2), 128>>>(
        qW1, qb1, qW2, qb2, kW1, kb1, kW2, kb2, q_noise, k_noise);
    fft_inv_kernel<<<256, 256>>>();
    gemm_scores_bf16<<<dim3(32, 32, BATCH), 256>>>(out);
    softmax_kernel<<<BATCH * LSEQ, 256>>>(out, mask);
}

// round 5
// speedup vs baseline: 3.8592x; 1.0678x over previous
#include <cuda_runtime.h>
#include <cuda_bf16.h>
#include <cstdint>

#define BATCH 2
#define LSEQ 4096
#define DMODEL 768
#define HDIM 128
#define FLEN 2049
#define INV_SQRT_DK 0.08838834764831845f
#define GEPS 1e-9f
#define PI_F 3.14159265358979323846f

// ---------------- scratch ----------------
__device__ float  g_q [BATCH*HDIM*LSEQ];   // projected q, layout [b][d][l]
__device__ float  g_k [BATCH*HDIM*LSEQ];
__device__ float2 g_Qf[BATCH*HDIM*FLEN];   // rfft of q rows
__device__ float2 g_Kf[BATCH*HDIM*FLEN];
__device__ float  g_zq[BATCH*FLEN];        // selector gains
__device__ float  g_zk[BATCH*FLEN];
__device__ __nv_bfloat16 g_qf_bf[BATCH*HDIM*LSEQ];  // filtered q (bf16)
__device__ __nv_bfloat16 g_kf_bf[BATCH*HDIM*LSEQ];

__device__ __forceinline__ uint32_t f2tf32(float f) {
    uint32_t r;
    asm("cvt.rna.tf32.f32 %0, %1;" : "=r"(r) : "f"(f));
    return r;
}
__device__ __forceinline__ uint32_t sptr(const void* p) {
    return (uint32_t)__cvta_generic_to_shared(p);
}
__device__ __forceinline__ void cp16(void* smem_dst, const void* gmem_src) {
    asm volatile("cp.async.ca.shared.global [%0], [%1], 16;"
                 :: "r"(sptr(smem_dst)), "l"(gmem_src));
}

// ---------------- projection GEMM (tf32 tensor cores) ----------------
__global__ __launch_bounds__(256) void proj_tc(
    const float* __restrict__ query, const float* __restrict__ key,
    const float* __restrict__ Wq, const float* __restrict__ bq,
    const float* __restrict__ Wk, const float* __restrict__ bk)
{
    const int tensor = blockIdx.y;
    const float* X  = tensor ? key : query;     // [8192][768]
    const float* W  = tensor ? Wk  : Wq;        // [128][768]
    const float* bi = tensor ? bk  : bq;        // [128]
    float* dst = tensor ? g_k : g_q;

    const int l0 = blockIdx.x * 128;

    __shared__ float Ds[32][136];   // [k][d]
    __shared__ float Ls[32][136];   // [k][l]

    const int tid  = threadIdx.x;
    const int warp = tid >> 5, lane = tid & 31;
    const int g = lane >> 2, tg = lane & 3;
    const int wd = (warp & 1) * 64;
    const int wn = (warp >> 1) * 32;

    float acc[4][4][4];
    #pragma unroll
    for (int i = 0; i < 4; i++)
        #pragma unroll
        for (int j = 0; j < 4; j++)
            #pragma unroll
            for (int c = 0; c < 4; c++) acc[i][j][c] = 0.f;

    for (int k0 = 0; k0 < DMODEL; k0 += 32) {
        #pragma unroll
        for (int ii = 0; ii < 4; ii++) {
            int idx = tid + 256 * ii;
            int r   = idx >> 3;
            int kq  = (idx & 7) << 2;
            float4 w = *(const float4*)(W + (size_t)r * DMODEL + k0 + kq);
            Ds[kq+0][r] = __uint_as_float(f2tf32(w.x));
            Ds[kq+1][r] = __uint_as_float(f2tf32(w.y));
            Ds[kq+2][r] = __uint_as_float(f2tf32(w.z));
            Ds[kq+3][r] = __uint_as_float(f2tf32(w.w));
            float4 x = *(const float4*)(X + (size_t)(l0 + r) * DMODEL + k0 + kq);
            Ls[kq+0][r] = __uint_as_float(f2tf32(x.x));
            Ls[kq+1][r] = __uint_as_float(f2tf32(x.y));
            Ls[kq+2][r] = __uint_as_float(f2tf32(x.z));
            Ls[kq+3][r] = __uint_as_float(f2tf32(x.w));
        }
        __syncthreads();

        #pragma unroll
        for (int ks = 0; ks < 4; ks++) {
            const int k = ks * 8;
            uint32_t a[4][4], bf[4][2];
            #pragma unroll
            for (int i = 0; i < 4; i++) {
                int d = wd + i * 16 + g;
                a[i][0] = __float_as_uint(Ds[k + tg    ][d    ]);
                a[i][1] = __float_as_uint(Ds[k + tg    ][d + 8]);
                a[i][2] = __float_as_uint(Ds[k + tg + 4][d    ]);
                a[i][3] = __float_as_uint(Ds[k + tg + 4][d + 8]);
            }
            #pragma unroll
            for (int j = 0; j < 4; j++) {
                int n = wn + j * 8 + g;
                bf[j][0] = __float_as_uint(Ls[k + tg    ][n]);
                bf[j][1] = __float_as_uint(Ls[k + tg + 4][n]);
            }
            #pragma unroll
            for (int i = 0; i < 4; i++)
                #pragma unroll
                for (int j = 0; j < 4; j++) {
                    asm volatile(
                        "mma.sync.aligned.m16n8k8.row.col.f32.tf32.tf32.f32 "
                        "{%0,%1,%2,%3},{%4,%5,%6,%7},{%8,%9},{%0,%1,%2,%3};"
                        : "+f"(acc[i][j][0]), "+f"(acc[i][j][1]),
                          "+f"(acc[i][j][2]), "+f"(acc[i][j][3])
                        : "r"(a[i][0]), "r"(a[i][1]), "r"(a[i][2]), "r"(a[i][3]),
                          "r"(bf[j][0]), "r"(bf[j][1]));
                }
        }
        __syncthreads();
    }

    #pragma unroll
    for (int i = 0; i < 4; i++) {
        int d0 = wd + i * 16 + g;
        float bv0 = bi[d0], bv1 = bi[d0 + 8];
        #pragma unroll
        for (int j = 0; j < 4; j++) {
            int gl = l0 + wn + j * 8 + 2 * tg;
            int b  = gl >> 12;
            int l  = gl & 4095;
            float* o0 = dst + (size_t)((b << 7) + d0    ) * LSEQ + l;
            float* o1 = dst + (size_t)((b << 7) + d0 + 8) * LSEQ + l;
            *(float2*)o0 = make_float2(acc[i][j][0] + bv0, acc[i][j][1] + bv0);
            *(float2*)o1 = make_float2(acc[i][j][2] + bv1, acc[i][j][3] + bv1);
        }
    }
}

// ---------------- radix-4 4096-pt FFT, 512 threads, 1024-entry twiddle table ----------------
#define FFT_NT 512
__device__ __forceinline__ void fill_tw(float2* tw, int tid)
{
    for (int j = tid; j < 1024; j += FFT_NT) {
        float ang = -PI_F * (float)j / 2048.0f;
        float s, c;
        __sincosf(ang, &s, &c);
        tw[j] = make_float2(c, s);
    }
}

__device__ __forceinline__ float2 cmul(float2 a, float2 b) {
    return make_float2(a.x*b.x - a.y*b.y, a.x*b.y + a.y*b.x);
}

// base-4 digit reversal of 12-bit index
__device__ __forceinline__ int dr12(int i) {
    unsigned y = __brev((unsigned)i) >> 20;
    return (int)(((y & 0x555u) << 1) | ((y >> 1) & 0x555u));
}

__device__ __forceinline__ void fft4096_r4(float2* s, const float2* tw, int tid, bool inv)
{
    #pragma unroll 1
    for (int st = 0; st < 6; st++) {
        const int twoSt = 2 * st;
        const int L = 1 << twoSt;
        const int shift = 10 - twoSt;
        #pragma unroll 1
        for (int t = tid; t < 1024; t += FFT_NT) {
            int j  = t & (L - 1);
            int i0 = ((t >> twoSt) << (twoSt + 2)) + j;
            int e  = j << shift;                 // < 1024
            float2 w1 = tw[e];
            if (inv) w1.y = -w1.y;
            float2 w2 = cmul(w1, w1);
            float2 w3 = cmul(w1, w2);

            float2 u0 = s[i0];
            float2 u1 = cmul(s[i0 + L],   w1);
            float2 u2 = cmul(s[i0 + 2*L], w2);
            float2 u3 = cmul(s[i0 + 3*L], w3);

            float2 v0 = make_float2(u0.x + u2.x, u0.y + u2.y);
            float2 v1 = make_float2(u0.x - u2.x, u0.y - u2.y);
            float2 v2 = make_float2(u1.x + u3.x, u1.y + u3.y);
            float2 v3 = make_float2(u1.x - u3.x, u1.y - u3.y);

            s[i0]       = make_float2(v0.x + v2.x, v0.y + v2.y);
            s[i0 + 2*L] = make_float2(v0.x - v2.x, v0.y - v2.y);
            if (!inv) {
                s[i0 + L]   = make_float2(v1.x + v3.y, v1.y - v3.x);
                s[i0 + 3*L] = make_float2(v1.x - v3.y, v1.y + v3.x);
            } else {
                s[i0 + L]   = make_float2(v1.x - v3.y, v1.y + v3.x);
                s[i0 + 3*L] = make_float2(v1.x + v3.y, v1.y - v3.x);
            }
        }
        __syncthreads();
    }
}

// forward: pack 2 real rows per complex FFT, Hermitian unpack.
__global__ __launch_bounds__(FFT_NT) void fft_fwd_kernel()
{
    __shared__ float2 s[4096];
    __shared__ float2 tw[1024];
    const int blk = blockIdx.x;                 // 0..255
    const int tensor = blk >> 7;
    const int pr = blk & 127;
    const int b = pr >> 6;
    const int j = pr & 63;
    const int row0 = b * 128 + 2 * j;
    const float* src0 = (tensor ? g_k : g_q) + (size_t)row0 * LSEQ;
    const float* src1 = src0 + LSEQ;
    float2* dst0 = (tensor ? g_Kf : g_Qf) + (size_t)row0 * FLEN;
    float2* dst1 = dst0 + FLEN;
    const int tid = threadIdx.x;

    fill_tw(tw, tid);
    for (int i = tid; i < 4096; i += FFT_NT) {
        s[dr12(i)] = make_float2(src0[i], src1[i]);
    }
    __syncthreads();
    fft4096_r4(s, tw, tid, false);

    for (int f = tid; f < FLEN; f += FFT_NT) {
        float2 cf = s[f];
        float2 cn = s[(4096 - f) & 4095];
        dst0[f] = make_float2(0.5f * (cf.x + cn.x), 0.5f * (cf.y - cn.y));
        dst1[f] = make_float2(0.5f * (cf.y + cn.y), 0.5f * (cn.x - cf.x));
    }
}

// ---------------- selector MLP ----------------
#define SEL_TF 16
__global__ __launch_bounds__(128) void selector_kernel(
    const float* __restrict__ qW1, const float* __restrict__ qb1,
    const float* __restrict__ qW2, const float* __restrict__ qb2,
    const float* __restrict__ kW1, const float* __restrict__ kb1,
    const float* __restrict__ kW2, const float* __restrict__ kb2,
    const float* __restrict__ q_noise, const float* __restrict__ k_noise)
{
    const int chunk = blockIdx.x;
    const int b = blockIdx.y;
    const int tensor = blockIdx.z;
    const float2* Freq = tensor ? g_Kf : g_Qf;
    const float* W1 = tensor ? kW1 : qW1;
    const float* b1 = tensor ? kb1 : qb1;
    const float* W2 = tensor ? kW2 : qW2;
    const float* b2 = tensor ? kb2 : qb2;
    const float* nz = tensor ? k_noise : q_noise;
    float* z = tensor ? g_zk : g_zq;

    __shared__ float W1s[64 * 128];
    __shared__ float xr[128];
    __shared__ float h1[64];
    __shared__ float lg[2];
    const int tid = threadIdx.x;

    for (int i = tid; i < 64 * 128; i += 128) W1s[i] = W1[i];
    __syncthreads();

    const int f0 = chunk * SEL_TF;
    for (int f = f0; f < f0 + SEL_TF && f < FLEN; f++) {
        xr[tid] = Freq[(size_t)(b * 128 + tid) * FLEN + f].x;
        __syncthreads();

        if (tid < 64) {
            float acc = b1[tid];
            const float* w = W1s + tid * 128;
            #pragma unroll 16
            for (int d = 0; d < 128; d++) acc += xr[d] * w[d];
            h1[tid] = fmaxf(acc, 0.f);
        }
        __syncthreads();
        if (tid < 2) {
            float acc = b2[tid];
            const float* w = W2 + tid * 64;
            #pragma unroll 8
            for (int j = 0; j < 64; j++) acc += h1[j] * w[j];
            float n = nz[((size_t)b * FLEN + f) * 2 + tid];
            float g = -logf(-logf(n + GEPS) + GEPS);
            lg[tid] = acc + g;
        }
        __syncthreads();
        if (tid == 0) z[b * FLEN + f] = 1.f / (1.f + expf(lg[0] - lg[1]));
        __syncthreads();
    }
}

// inverse: pack 2 filtered rows per complex iFFT; store bf16.
__global__ __launch_bounds__(FFT_NT) void fft_inv_kernel()
{
    __shared__ float2 s[4096];
    __shared__ float2 tw[1024];
    const int blk = blockIdx.x;
    const int tensor = blk >> 7;
    const int pr = blk & 127;
    const int b = pr >> 6;
    const int j = pr & 63;
    const int row0 = b * 128 + 2 * j;
    const float2* src0 = (tensor ? g_Kf : g_Qf) + (size_t)row0 * FLEN;
    const float2* src1 = src0 + FLEN;
    const float* z = (tensor ? g_zk : g_zq) + (size_t)b * FLEN;
    __nv_bfloat16* dst0 = (tensor ? g_kf_bf : g_qf_bf) + (size_t)row0 * LSEQ;
    __nv_bfloat16* dst1 = dst0 + LSEQ;
    const int tid = threadIdx.x;

    fill_tw(tw, tid);
    for (int i = tid; i < 4096; i += FFT_NT) {
        int f = (i <= 2048) ? i : (4096 - i);
        float zz = z[f];
        float2 a = src0[f];
        float2 bb = src1[f];
        if (i > 2048) { a.y = -a.y; bb.y = -bb.y; }
        a.x *= zz; a.y *= zz; bb.x *= zz; bb.y *= zz;
        s[dr12(i)] = make_float2(a.x - bb.y, a.y + bb.x);
    }
    __syncthreads();
    fft4096_r4(s, tw, tid, true);
    const float inv = 1.f / 4096.f;
    for (int i = tid; i < 4096; i += FFT_NT) {
        float2 v = s[i];
        dst0[i] = __float2bfloat16(v.x * inv);
        dst1[i] = __float2bfloat16(v.y * inv);
    }
}

// ---------------- scores GEMM: bf16 mma.m16n8k16 + cp.async double buffer ----------------
// C[b][l][m] = scale * sum_d qf[d][l] * kf[d][m]; BK=32, 4 chunks, 2-stage pipeline.
__global__ __launch_bounds__(256) void gemm_scores_bf16(float* __restrict__ out)
{
    __shared__ __align__(16) __nv_bfloat16 Qs[2][32][136];
    __shared__ __align__(16) __nv_bfloat16 Ks[2][32][136];

    const int b  = blockIdx.z;
    const int l0 = blockIdx.y * 128;
    const int m0 = blockIdx.x * 128;
    const __nv_bfloat16* A  = g_qf_bf + (size_t)b * HDIM * LSEQ;
    const __nv_bfloat16* Bm = g_kf_bf + (size_t)b * HDIM * LSEQ;

    const int tid  = threadIdx.x;
    const int warp = tid >> 5, lane = tid & 31;
    const int g = lane >> 2, tg = lane & 3;
    const int wl = (warp & 1) * 64;
    const int wn = (warp >> 1) * 32;

    // ldmatrix lane address components
    const int lr   = lane & 7;
    const int koff = lr + ((lane & 16) ? 8 : 0);
    const int coff = (lane & 8) ? 8 : 0;
    const int kb   = lr + ((lane & 8) ? 8 : 0);
    const int cb   = (lane & 16) ? 8 : 0;

    float acc[4][4][4];
    #pragma unroll
    for (int i = 0; i < 4; i++)
        #pragma unroll
        for (int j = 0; j < 4; j++)
            #pragma unroll
            for (int c = 0; c < 4; c++) acc[i][j][c] = 0.f;

    // async fill of chunk kc into buffer bufi: 512 16B ops per matrix
    auto load_chunk = [&](int kc, int bufi) {
        #pragma unroll
        for (int it = 0; it < 2; it++) {
            int idx = tid + 256 * it;            // 0..511
            int k  = idx >> 4;                   // 0..31
            int c8 = (idx & 15) << 3;            // 0..120
            cp16(&Qs[bufi][k][c8], A  + (size_t)(kc * 32 + k) * LSEQ + l0 + c8);
            cp16(&Ks[bufi][k][c8], Bm + (size_t)(kc * 32 + k) * LSEQ + m0 + c8);
        }
        asm volatile("cp.async.commit_group;");
    };

    load_chunk(0, 0);

    #pragma unroll 1
    for (int kc = 0; kc < 4; kc++) {
        const int buf = kc & 1;
        if (kc < 3) load_chunk(kc + 1, buf ^ 1);
        if (kc < 3) asm volatile("cp.async.wait_group 1;");
        else        asm volatile("cp.async.wait_group 0;");
        __syncthreads();

        #pragma unroll
        for (int ks = 0; ks < 2; ks++) {
            const int k0 = ks * 16;
            uint32_t a[4][4];
            #pragma unroll
            for (int i = 0; i < 4; i++) {
                uint32_t addr = sptr(&Qs[buf][k0 + koff][wl + 16 * i + coff]);
                asm volatile(
                    "ldmatrix.sync.aligned.m8n8.x4.trans.shared.b16 {%0,%1,%2,%3}, [%4];"
                    : "=r"(a[i][0]), "=r"(a[i][1]), "=r"(a[i][2]), "=r"(a[i][3])
                    : "r"(addr));
            }
            uint32_t bfr[2][4];
            #pragma unroll
            for (int jj = 0; jj < 2; jj++) {
                uint32_t addr = sptr(&Ks[buf][k0 + kb][wn + 16 * jj + cb]);
                asm volatile(
                    "ldmatrix.sync.aligned.m8n8.x4.trans.shared.b16 {%0,%1,%2,%3}, [%4];"
                    : "=r"(bfr[jj][0]), "=r"(bfr[jj][1]), "=r"(bfr[jj][2]), "=r"(bfr[jj][3])
                    : "r"(addr));
            }
            #pragma unroll
            for (int i = 0; i < 4; i++)
                #pragma unroll
                for (int j = 0; j < 4; j++) {
                    uint32_t b0 = bfr[j >> 1][2 * (j & 1)];
                    uint32_t b1 = bfr[j >> 1][2 * (j & 1) + 1];
                    asm volatile(
                        "mma.sync.aligned.m16n8k16.row.col.f32.bf16.bf16.f32 "
                        "{%0,%1,%2,%3},{%4,%5,%6,%7},{%8,%9},{%0,%1,%2,%3};"
                        : "+f"(acc[i][j][0]), "+f"(acc[i][j][1]),
                          "+f"(acc[i][j][2]), "+f"(acc[i][j][3])
                        : "r"(a[i][0]), "r"(a[i][1]), "r"(a[i][2]), "r"(a[i][3]),
                          "r"(b0), "r"(b1));
                }
        }
        __syncthreads();
    }

    #pragma unroll
    for (int i = 0; i < 4; i++) {
        int row0 = l0 + wl + i * 16 + g;
        #pragma unroll
        for (int j = 0; j < 4; j++) {
            int col = m0 + wn + j * 8 + 2 * tg;
            float2 v0 = make_float2(acc[i][j][0] * INV_SQRT_DK, acc[i][j][1] * INV_SQRT_DK);
            float2 v1 = make_float2(acc[i][j][2] * INV_SQRT_DK, acc[i][j][3] * INV_SQRT_DK);
            *(float2*)(out + ((size_t)b * LSEQ + row0    ) * LSEQ + col) = v0;
            *(float2*)(out + ((size_t)b * LSEQ + row0 + 8) * LSEQ + col) = v1;
        }
    }
}

// ---------------- masked row softmax ----------------
__device__ __forceinline__ float warpMax(float v) {
    #pragma unroll
    for (int o = 16; o; o >>= 1) v = fmaxf(v, __shfl_xor_sync(0xffffffffu, v, o));
    return v;
}
__device__ __forceinline__ float warpSum(float v) {
    #pragma unroll
    for (int o = 16; o; o >>= 1) v += __shfl_xor_sync(0xffffffffu, v, o);
    return v;
}

__global__ __launch_bounds__(256) void softmax_kernel(float* __restrict__ out,
                                                      const int* __restrict__ mask)
{
    const int row = blockIdx.x;
    const int b = row >> 12;
    float* p = out + (size_t)row * LSEQ;
    const int* mrow = mask + (size_t)b * LSEQ;
    const int tid = threadIdx.x;

    __shared__ float red[8];
    __shared__ float bc;

    float4 v[4];
    float mx = -3.0e38f;
    #pragma unroll
    for (int i = 0; i < 4; i++) {
        int c4 = tid + 256 * i;
        float4 s = ((const float4*)p)[c4];
        int4 m = ((const int4*)mrow)[c4];
        s.x = (m.x == 0) ? -1.0e9f : s.x;
        s.y = (m.y == 0) ? -1.0e9f : s.y;
        s.z = (m.z == 0) ? -1.0e9f : s.z;
        s.w = (m.w == 0) ? -1.0e9f : s.w;
        v[i] = s;
        mx = fmaxf(mx, fmaxf(fmaxf(s.x, s.y), fmaxf(s.z, s.w)));
    }
    mx = warpMax(mx);
    if ((tid & 31) == 0) red[tid >> 5] = mx;
    __syncthreads();
    if (tid < 32) {
        float m2 = (tid < 8) ? red[tid] : -3.0e38f;
        m2 = warpMax(m2);
        if (tid == 0) bc = m2;
    }
    __syncthreads();
    mx = bc;

    float sum = 0.f;
    #pragma unroll
    for (int i = 0; i < 4; i++) {
        v[i].x = __expf(v[i].x - mx);
        v[i].y = __expf(v[i].y - mx);
        v[i].z = __expf(v[i].z - mx);
        v[i].w = __expf(v[i].w - mx);
        sum += v[i].x + v[i].y + v[i].z + v[i].w;
    }
    sum = warpSum(sum);
    if ((tid & 31) == 0) red[tid >> 5] = sum;
    __syncthreads();
    if (tid < 32) {
        float s2 = (tid < 8) ? red[tid] : 0.f;
        s2 = warpSum(s2);
        if (tid == 0) bc = s2;
    }
    __syncthreads();
    const float inv = 1.f / bc;

    #pragma unroll
    for (int i = 0; i < 4; i++) {
        float4 o = make_float4(v[i].x * inv, v[i].y * inv, v[i].z * inv, v[i].w * inv);
        ((float4*)p)[tid + 256 * i] = o;
    }
}

// ---------------- launch ----------------
extern "C" void kernel_launch(void* const* d_in, const int* in_sizes, int n_in,
                              void* d_out, int out_size)
{
    const float* query   = (const float*)d_in[0];
    const float* key     = (const float*)d_in[1];
    const int*   mask    = (const int*)  d_in[2];
    const float* Wq      = (const float*)d_in[3];
    const float* bq      = (const float*)d_in[4];
    const float* Wk      = (const float*)d_in[5];
    const float* bk      = (const float*)d_in[6];
    const float* qW1     = (const float*)d_in[7];
    const float* qb1     = (const float*)d_in[8];
    const float* qW2     = (const float*)d_in[9];
    const float* qb2     = (const float*)d_in[10];
    const float* kW1     = (const float*)d_in[11];
    const float* kb1     = (const float*)d_in[12];
    const float* kW2     = (const float*)d_in[13];
    const float* kb2     = (const float*)d_in[14];
    const float* q_noise = (const float*)d_in[15];
    const float* k_noise = (const float*)d_in[16];
    float* out = (float*)d_out;

    proj_tc<<<dim3(64, 2), 256>>>(query, key, Wq, bq, Wk, bk);
    fft_fwd_kernel<<<256, FFT_NT>>>();
    selector_kernel<<<dim3((FLEN + SEL_TF - 1) / SEL_TF, BATCH, 2), 128>>>(
        qW1, qb1, qW2, qb2, kW1, kb1, kW2, kb2, q_noise, k_noise);
    fft_inv_kernel<<<256, FFT_NT>>>();
    gemm_scores_bf16<<<dim3(32, 32, BATCH), 256>>>(out);
    softmax_kernel<<<BATCH * LSEQ, 256>>>(out, mask);
}

// round 6
// speedup vs baseline: 4.1698x; 1.0805x over previous
#include <cuda_runtime.h>
#include <cuda_bf16.h>
#include <cstdint>

#define BATCH 2
#define LSEQ 4096
#define DMODEL 768
#define HDIM 128
#define FLEN 2049
#define INV_SQRT_DK 0.08838834764831845f
#define GEPS 1e-9f
#define PI_F 3.14159265358979323846f

// ---------------- scratch ----------------
__device__ float  g_q [BATCH*HDIM*LSEQ];   // projected q, layout [b][d][l]
__device__ float  g_k [BATCH*HDIM*LSEQ];
__device__ float2 g_Qf[BATCH*HDIM*FLEN];   // rfft of q rows
__device__ float2 g_Kf[BATCH*HDIM*FLEN];
__device__ float  g_zq[BATCH*FLEN];        // selector gains
__device__ float  g_zk[BATCH*FLEN];
__device__ __nv_bfloat16 g_qf_bf[BATCH*HDIM*LSEQ];  // filtered q (bf16)
__device__ __nv_bfloat16 g_kf_bf[BATCH*HDIM*LSEQ];

__device__ __forceinline__ uint32_t sptr(const void* p) {
    return (uint32_t)__cvta_generic_to_shared(p);
}
__device__ __forceinline__ void cp16(void* smem_dst, const void* gmem_src) {
    asm volatile("cp.async.ca.shared.global [%0], [%1], 16;"
                 :: "r"(sptr(smem_dst)), "l"(gmem_src));
}

// ---------------- projection GEMM: tf32 mma + 3-stage cp.async ----------------
// C[d][l] = W[d][:] . X[l][:] + b[d], dst[b][d][l].
// smem keeps global [row][k] layout (A row-major m=d, B col-major n=l).
#define PROJ_STAGES 3
#define PROJ_BK 32
#define PROJ_KP 36                      // padded k stride (floats)
#define PROJ_MAT (128 * PROJ_KP)        // floats per matrix per stage
#define PROJ_SMEM_FLOATS (PROJ_STAGES * PROJ_MAT * 2)
#define PROJ_SMEM_BYTES (PROJ_SMEM_FLOATS * 4)

__global__ __launch_bounds__(256) void proj_tc(
    const float* __restrict__ query, const float* __restrict__ key,
    const float* __restrict__ Wq, const float* __restrict__ bq,
    const float* __restrict__ Wk, const float* __restrict__ bk)
{
    extern __shared__ float dsm[];
    float* Wbase = dsm;                          // [stage][128 d][36]
    float* Xbase = dsm + PROJ_STAGES * PROJ_MAT; // [stage][128 l][36]

    const int tensor = blockIdx.y;
    const float* X  = tensor ? key : query;     // [8192][768]
    const float* W  = tensor ? Wk  : Wq;        // [128][768]
    const float* bi = tensor ? bk  : bq;        // [128]
    float* dst = tensor ? g_k : g_q;

    const int l0 = blockIdx.x * 128;
    const int tid  = threadIdx.x;
    const int warp = tid >> 5, lane = tid & 31;
    const int g = lane >> 2, tg = lane & 3;
    const int wd = (warp & 1) * 64;
    const int wn = (warp >> 1) * 32;

    float acc[4][4][4];
    #pragma unroll
    for (int i = 0; i < 4; i++)
        #pragma unroll
        for (int j = 0; j < 4; j++)
            #pragma unroll
            for (int c = 0; c < 4; c++) acc[i][j][c] = 0.f;

    auto load_stage = [&](int kc, int st) {
        const int k0 = kc * PROJ_BK;
        float* Ws = Wbase + st * PROJ_MAT;
        float* Xs = Xbase + st * PROJ_MAT;
        #pragma unroll
        for (int it = 0; it < 4; it++) {
            int idx = tid + 256 * it;            // 0..1023
            int row = idx >> 3;                  // 0..127
            int seg = (idx & 7) << 2;            // 0,4,..28
            cp16(Ws + row * PROJ_KP + seg, W + (size_t)row * DMODEL + k0 + seg);
            cp16(Xs + row * PROJ_KP + seg, X + (size_t)(l0 + row) * DMODEL + k0 + seg);
        }
        asm volatile("cp.async.commit_group;");
    };

    load_stage(0, 0);
    load_stage(1, 1);

    const int NCHUNK = DMODEL / PROJ_BK;        // 24
    #pragma unroll 1
    for (int kc = 0; kc < NCHUNK; kc++) {
        const int st = kc % PROJ_STAGES;
        asm volatile("cp.async.wait_group 1;");
        __syncthreads();
        if (kc + 2 < NCHUNK) load_stage(kc + 2, (kc + 2) % PROJ_STAGES);

        const float* Ws = Wbase + st * PROJ_MAT;
        const float* Xs = Xbase + st * PROJ_MAT;

        #pragma unroll
        for (int ks = 0; ks < 4; ks++) {
            const int k = ks * 8;
            uint32_t a[4][4], bf[4][2];
            #pragma unroll
            for (int i = 0; i < 4; i++) {
                int d = wd + i * 16 + g;
                a[i][0] = __float_as_uint(Ws[(d    ) * PROJ_KP + k + tg    ]);
                a[i][1] = __float_as_uint(Ws[(d + 8) * PROJ_KP + k + tg    ]);
                a[i][2] = __float_as_uint(Ws[(d    ) * PROJ_KP + k + tg + 4]);
                a[i][3] = __float_as_uint(Ws[(d + 8) * PROJ_KP + k + tg + 4]);
            }
            #pragma unroll
            for (int j = 0; j < 4; j++) {
                int n = wn + j * 8 + g;
                bf[j][0] = __float_as_uint(Xs[n * PROJ_KP + k + tg    ]);
                bf[j][1] = __float_as_uint(Xs[n * PROJ_KP + k + tg + 4]);
            }
            #pragma unroll
            for (int i = 0; i < 4; i++)
                #pragma unroll
                for (int j = 0; j < 4; j++) {
                    asm volatile(
                        "mma.sync.aligned.m16n8k8.row.col.f32.tf32.tf32.f32 "
                        "{%0,%1,%2,%3},{%4,%5,%6,%7},{%8,%9},{%0,%1,%2,%3};"
                        : "+f"(acc[i][j][0]), "+f"(acc[i][j][1]),
                          "+f"(acc[i][j][2]), "+f"(acc[i][j][3])
                        : "r"(a[i][0]), "r"(a[i][1]), "r"(a[i][2]), "r"(a[i][3]),
                          "r"(bf[j][0]), "r"(bf[j][1]));
                }
        }
        __syncthreads();
    }

    #pragma unroll
    for (int i = 0; i < 4; i++) {
        int d0 = wd + i * 16 + g;
        float bv0 = bi[d0], bv1 = bi[d0 + 8];
        #pragma unroll
        for (int j = 0; j < 4; j++) {
            int gl = l0 + wn + j * 8 + 2 * tg;
            int b  = gl >> 12;
            int l  = gl & 4095;
            float* o0 = dst + (size_t)((b << 7) + d0    ) * LSEQ + l;
            float* o1 = dst + (size_t)((b << 7) + d0 + 8) * LSEQ + l;
            *(float2*)o0 = make_float2(acc[i][j][0] + bv0, acc[i][j][1] + bv0);
            *(float2*)o1 = make_float2(acc[i][j][2] + bv1, acc[i][j][3] + bv1);
        }
    }
}

// ---------------- radix-4 4096-pt FFT, 512 threads, 1024-entry twiddle table ----------------
#define FFT_NT 512
__device__ __forceinline__ void fill_tw(float2* tw, int tid)
{
    for (int j = tid; j < 1024; j += FFT_NT) {
        float ang = -PI_F * (float)j / 2048.0f;
        float s, c;
        __sincosf(ang, &s, &c);
        tw[j] = make_float2(c, s);
    }
}

__device__ __forceinline__ float2 cmul(float2 a, float2 b) {
    return make_float2(a.x*b.x - a.y*b.y, a.x*b.y + a.y*b.x);
}

__device__ __forceinline__ int dr12(int i) {
    unsigned y = __brev((unsigned)i) >> 20;
    return (int)(((y & 0x555u) << 1) | ((y >> 1) & 0x555u));
}

__device__ __forceinline__ void fft4096_r4(float2* s, const float2* tw, int tid, bool inv)
{
    #pragma unroll 1
    for (int st = 0; st < 6; st++) {
        const int twoSt = 2 * st;
        const int L = 1 << twoSt;
        const int shift = 10 - twoSt;
        #pragma unroll 1
        for (int t = tid; t < 1024; t += FFT_NT) {
            int j  = t & (L - 1);
            int i0 = ((t >> twoSt) << (twoSt + 2)) + j;
            int e  = j << shift;
            float2 w1 = tw[e];
            if (inv) w1.y = -w1.y;
            float2 w2 = cmul(w1, w1);
            float2 w3 = cmul(w1, w2);

            float2 u0 = s[i0];
            float2 u1 = cmul(s[i0 + L],   w1);
            float2 u2 = cmul(s[i0 + 2*L], w2);
            float2 u3 = cmul(s[i0 + 3*L], w3);

            float2 v0 = make_float2(u0.x + u2.x, u0.y + u2.y);
            float2 v1 = make_float2(u0.x - u2.x, u0.y - u2.y);
            float2 v2 = make_float2(u1.x + u3.x, u1.y + u3.y);
            float2 v3 = make_float2(u1.x - u3.x, u1.y - u3.y);

            s[i0]       = make_float2(v0.x + v2.x, v0.y + v2.y);
            s[i0 + 2*L] = make_float2(v0.x - v2.x, v0.y - v2.y);
            if (!inv) {
                s[i0 + L]   = make_float2(v1.x + v3.y, v1.y - v3.x);
                s[i0 + 3*L] = make_float2(v1.x - v3.y, v1.y + v3.x);
            } else {
                s[i0 + L]   = make_float2(v1.x - v3.y, v1.y + v3.x);
                s[i0 + 3*L] = make_float2(v1.x + v3.y, v1.y - v3.x);
            }
        }
        __syncthreads();
    }
}

__global__ __launch_bounds__(FFT_NT) void fft_fwd_kernel()
{
    __shared__ float2 s[4096];
    __shared__ float2 tw[1024];
    const int blk = blockIdx.x;
    const int tensor = blk >> 7;
    const int pr = blk & 127;
    const int b = pr >> 6;
    const int j = pr & 63;
    const int row0 = b * 128 + 2 * j;
    const float* src0 = (tensor ? g_k : g_q) + (size_t)row0 * LSEQ;
    const float* src1 = src0 + LSEQ;
    float2* dst0 = (tensor ? g_Kf : g_Qf) + (size_t)row0 * FLEN;
    float2* dst1 = dst0 + FLEN;
    const int tid = threadIdx.x;

    fill_tw(tw, tid);
    for (int i = tid; i < 4096; i += FFT_NT) {
        s[dr12(i)] = make_float2(src0[i], src1[i]);
    }
    __syncthreads();
    fft4096_r4(s, tw, tid, false);

    for (int f = tid; f < FLEN; f += FFT_NT) {
        float2 cf = s[f];
        float2 cn = s[(4096 - f) & 4095];
        dst0[f] = make_float2(0.5f * (cf.x + cn.x), 0.5f * (cf.y - cn.y));
        dst1[f] = make_float2(0.5f * (cf.y + cn.y), 0.5f * (cn.x - cf.x));
    }
}

// ---------------- selector MLP ----------------
#define SEL_TF 16
__global__ __launch_bounds__(128) void selector_kernel(
    const float* __restrict__ qW1, const float* __restrict__ qb1,
    const float* __restrict__ qW2, const float* __restrict__ qb2,
    const float* __restrict__ kW1, const float* __restrict__ kb1,
    const float* __restrict__ kW2, const float* __restrict__ kb2,
    const float* __restrict__ q_noise, const float* __restrict__ k_noise)
{
    const int chunk = blockIdx.x;
    const int b = blockIdx.y;
    const int tensor = blockIdx.z;
    const float2* Freq = tensor ? g_Kf : g_Qf;
    const float* W1 = tensor ? kW1 : qW1;
    const float* b1 = tensor ? kb1 : qb1;
    const float* W2 = tensor ? kW2 : qW2;
    const float* b2 = tensor ? kb2 : qb2;
    const float* nz = tensor ? k_noise : q_noise;
    float* z = tensor ? g_zk : g_zq;

    __shared__ float W1s[64 * 128];
    __shared__ float xr[128];
    __shared__ float h1[64];
    __shared__ float lg[2];
    const int tid = threadIdx.x;

    for (int i = tid; i < 64 * 128; i += 128) W1s[i] = W1[i];
    __syncthreads();

    const int f0 = chunk * SEL_TF;
    for (int f = f0; f < f0 + SEL_TF && f < FLEN; f++) {
        xr[tid] = Freq[(size_t)(b * 128 + tid) * FLEN + f].x;
        __syncthreads();

        if (tid < 64) {
            float acc = b1[tid];
            const float* w = W1s + tid * 128;
            #pragma unroll 16
            for (int d = 0; d < 128; d++) acc += xr[d] * w[d];
            h1[tid] = fmaxf(acc, 0.f);
        }
        __syncthreads();
        if (tid < 2) {
            float acc = b2[tid];
            const float* w = W2 + tid * 64;
            #pragma unroll 8
            for (int j = 0; j < 64; j++) acc += h1[j] * w[j];
            float n = nz[((size_t)b * FLEN + f) * 2 + tid];
            float g = -logf(-logf(n + GEPS) + GEPS);
            lg[tid] = acc + g;
        }
        __syncthreads();
        if (tid == 0) z[b * FLEN + f] = 1.f / (1.f + expf(lg[0] - lg[1]));
        __syncthreads();
    }
}

__global__ __launch_bounds__(FFT_NT) void fft_inv_kernel()
{
    __shared__ float2 s[4096];
    __shared__ float2 tw[1024];
    const int blk = blockIdx.x;
    const int tensor = blk >> 7;
    const int pr = blk & 127;
    const int b = pr >> 6;
    const int j = pr & 63;
    const int row0 = b * 128 + 2 * j;
    const float2* src0 = (tensor ? g_Kf : g_Qf) + (size_t)row0 * FLEN;
    const float2* src1 = src0 + FLEN;
    const float* z = (tensor ? g_zk : g_zq) + (size_t)b * FLEN;
    __nv_bfloat16* dst0 = (tensor ? g_kf_bf : g_qf_bf) + (size_t)row0 * LSEQ;
    __nv_bfloat16* dst1 = dst0 + LSEQ;
    const int tid = threadIdx.x;

    fill_tw(tw, tid);
    for (int i = tid; i < 4096; i += FFT_NT) {
        int f = (i <= 2048) ? i : (4096 - i);
        float zz = z[f];
        float2 a = src0[f];
        float2 bb = src1[f];
        if (i > 2048) { a.y = -a.y; bb.y = -bb.y; }
        a.x *= zz; a.y *= zz; bb.x *= zz; bb.y *= zz;
        s[dr12(i)] = make_float2(a.x - bb.y, a.y + bb.x);
    }
    __syncthreads();
    fft4096_r4(s, tw, tid, true);
    const float inv = 1.f / 4096.f;
    for (int i = tid; i < 4096; i += FFT_NT) {
        float2 v = s[i];
        dst0[i] = __float2bfloat16(v.x * inv);
        dst1[i] = __float2bfloat16(v.y * inv);
    }
}

// ---------------- scores GEMM: bf16 mma.m16n8k16 + cp.async double buffer ----------------
__global__ __launch_bounds__(256) void gemm_scores_bf16(float* __restrict__ out)
{
    __shared__ __align__(16) __nv_bfloat16 Qs[2][32][136];
    __shared__ __align__(16) __nv_bfloat16 Ks[2][32][136];

    const int b  = blockIdx.z;
    const int l0 = blockIdx.y * 128;
    const int m0 = blockIdx.x * 128;
    const __nv_bfloat16* A  = g_qf_bf + (size_t)b * HDIM * LSEQ;
    const __nv_bfloat16* Bm = g_kf_bf + (size_t)b * HDIM * LSEQ;

    const int tid  = threadIdx.x;
    const int warp = tid >> 5, lane = tid & 31;
    const int g = lane >> 2, tg = lane & 3;
    const int wl = (warp & 1) * 64;
    const int wn = (warp >> 1) * 32;

    const int lr   = lane & 7;
    const int koff = lr + ((lane & 16) ? 8 : 0);
    const int coff = (lane & 8) ? 8 : 0;
    const int kb   = lr + ((lane & 8) ? 8 : 0);
    const int cb   = (lane & 16) ? 8 : 0;

    float acc[4][4][4];
    #pragma unroll
    for (int i = 0; i < 4; i++)
        #pragma unroll
        for (int j = 0; j < 4; j++)
            #pragma unroll
            for (int c = 0; c < 4; c++) acc[i][j][c] = 0.f;

    auto load_chunk = [&](int kc, int bufi) {
        #pragma unroll
        for (int it = 0; it < 2; it++) {
            int idx = tid + 256 * it;
            int k  = idx >> 4;
            int c8 = (idx & 15) << 3;
            cp16(&Qs[bufi][k][c8], A  + (size_t)(kc * 32 + k) * LSEQ + l0 + c8);
            cp16(&Ks[bufi][k][c8], Bm + (size_t)(kc * 32 + k) * LSEQ + m0 + c8);
        }
        asm volatile("cp.async.commit_group;");
    };

    load_chunk(0, 0);

    #pragma unroll 1
    for (int kc = 0; kc < 4; kc++) {
        const int buf = kc & 1;
        if (kc < 3) load_chunk(kc + 1, buf ^ 1);
        if (kc < 3) asm volatile("cp.async.wait_group 1;");
        else        asm volatile("cp.async.wait_group 0;");
        __syncthreads();

        #pragma unroll
        for (int ks = 0; ks < 2; ks++) {
            const int k0 = ks * 16;
            uint32_t a[4][4];
            #pragma unroll
            for (int i = 0; i < 4; i++) {
                uint32_t addr = sptr(&Qs[buf][k0 + koff][wl + 16 * i + coff]);
                asm volatile(
                    "ldmatrix.sync.aligned.m8n8.x4.trans.shared.b16 {%0,%1,%2,%3}, [%4];"
                    : "=r"(a[i][0]), "=r"(a[i][1]), "=r"(a[i][2]), "=r"(a[i][3])
                    : "r"(addr));
            }
            uint32_t bfr[2][4];
            #pragma unroll
            for (int jj = 0; jj < 2; jj++) {
                uint32_t addr = sptr(&Ks[buf][k0 + kb][wn + 16 * jj + cb]);
                asm volatile(
                    "ldmatrix.sync.aligned.m8n8.x4.trans.shared.b16 {%0,%1,%2,%3}, [%4];"
                    : "=r"(bfr[jj][0]), "=r"(bfr[jj][1]), "=r"(bfr[jj][2]), "=r"(bfr[jj][3])
                    : "r"(addr));
            }
            #pragma unroll
            for (int i = 0; i < 4; i++)
                #pragma unroll
                for (int j = 0; j < 4; j++) {
                    uint32_t b0 = bfr[j >> 1][2 * (j & 1)];
                    uint32_t b1 = bfr[j >> 1][2 * (j & 1) + 1];
                    asm volatile(
                        "mma.sync.aligned.m16n8k16.row.col.f32.bf16.bf16.f32 "
                        "{%0,%1,%2,%3},{%4,%5,%6,%7},{%8,%9},{%0,%1,%2,%3};"
                        : "+f"(acc[i][j][0]), "+f"(acc[i][j][1]),
                          "+f"(acc[i][j][2]), "+f"(acc[i][j][3])
                        : "r"(a[i][0]), "r"(a[i][1]), "r"(a[i][2]), "r"(a[i][3]),
                          "r"(b0), "r"(b1));
                }
        }
        __syncthreads();
    }

    #pragma unroll
    for (int i = 0; i < 4; i++) {
        int row0 = l0 + wl + i * 16 + g;
        #pragma unroll
        for (int j = 0; j < 4; j++) {
            int col = m0 + wn + j * 8 + 2 * tg;
            float2 v0 = make_float2(acc[i][j][0] * INV_SQRT_DK, acc[i][j][1] * INV_SQRT_DK);
            float2 v1 = make_float2(acc[i][j][2] * INV_SQRT_DK, acc[i][j][3] * INV_SQRT_DK);
            *(float2*)(out + ((size_t)b * LSEQ + row0    ) * LSEQ + col) = v0;
            *(float2*)(out + ((size_t)b * LSEQ + row0 + 8) * LSEQ + col) = v1;
        }
    }
}

// ---------------- masked row softmax, 512 threads ----------------
__device__ __forceinline__ float warpMax(float v) {
    #pragma unroll
    for (int o = 16; o; o >>= 1) v = fmaxf(v, __shfl_xor_sync(0xffffffffu, v, o));
    return v;
}
__device__ __forceinline__ float warpSum(float v) {
    #pragma unroll
    for (int o = 16; o; o >>= 1) v += __shfl_xor_sync(0xffffffffu, v, o);
    return v;
}

__global__ __launch_bounds__(512) void softmax_kernel(float* __restrict__ out,
                                                      const int* __restrict__ mask)
{
    const int row = blockIdx.x;
    const int b = row >> 12;
    float* p = out + (size_t)row * LSEQ;
    const int* mrow = mask + (size_t)b * LSEQ;
    const int tid = threadIdx.x;

    __shared__ float red[16];
    __shared__ float bc;

    float4 v[2];
    float mx = -3.0e38f;
    #pragma unroll
    for (int i = 0; i < 2; i++) {
        int c4 = tid + 512 * i;
        float4 s = ((const float4*)p)[c4];
        int4 m = ((const int4*)mrow)[c4];
        s.x = (m.x == 0) ? -1.0e9f : s.x;
        s.y = (m.y == 0) ? -1.0e9f : s.y;
        s.z = (m.z == 0) ? -1.0e9f : s.z;
        s.w = (m.w == 0) ? -1.0e9f : s.w;
        v[i] = s;
        mx = fmaxf(mx, fmaxf(fmaxf(s.x, s.y), fmaxf(s.z, s.w)));
    }
    mx = warpMax(mx);
    if ((tid & 31) == 0) red[tid >> 5] = mx;
    __syncthreads();
    if (tid < 32) {
        float m2 = (tid < 16) ? red[tid] : -3.0e38f;
        m2 = warpMax(m2);
        if (tid == 0) bc = m2;
    }
    __syncthreads();
    mx = bc;

    float sum = 0.f;
    #pragma unroll
    for (int i = 0; i < 2; i++) {
        v[i].x = __expf(v[i].x - mx);
        v[i].y = __expf(v[i].y - mx);
        v[i].z = __expf(v[i].z - mx);
        v[i].w = __expf(v[i].w - mx);
        sum += v[i].x + v[i].y + v[i].z + v[i].w;
    }
    sum = warpSum(sum);
    if ((tid & 31) == 0) red[tid >> 5] = sum;
    __syncthreads();
    if (tid < 32) {
        float s2 = (tid < 16) ? red[tid] : 0.f;
        s2 = warpSum(s2);
        if (tid == 0) bc = s2;
    }
    __syncthreads();
    const float inv = 1.f / bc;

    #pragma unroll
    for (int i = 0; i < 2; i++) {
        float4 o = make_float4(v[i].x * inv, v[i].y * inv, v[i].z * inv, v[i].w * inv);
        ((float4*)p)[tid + 512 * i] = o;
    }
}

// ---------------- launch ----------------
extern "C" void kernel_launch(void* const* d_in, const int* in_sizes, int n_in,
                              void* d_out, int out_size)
{
    const float* query   = (const float*)d_in[0];
    const float* key     = (const float*)d_in[1];
    const int*   mask    = (const int*)  d_in[2];
    const float* Wq      = (const float*)d_in[3];
    const float* bq      = (const float*)d_in[4];
    const float* Wk      = (const float*)d_in[5];
    const float* bk      = (const float*)d_in[6];
    const float* qW1     = (const float*)d_in[7];
    const float* qb1     = (const float*)d_in[8];
    const float* qW2     = (const float*)d_in[9];
    const float* qb2     = (const float*)d_in[10];
    const float* kW1     = (const float*)d_in[11];
    const float* kb1     = (const float*)d_in[12];
    const float* kW2     = (const float*)d_in[13];
    const float* kb2     = (const float*)d_in[14];
    const float* q_noise = (const float*)d_in[15];
    const float* k_noise = (const float*)d_in[16];
    float* out = (float*)d_out;

    cudaFuncSetAttribute(proj_tc, cudaFuncAttributeMaxDynamicSharedMemorySize,
                         PROJ_SMEM_BYTES);

    proj_tc<<<dim3(64, 2), 256, PROJ_SMEM_BYTES>>>(query, key, Wq, bq, Wk, bk);
    fft_fwd_kernel<<<256, FFT_NT>>>();
    selector_kernel<<<dim3((FLEN + SEL_TF - 1) / SEL_TF, BATCH, 2), 128>>>(
        qW1, qb1, qW2, qb2, kW1, kb1, kW2, kb2, q_noise, k_noise);
    fft_inv_kernel<<<256, FFT_NT>>>();
    gemm_scores_bf16<<<dim3(32, 32, BATCH), 256>>>(out);
    softmax_kernel<<<BATCH * LSEQ, 512>>>(out, mask);
}

// round 7
// speedup vs baseline: 5.0344x; 1.2074x over previous
#include <cuda_runtime.h>
#include <cuda_bf16.h>
#include <cstdint>

#define BATCH 2
#define LSEQ 4096
#define DMODEL 768
#define HDIM 128
#define FLEN 2049
#define INV_SQRT_DK 0.08838834764831845f
#define GEPS 1e-9f
#define PI_F 3.14159265358979323846f

// ---------------- scratch ----------------
__device__ float  g_q [BATCH*HDIM*LSEQ];   // projected q, layout [b][d][l]
__device__ float  g_k [BATCH*HDIM*LSEQ];
__device__ float2 g_Qf[BATCH*HDIM*FLEN];   // rfft of q rows
__device__ float2 g_Kf[BATCH*HDIM*FLEN];
__device__ float  g_ReT[2*BATCH*FLEN*HDIM]; // real parts, freq-major: [(t*B+b)*FLEN+f][d]
__device__ float  g_zq[BATCH*FLEN];        // selector gains
__device__ float  g_zk[BATCH*FLEN];
__device__ __nv_bfloat16 g_qf_bf[BATCH*HDIM*LSEQ];  // filtered q (bf16)
__device__ __nv_bfloat16 g_kf_bf[BATCH*HDIM*LSEQ];
__device__ float  g_rowsum[BATCH*LSEQ];

__device__ __forceinline__ uint32_t sptr(const void* p) {
    return (uint32_t)__cvta_generic_to_shared(p);
}
__device__ __forceinline__ void cp16(void* smem_dst, const void* gmem_src) {
    asm volatile("cp.async.ca.shared.global [%0], [%1], 16;"
                 :: "r"(sptr(smem_dst)), "l"(gmem_src));
}

// ---------------- projection GEMM: tf32 mma + 3-stage cp.async ----------------
#define PROJ_STAGES 3
#define PROJ_BK 32
#define PROJ_KP 36
#define PROJ_MAT (128 * PROJ_KP)
#define PROJ_SMEM_FLOATS (PROJ_STAGES * PROJ_MAT * 2)
#define PROJ_SMEM_BYTES (PROJ_SMEM_FLOATS * 4)

__global__ __launch_bounds__(256) void proj_tc(
    const float* __restrict__ query, const float* __restrict__ key,
    const float* __restrict__ Wq, const float* __restrict__ bq,
    const float* __restrict__ Wk, const float* __restrict__ bk)
{
    extern __shared__ float dsm[];
    float* Wbase = dsm;
    float* Xbase = dsm + PROJ_STAGES * PROJ_MAT;

    const int tensor = blockIdx.y;
    const float* X  = tensor ? key : query;
    const float* W  = tensor ? Wk  : Wq;
    const float* bi = tensor ? bk  : bq;
    float* dst = tensor ? g_k : g_q;

    const int l0 = blockIdx.x * 128;
    const int tid  = threadIdx.x;
    const int warp = tid >> 5, lane = tid & 31;
    const int g = lane >> 2, tg = lane & 3;
    const int wd = (warp & 1) * 64;
    const int wn = (warp >> 1) * 32;

    float acc[4][4][4];
    #pragma unroll
    for (int i = 0; i < 4; i++)
        #pragma unroll
        for (int j = 0; j < 4; j++)
            #pragma unroll
            for (int c = 0; c < 4; c++) acc[i][j][c] = 0.f;

    auto load_stage = [&](int kc, int st) {
        const int k0 = kc * PROJ_BK;
        float* Ws = Wbase + st * PROJ_MAT;
        float* Xs = Xbase + st * PROJ_MAT;
        #pragma unroll
        for (int it = 0; it < 4; it++) {
            int idx = tid + 256 * it;
            int row = idx >> 3;
            int seg = (idx & 7) << 2;
            cp16(Ws + row * PROJ_KP + seg, W + (size_t)row * DMODEL + k0 + seg);
            cp16(Xs + row * PROJ_KP + seg, X + (size_t)(l0 + row) * DMODEL + k0 + seg);
        }
        asm volatile("cp.async.commit_group;");
    };

    load_stage(0, 0);
    load_stage(1, 1);

    const int NCHUNK = DMODEL / PROJ_BK;
    #pragma unroll 1
    for (int kc = 0; kc < NCHUNK; kc++) {
        const int st = kc % PROJ_STAGES;
        asm volatile("cp.async.wait_group 1;");
        __syncthreads();
        if (kc + 2 < NCHUNK) load_stage(kc + 2, (kc + 2) % PROJ_STAGES);

        const float* Ws = Wbase + st * PROJ_MAT;
        const float* Xs = Xbase + st * PROJ_MAT;

        #pragma unroll
        for (int ks = 0; ks < 4; ks++) {
            const int k = ks * 8;
            uint32_t a[4][4], bf[4][2];
            #pragma unroll
            for (int i = 0; i < 4; i++) {
                int d = wd + i * 16 + g;
                a[i][0] = __float_as_uint(Ws[(d    ) * PROJ_KP + k + tg    ]);
                a[i][1] = __float_as_uint(Ws[(d + 8) * PROJ_KP + k + tg    ]);
                a[i][2] = __float_as_uint(Ws[(d    ) * PROJ_KP + k + tg + 4]);
                a[i][3] = __float_as_uint(Ws[(d + 8) * PROJ_KP + k + tg + 4]);
            }
            #pragma unroll
            for (int j = 0; j < 4; j++) {
                int n = wn + j * 8 + g;
                bf[j][0] = __float_as_uint(Xs[n * PROJ_KP + k + tg    ]);
                bf[j][1] = __float_as_uint(Xs[n * PROJ_KP + k + tg + 4]);
            }
            #pragma unroll
            for (int i = 0; i < 4; i++)
                #pragma unroll
                for (int j = 0; j < 4; j++) {
                    asm volatile(
                        "mma.sync.aligned.m16n8k8.row.col.f32.tf32.tf32.f32 "
                        "{%0,%1,%2,%3},{%4,%5,%6,%7},{%8,%9},{%0,%1,%2,%3};"
                        : "+f"(acc[i][j][0]), "+f"(acc[i][j][1]),
                          "+f"(acc[i][j][2]), "+f"(acc[i][j][3])
                        : "r"(a[i][0]), "r"(a[i][1]), "r"(a[i][2]), "r"(a[i][3]),
                          "r"(bf[j][0]), "r"(bf[j][1]));
                }
        }
        __syncthreads();
    }

    #pragma unroll
    for (int i = 0; i < 4; i++) {
        int d0 = wd + i * 16 + g;
        float bv0 = bi[d0], bv1 = bi[d0 + 8];
        #pragma unroll
        for (int j = 0; j < 4; j++) {
            int gl = l0 + wn + j * 8 + 2 * tg;
            int b  = gl >> 12;
            int l  = gl & 4095;
            float* o0 = dst + (size_t)((b << 7) + d0    ) * LSEQ + l;
            float* o1 = dst + (size_t)((b << 7) + d0 + 8) * LSEQ + l;
            *(float2*)o0 = make_float2(acc[i][j][0] + bv0, acc[i][j][1] + bv0);
            *(float2*)o1 = make_float2(acc[i][j][2] + bv1, acc[i][j][3] + bv1);
        }
    }
}

// ---------------- radix-4 4096-pt FFT ----------------
#define FFT_NT 512
__device__ __forceinline__ void fill_tw(float2* tw, int tid)
{
    for (int j = tid; j < 1024; j += FFT_NT) {
        float ang = -PI_F * (float)j / 2048.0f;
        float s, c;
        __sincosf(ang, &s, &c);
        tw[j] = make_float2(c, s);
    }
}

__device__ __forceinline__ float2 cmul(float2 a, float2 b) {
    return make_float2(a.x*b.x - a.y*b.y, a.x*b.y + a.y*b.x);
}

__device__ __forceinline__ int dr12(int i) {
    unsigned y = __brev((unsigned)i) >> 20;
    return (int)(((y & 0x555u) << 1) | ((y >> 1) & 0x555u));
}

__device__ __forceinline__ void fft4096_r4(float2* s, const float2* tw, int tid, bool inv)
{
    #pragma unroll 1
    for (int st = 0; st < 6; st++) {
        const int twoSt = 2 * st;
        const int L = 1 << twoSt;
        const int shift = 10 - twoSt;
        #pragma unroll
        for (int tt = 0; tt < 1024 / FFT_NT; tt++) {
            int t = tid + tt * FFT_NT;
            int j  = t & (L - 1);
            int i0 = ((t >> twoSt) << (twoSt + 2)) + j;
            int e  = j << shift;
            float2 w1 = tw[e];
            if (inv) w1.y = -w1.y;
            float2 w2 = cmul(w1, w1);
            float2 w3 = cmul(w1, w2);

            float2 u0 = s[i0];
            float2 u1 = cmul(s[i0 + L],   w1);
            float2 u2 = cmul(s[i0 + 2*L], w2);
            float2 u3 = cmul(s[i0 + 3*L], w3);

            float2 v0 = make_float2(u0.x + u2.x, u0.y + u2.y);
            float2 v1 = make_float2(u0.x - u2.x, u0.y - u2.y);
            float2 v2 = make_float2(u1.x + u3.x, u1.y + u3.y);
            float2 v3 = make_float2(u1.x - u3.x, u1.y - u3.y);

            s[i0]       = make_float2(v0.x + v2.x, v0.y + v2.y);
            s[i0 + 2*L] = make_float2(v0.x - v2.x, v0.y - v2.y);
            if (!inv) {
                s[i0 + L]   = make_float2(v1.x + v3.y, v1.y - v3.x);
                s[i0 + 3*L] = make_float2(v1.x - v3.y, v1.y + v3.x);
            } else {
                s[i0 + L]   = make_float2(v1.x - v3.y, v1.y + v3.x);
                s[i0 + 3*L] = make_float2(v1.x + v3.y, v1.y - v3.x);
            }
        }
        __syncthreads();
    }
}

// forward: pack 2 real rows per complex FFT, Hermitian unpack; also emit
// freq-major real parts for the selector.
__global__ __launch_bounds__(FFT_NT) void fft_fwd_kernel()
{
    __shared__ float2 s[4096];
    __shared__ float2 tw[1024];
    const int blk = blockIdx.x;
    const int tensor = blk >> 7;
    const int pr = blk & 127;
    const int b = pr >> 6;
    const int j = pr & 63;
    const int row0 = b * 128 + 2 * j;
    const float* src0 = (tensor ? g_k : g_q) + (size_t)row0 * LSEQ;
    const float* src1 = src0 + LSEQ;
    float2* dst0 = (tensor ? g_Kf : g_Qf) + (size_t)row0 * FLEN;
    float2* dst1 = dst0 + FLEN;
    float* rt = g_ReT + ((size_t)(tensor * BATCH + b) * FLEN) * HDIM;
    const int tid = threadIdx.x;

    fill_tw(tw, tid);
    for (int i = tid; i < 4096; i += FFT_NT) {
        s[dr12(i)] = make_float2(src0[i], src1[i]);
    }
    __syncthreads();
    fft4096_r4(s, tw, tid, false);

    for (int f = tid; f < FLEN; f += FFT_NT) {
        float2 cf = s[f];
        float2 cn = s[(4096 - f) & 4095];
        float re0 = 0.5f * (cf.x + cn.x);
        float re1 = 0.5f * (cf.y + cn.y);
        dst0[f] = make_float2(re0, 0.5f * (cf.y - cn.y));
        dst1[f] = make_float2(re1, 0.5f * (cn.x - cf.x));
        rt[(size_t)f * HDIM + 2 * j    ] = re0;
        rt[(size_t)f * HDIM + 2 * j + 1] = re1;
    }
}

// ---------------- selector MLP: conflict-free, 2 freqs per iter ----------------
#define SEL_CHUNK 32
__global__ __launch_bounds__(128) void selector_kernel(
    const float* __restrict__ qW1, const float* __restrict__ qb1,
    const float* __restrict__ qW2, const float* __restrict__ qb2,
    const float* __restrict__ kW1, const float* __restrict__ kb1,
    const float* __restrict__ kW2, const float* __restrict__ kb2,
    const float* __restrict__ q_noise, const float* __restrict__ k_noise)
{
    const int chunk = blockIdx.x;
    const int b = blockIdx.y;
    const int tensor = blockIdx.z;
    const float* ReT = g_ReT + ((size_t)(tensor * BATCH + b) * FLEN) * HDIM;
    const float* W1 = tensor ? kW1 : qW1;
    const float* b1 = tensor ? kb1 : qb1;
    const float* W2 = tensor ? kW2 : qW2;
    const float* b2 = tensor ? kb2 : qb2;
    const float* nz = tensor ? k_noise : q_noise;
    float* z = tensor ? g_zk : g_zq;

    __shared__ float W1sT[128 * 65];   // [d][u], pad 65 -> conflict-free
    __shared__ float xr[2][128];
    __shared__ float h1[2][64];
    __shared__ float lg[2][2];
    const int tid = threadIdx.x;

    for (int idx = tid; idx < 64 * 128; idx += 128) {
        int u = idx >> 7, d = idx & 127;
        W1sT[d * 65 + u] = W1[idx];
    }
    __syncthreads();

    const int u  = tid & 63;
    const int ff = tid >> 6;

    #pragma unroll 1
    for (int fp = 0; fp < SEL_CHUNK / 2; fp++) {
        const int f0 = chunk * SEL_CHUNK + fp * 2;
        if (f0 >= FLEN) break;

        xr[0][tid] = ReT[(size_t)f0 * HDIM + tid];
        xr[1][tid] = (f0 + 1 < FLEN) ? ReT[(size_t)(f0 + 1) * HDIM + tid] : 0.f;
        __syncthreads();

        float a = b1[u];
        #pragma unroll 16
        for (int d = 0; d < 128; d++)
            a = fmaf(xr[ff][d], W1sT[d * 65 + u], a);
        h1[ff][u] = fmaxf(a, 0.f);
        __syncthreads();

        if (tid < 4) {
            int f2 = tid >> 1, c = tid & 1;
            int f = f0 + f2;
            if (f < FLEN) {
                float acc2 = b2[c];
                const float* w2 = W2 + c * 64;
                #pragma unroll 8
                for (int j2 = 0; j2 < 64; j2++) acc2 += h1[f2][j2] * w2[j2];
                float n = nz[((size_t)b * FLEN + f) * 2 + c];
                float gg = -logf(-logf(n + GEPS) + GEPS);
                lg[f2][c] = acc2 + gg;
            }
        }
        __syncthreads();
        if (tid < 2) {
            int f = f0 + tid;
            if (f < FLEN) z[b * FLEN + f] = 1.f / (1.f + expf(lg[tid][0] - lg[tid][1]));
        }
        __syncthreads();
    }
}

// inverse: pack 2 filtered rows per complex iFFT; store bf16.
__global__ __launch_bounds__(FFT_NT) void fft_inv_kernel()
{
    __shared__ float2 s[4096];
    __shared__ float2 tw[1024];
    const int blk = blockIdx.x;
    const int tensor = blk >> 7;
    const int pr = blk & 127;
    const int b = pr >> 6;
    const int j = pr & 63;
    const int row0 = b * 128 + 2 * j;
    const float2* src0 = (tensor ? g_Kf : g_Qf) + (size_t)row0 * FLEN;
    const float2* src1 = src0 + FLEN;
    const float* z = (tensor ? g_zk : g_zq) + (size_t)b * FLEN;
    __nv_bfloat16* dst0 = (tensor ? g_kf_bf : g_qf_bf) + (size_t)row0 * LSEQ;
    __nv_bfloat16* dst1 = dst0 + LSEQ;
    const int tid = threadIdx.x;

    fill_tw(tw, tid);
    for (int i = tid; i < 4096; i += FFT_NT) {
        int f = (i <= 2048) ? i : (4096 - i);
        float zz = z[f];
        float2 a = src0[f];
        float2 bb = src1[f];
        if (i > 2048) { a.y = -a.y; bb.y = -bb.y; }
        a.x *= zz; a.y *= zz; bb.x *= zz; bb.y *= zz;
        s[dr12(i)] = make_float2(a.x - bb.y, a.y + bb.x);
    }
    __syncthreads();
    fft4096_r4(s, tw, tid, true);
    const float inv = 1.f / 4096.f;
    for (int i = tid; i < 4096; i += FFT_NT) {
        float2 v = s[i];
        dst0[i] = __float2bfloat16(v.x * inv);
        dst1[i] = __float2bfloat16(v.y * inv);
    }
}

// ---------------- zero row sums ----------------
__global__ void zero_sums()
{
    g_rowsum[blockIdx.x * 512 + threadIdx.x] = 0.f;
}

// ---------------- scores GEMM + fused mask/exp/rowsum epilogue ----------------
__global__ __launch_bounds__(256) void gemm_scores_bf16(float* __restrict__ out,
                                                        const int* __restrict__ mask)
{
    __shared__ __align__(16) __nv_bfloat16 Qs[2][32][136];
    __shared__ __align__(16) __nv_bfloat16 Ks[2][32][136];

    const int b  = blockIdx.z;
    const int l0 = blockIdx.y * 128;
    const int m0 = blockIdx.x * 128;
    const __nv_bfloat16* A  = g_qf_bf + (size_t)b * HDIM * LSEQ;
    const __nv_bfloat16* Bm = g_kf_bf + (size_t)b * HDIM * LSEQ;
    const int* mrow = mask + (size_t)b * LSEQ;

    const int tid  = threadIdx.x;
    const int warp = tid >> 5, lane = tid & 31;
    const int g = lane >> 2, tg = lane & 3;
    const int wl = (warp & 1) * 64;
    const int wn = (warp >> 1) * 32;

    const int lr   = lane & 7;
    const int koff = lr + ((lane & 16) ? 8 : 0);
    const int coff = (lane & 8) ? 8 : 0;
    const int kb   = lr + ((lane & 8) ? 8 : 0);
    const int cb   = (lane & 16) ? 8 : 0;

    float acc[4][4][4];
    #pragma unroll
    for (int i = 0; i < 4; i++)
        #pragma unroll
        for (int j = 0; j < 4; j++)
            #pragma unroll
            for (int c = 0; c < 4; c++) acc[i][j][c] = 0.f;

    auto load_chunk = [&](int kc, int bufi) {
        #pragma unroll
        for (int it = 0; it < 2; it++) {
            int idx = tid + 256 * it;
            int k  = idx >> 4;
            int c8 = (idx & 15) << 3;
            cp16(&Qs[bufi][k][c8], A  + (size_t)(kc * 32 + k) * LSEQ + l0 + c8);
            cp16(&Ks[bufi][k][c8], Bm + (size_t)(kc * 32 + k) * LSEQ + m0 + c8);
        }
        asm volatile("cp.async.commit_group;");
    };

    load_chunk(0, 0);

    #pragma unroll 1
    for (int kc = 0; kc < 4; kc++) {
        const int buf = kc & 1;
        if (kc < 3) load_chunk(kc + 1, buf ^ 1);
        if (kc < 3) asm volatile("cp.async.wait_group 1;");
        else        asm volatile("cp.async.wait_group 0;");
        __syncthreads();

        #pragma unroll
        for (int ks = 0; ks < 2; ks++) {
            const int k0 = ks * 16;
            uint32_t a[4][4];
            #pragma unroll
            for (int i = 0; i < 4; i++) {
                uint32_t addr = sptr(&Qs[buf][k0 + koff][wl + 16 * i + coff]);
                asm volatile(
                    "ldmatrix.sync.aligned.m8n8.x4.trans.shared.b16 {%0,%1,%2,%3}, [%4];"
                    : "=r"(a[i][0]), "=r"(a[i][1]), "=r"(a[i][2]), "=r"(a[i][3])
                    : "r"(addr));
            }
            uint32_t bfr[2][4];
            #pragma unroll
            for (int jj = 0; jj < 2; jj++) {
                uint32_t addr = sptr(&Ks[buf][k0 + kb][wn + 16 * jj + cb]);
                asm volatile(
                    "ldmatrix.sync.aligned.m8n8.x4.trans.shared.b16 {%0,%1,%2,%3}, [%4];"
                    : "=r"(bfr[jj][0]), "=r"(bfr[jj][1]), "=r"(bfr[jj][2]), "=r"(bfr[jj][3])
                    : "r"(addr));
            }
            #pragma unroll
            for (int i = 0; i < 4; i++)
                #pragma unroll
                for (int j = 0; j < 4; j++) {
                    uint32_t b0 = bfr[j >> 1][2 * (j & 1)];
                    uint32_t b1 = bfr[j >> 1][2 * (j & 1) + 1];
                    asm volatile(
                        "mma.sync.aligned.m16n8k16.row.col.f32.bf16.bf16.f32 "
                        "{%0,%1,%2,%3},{%4,%5,%6,%7},{%8,%9},{%0,%1,%2,%3};"
                        : "+f"(acc[i][j][0]), "+f"(acc[i][j][1]),
                          "+f"(acc[i][j][2]), "+f"(acc[i][j][3])
                        : "r"(a[i][0]), "r"(a[i][1]), "r"(a[i][2]), "r"(a[i][3]),
                          "r"(b0), "r"(b1));
                }
        }
        __syncthreads();
    }

    // fused epilogue: mask -> exp -> store unnormalized probs + row sums
    #pragma unroll
    for (int i = 0; i < 4; i++) {
        int row0 = l0 + wl + i * 16 + g;
        float rs0 = 0.f, rs1 = 0.f;
        #pragma unroll
        for (int j = 0; j < 4; j++) {
            int col = m0 + wn + j * 8 + 2 * tg;
            int mv0 = mrow[col], mv1 = mrow[col + 1];
            float p00 = mv0 ? __expf(acc[i][j][0] * INV_SQRT_DK) : 0.f;
            float p01 = mv1 ? __expf(acc[i][j][1] * INV_SQRT_DK) : 0.f;
            float p10 = mv0 ? __expf(acc[i][j][2] * INV_SQRT_DK) : 0.f;
            float p11 = mv1 ? __expf(acc[i][j][3] * INV_SQRT_DK) : 0.f;
            *(float2*)(out + ((size_t)b * LSEQ + row0    ) * LSEQ + col) = make_float2(p00, p01);
            *(float2*)(out + ((size_t)b * LSEQ + row0 + 8) * LSEQ + col) = make_float2(p10, p11);
            rs0 += p00 + p01;
            rs1 += p10 + p11;
        }
        rs0 += __shfl_xor_sync(0xffffffffu, rs0, 1);
        rs0 += __shfl_xor_sync(0xffffffffu, rs0, 2);
        rs1 += __shfl_xor_sync(0xffffffffu, rs1, 1);
        rs1 += __shfl_xor_sync(0xffffffffu, rs1, 2);
        if (tg == 0) {
            atomicAdd(&g_rowsum[b * LSEQ + row0    ], rs0);
            atomicAdd(&g_rowsum[b * LSEQ + row0 + 8], rs1);
        }
    }
}

// ---------------- final normalize: pure streaming scale ----------------
__global__ __launch_bounds__(512) void scale_kernel(float* __restrict__ out)
{
    size_t i4 = (size_t)blockIdx.x * 512 + threadIdx.x;    // float4 index
    int row = (int)(i4 >> 10);                             // 1024 float4 per row
    float inv = 1.f / g_rowsum[row];
    float4 v = ((const float4*)out)[i4];
    v.x *= inv; v.y *= inv; v.z *= inv; v.w *= inv;
    ((float4*)out)[i4] = v;
}

// ---------------- launch ----------------
extern "C" void kernel_launch(void* const* d_in, const int* in_sizes, int n_in,
                              void* d_out, int out_size)
{
    const float* query   = (const float*)d_in[0];
    const float* key     = (const float*)d_in[1];
    const int*   mask    = (const int*)  d_in[2];
    const float* Wq      = (const float*)d_in[3];
    const float* bq      = (const float*)d_in[4];
    const float* Wk      = (const float*)d_in[5];
    const float* bk      = (const float*)d_in[6];
    const float* qW1     = (const float*)d_in[7];
    const float* qb1     = (const float*)d_in[8];
    const float* qW2     = (const float*)d_in[9];
    const float* qb2     = (const float*)d_in[10];
    const float* kW1     = (const float*)d_in[11];
    const float* kb1     = (const float*)d_in[12];
    const float* kW2     = (const float*)d_in[13];
    const float* kb2     = (const float*)d_in[14];
    const float* q_noise = (const float*)d_in[15];
    const float* k_noise = (const float*)d_in[16];
    float* out = (float*)d_out;

    cudaFuncSetAttribute(proj_tc, cudaFuncAttributeMaxDynamicSharedMemorySize,
                         PROJ_SMEM_BYTES);

    zero_sums<<<BATCH * LSEQ / 512, 512>>>();
    proj_tc<<<dim3(64, 2), 256, PROJ_SMEM_BYTES>>>(query, key, Wq, bq, Wk, bk);
    fft_fwd_kernel<<<256, FFT_NT>>>();
    selector_kernel<<<dim3((FLEN + SEL_CHUNK - 1) / SEL_CHUNK, BATCH, 2), 128>>>(
        qW1, qb1, qW2, qb2, kW1, kb1, kW2, kb2, q_noise, k_noise);
    fft_inv_kernel<<<256, FFT_NT>>>();
    gemm_scores_bf16<<<dim3(32, 32, BATCH), 256>>>(out, mask);
    scale_kernel<<<(int)((size_t)BATCH * LSEQ * LSEQ / 4 / 512), 512>>>(out);
}

// round 8
// speedup vs baseline: 5.3197x; 1.0567x over previous
#include <cuda_runtime.h>
#include <cuda_bf16.h>
#include <cstdint>

#define BATCH 2
#define LSEQ 4096
#define DMODEL 768
#define HDIM 128
#define FLEN 2049
#define INV_SQRT_DK 0.08838834764831845f
#define GEPS 1e-9f
#define PI_F 3.14159265358979323846f

// ---------------- scratch ----------------
__device__ float  g_q [BATCH*HDIM*LSEQ];   // projected q, layout [b][d][l]
__device__ float  g_k [BATCH*HDIM*LSEQ];
__device__ float2 g_Qf[BATCH*HDIM*FLEN];   // rfft of q rows
__device__ float2 g_Kf[BATCH*HDIM*FLEN];
__device__ float  g_ReT[2*BATCH*FLEN*HDIM]; // real parts, freq-major
__device__ float  g_zq[BATCH*FLEN];        // selector gains
__device__ float  g_zk[BATCH*FLEN];
__device__ __nv_bfloat16 g_qf_bf[BATCH*HDIM*LSEQ];  // filtered q (bf16)
__device__ __nv_bfloat16 g_kf_bf[BATCH*HDIM*LSEQ];
__device__ float  g_rowsum[BATCH*LSEQ];

__device__ __forceinline__ uint32_t sptr(const void* p) {
    return (uint32_t)__cvta_generic_to_shared(p);
}
__device__ __forceinline__ void cp16(void* smem_dst, const void* gmem_src) {
    asm volatile("cp.async.ca.shared.global [%0], [%1], 16;"
                 :: "r"(sptr(smem_dst)), "l"(gmem_src));
}

// ---------------- projection GEMM: tf32 mma + 3-stage cp.async ----------------
#define PROJ_STAGES 3
#define PROJ_BK 32
#define PROJ_KP 36
#define PROJ_MAT (128 * PROJ_KP)
#define PROJ_SMEM_FLOATS (PROJ_STAGES * PROJ_MAT * 2)
#define PROJ_SMEM_BYTES (PROJ_SMEM_FLOATS * 4)

__global__ __launch_bounds__(256) void proj_tc(
    const float* __restrict__ query, const float* __restrict__ key,
    const float* __restrict__ Wq, const float* __restrict__ bq,
    const float* __restrict__ Wk, const float* __restrict__ bk)
{
    extern __shared__ float dsm[];
    float* Wbase = dsm;
    float* Xbase = dsm + PROJ_STAGES * PROJ_MAT;

    const int tensor = blockIdx.y;
    const float* X  = tensor ? key : query;
    const float* W  = tensor ? Wk  : Wq;
    const float* bi = tensor ? bk  : bq;
    float* dst = tensor ? g_k : g_q;

    const int l0 = blockIdx.x * 128;
    const int tid  = threadIdx.x;
    const int warp = tid >> 5, lane = tid & 31;
    const int g = lane >> 2, tg = lane & 3;
    const int wd = (warp & 1) * 64;
    const int wn = (warp >> 1) * 32;

    float acc[4][4][4];
    #pragma unroll
    for (int i = 0; i < 4; i++)
        #pragma unroll
        for (int j = 0; j < 4; j++)
            #pragma unroll
            for (int c = 0; c < 4; c++) acc[i][j][c] = 0.f;

    auto load_stage = [&](int kc, int st) {
        const int k0 = kc * PROJ_BK;
        float* Ws = Wbase + st * PROJ_MAT;
        float* Xs = Xbase + st * PROJ_MAT;
        #pragma unroll
        for (int it = 0; it < 4; it++) {
            int idx = tid + 256 * it;
            int row = idx >> 3;
            int seg = (idx & 7) << 2;
            cp16(Ws + row * PROJ_KP + seg, W + (size_t)row * DMODEL + k0 + seg);
            cp16(Xs + row * PROJ_KP + seg, X + (size_t)(l0 + row) * DMODEL + k0 + seg);
        }
        asm volatile("cp.async.commit_group;");
    };

    load_stage(0, 0);
    load_stage(1, 1);

    const int NCHUNK = DMODEL / PROJ_BK;
    #pragma unroll 1
    for (int kc = 0; kc < NCHUNK; kc++) {
        const int st = kc % PROJ_STAGES;
        asm volatile("cp.async.wait_group 1;");
        __syncthreads();
        if (kc + 2 < NCHUNK) load_stage(kc + 2, (kc + 2) % PROJ_STAGES);

        const float* Ws = Wbase + st * PROJ_MAT;
        const float* Xs = Xbase + st * PROJ_MAT;

        #pragma unroll
        for (int ks = 0; ks < 4; ks++) {
            const int k = ks * 8;
            uint32_t a[4][4], bf[4][2];
            #pragma unroll
            for (int i = 0; i < 4; i++) {
                int d = wd + i * 16 + g;
                a[i][0] = __float_as_uint(Ws[(d    ) * PROJ_KP + k + tg    ]);
                a[i][1] = __float_as_uint(Ws[(d + 8) * PROJ_KP + k + tg    ]);
                a[i][2] = __float_as_uint(Ws[(d    ) * PROJ_KP + k + tg + 4]);
                a[i][3] = __float_as_uint(Ws[(d + 8) * PROJ_KP + k + tg + 4]);
            }
            #pragma unroll
            for (int j = 0; j < 4; j++) {
                int n = wn + j * 8 + g;
                bf[j][0] = __float_as_uint(Xs[n * PROJ_KP + k + tg    ]);
                bf[j][1] = __float_as_uint(Xs[n * PROJ_KP + k + tg + 4]);
            }
            #pragma unroll
            for (int i = 0; i < 4; i++)
                #pragma unroll
                for (int j = 0; j < 4; j++) {
                    asm volatile(
                        "mma.sync.aligned.m16n8k8.row.col.f32.tf32.tf32.f32 "
                        "{%0,%1,%2,%3},{%4,%5,%6,%7},{%8,%9},{%0,%1,%2,%3};"
                        : "+f"(acc[i][j][0]), "+f"(acc[i][j][1]),
                          "+f"(acc[i][j][2]), "+f"(acc[i][j][3])
                        : "r"(a[i][0]), "r"(a[i][1]), "r"(a[i][2]), "r"(a[i][3]),
                          "r"(bf[j][0]), "r"(bf[j][1]));
                }
        }
        __syncthreads();
    }

    #pragma unroll
    for (int i = 0; i < 4; i++) {
        int d0 = wd + i * 16 + g;
        float bv0 = bi[d0], bv1 = bi[d0 + 8];
        #pragma unroll
        for (int j = 0; j < 4; j++) {
            int gl = l0 + wn + j * 8 + 2 * tg;
            int b  = gl >> 12;
            int l  = gl & 4095;
            float* o0 = dst + (size_t)((b << 7) + d0    ) * LSEQ + l;
            float* o1 = dst + (size_t)((b << 7) + d0 + 8) * LSEQ + l;
            *(float2*)o0 = make_float2(acc[i][j][0] + bv0, acc[i][j][1] + bv0);
            *(float2*)o1 = make_float2(acc[i][j][2] + bv1, acc[i][j][3] + bv1);
        }
    }
}

// ---------------- radix-4 4096-pt FFT ----------------
#define FFT_NT 512
__device__ __forceinline__ void fill_tw(float2* tw, int tid)
{
    for (int j = tid; j < 1024; j += FFT_NT) {
        float ang = -PI_F * (float)j / 2048.0f;
        float s, c;
        __sincosf(ang, &s, &c);
        tw[j] = make_float2(c, s);
    }
}

__device__ __forceinline__ float2 cmul(float2 a, float2 b) {
    return make_float2(a.x*b.x - a.y*b.y, a.x*b.y + a.y*b.x);
}

__device__ __forceinline__ int dr12(int i) {
    unsigned y = __brev((unsigned)i) >> 20;
    return (int)(((y & 0x555u) << 1) | ((y >> 1) & 0x555u));
}

__device__ __forceinline__ void fft4096_r4(float2* s, const float2* tw, int tid, bool inv)
{
    #pragma unroll 1
    for (int st = 0; st < 6; st++) {
        const int twoSt = 2 * st;
        const int L = 1 << twoSt;
        const int shift = 10 - twoSt;
        #pragma unroll
        for (int tt = 0; tt < 1024 / FFT_NT; tt++) {
            int t = tid + tt * FFT_NT;
            int j  = t & (L - 1);
            int i0 = ((t >> twoSt) << (twoSt + 2)) + j;
            int e  = j << shift;
            float2 w1 = tw[e];
            if (inv) w1.y = -w1.y;
            float2 w2 = cmul(w1, w1);
            float2 w3 = cmul(w1, w2);

            float2 u0 = s[i0];
            float2 u1 = cmul(s[i0 + L],   w1);
            float2 u2 = cmul(s[i0 + 2*L], w2);
            float2 u3 = cmul(s[i0 + 3*L], w3);

            float2 v0 = make_float2(u0.x + u2.x, u0.y + u2.y);
            float2 v1 = make_float2(u0.x - u2.x, u0.y - u2.y);
            float2 v2 = make_float2(u1.x + u3.x, u1.y + u3.y);
            float2 v3 = make_float2(u1.x - u3.x, u1.y - u3.y);

            s[i0]       = make_float2(v0.x + v2.x, v0.y + v2.y);
            s[i0 + 2*L] = make_float2(v0.x - v2.x, v0.y - v2.y);
            if (!inv) {
                s[i0 + L]   = make_float2(v1.x + v3.y, v1.y - v3.x);
                s[i0 + 3*L] = make_float2(v1.x - v3.y, v1.y + v3.x);
            } else {
                s[i0 + L]   = make_float2(v1.x - v3.y, v1.y + v3.x);
                s[i0 + 3*L] = make_float2(v1.x + v3.y, v1.y - v3.x);
            }
        }
        __syncthreads();
    }
}

// forward: pack 2 real rows per complex FFT, Hermitian unpack; emit freq-major
// real parts for the selector.
__global__ __launch_bounds__(FFT_NT) void fft_fwd_kernel()
{
    __shared__ float2 s[4096];
    __shared__ float2 tw[1024];
    const int blk = blockIdx.x;
    const int tensor = blk >> 7;
    const int pr = blk & 127;
    const int b = pr >> 6;
    const int j = pr & 63;
    const int row0 = b * 128 + 2 * j;
    const float* src0 = (tensor ? g_k : g_q) + (size_t)row0 * LSEQ;
    const float* src1 = src0 + LSEQ;
    float2* dst0 = (tensor ? g_Kf : g_Qf) + (size_t)row0 * FLEN;
    float2* dst1 = dst0 + FLEN;
    float* rt = g_ReT + ((size_t)(tensor * BATCH + b) * FLEN) * HDIM;
    const int tid = threadIdx.x;

    fill_tw(tw, tid);
    for (int i = tid; i < 4096; i += FFT_NT) {
        s[dr12(i)] = make_float2(src0[i], src1[i]);
    }
    __syncthreads();
    fft4096_r4(s, tw, tid, false);

    for (int f = tid; f < FLEN; f += FFT_NT) {
        float2 cf = s[f];
        float2 cn = s[(4096 - f) & 4095];
        float re0 = 0.5f * (cf.x + cn.x);
        float re1 = 0.5f * (cf.y + cn.y);
        dst0[f] = make_float2(re0, 0.5f * (cf.y - cn.y));
        dst1[f] = make_float2(re1, 0.5f * (cn.x - cf.x));
        rt[(size_t)f * HDIM + 2 * j    ] = re0;
        rt[(size_t)f * HDIM + 2 * j + 1] = re1;
    }
}

// ---------------- selector MLP: 8 freqs concurrent, 512 threads ----------------
#define SEL_NT 512
#define SEL_FPB 8                  // concurrent freqs (one 64-thread group each)
#define SEL_ITERS 2
#define SEL_CHUNK (SEL_FPB * SEL_ITERS)   // 16 freqs per block
__global__ __launch_bounds__(SEL_NT) void selector_kernel(
    const float* __restrict__ qW1, const float* __restrict__ qb1,
    const float* __restrict__ qW2, const float* __restrict__ qb2,
    const float* __restrict__ kW1, const float* __restrict__ kb1,
    const float* __restrict__ kW2, const float* __restrict__ kb2,
    const float* __restrict__ q_noise, const float* __restrict__ k_noise)
{
    const int chunk = blockIdx.x;
    const int b = blockIdx.y;
    const int tensor = blockIdx.z;
    const float* ReT = g_ReT + ((size_t)(tensor * BATCH + b) * FLEN) * HDIM;
    const float* W1 = tensor ? kW1 : qW1;
    const float* b1 = tensor ? kb1 : qb1;
    const float* W2 = tensor ? kW2 : qW2;
    const float* b2 = tensor ? kb2 : qb2;
    const float* nz = tensor ? k_noise : q_noise;
    float* z = tensor ? g_zk : g_zq;

    __shared__ float W1sT[128 * 65];         // [d][u], pad 65
    __shared__ float xr[SEL_FPB][128];
    __shared__ float h1[SEL_FPB][64];
    __shared__ float lg[SEL_FPB][2];
    const int tid = threadIdx.x;

    for (int idx = tid; idx < 64 * 128; idx += SEL_NT) {
        int u = idx >> 7, d = idx & 127;
        W1sT[d * 65 + u] = W1[idx];
    }
    __syncthreads();

    const int grp = tid >> 6;                 // 0..7  (frequency group)
    const int u   = tid & 63;                 // hidden unit

    #pragma unroll 1
    for (int it = 0; it < SEL_ITERS; it++) {
        const int fbase = chunk * SEL_CHUNK + it * SEL_FPB;
        const int f = fbase + grp;
        const bool valid = (f < FLEN);

        // each group loads its freq's 128 real parts (2 per thread)
        {
            float v0 = 0.f, v1 = 0.f;
            if (valid) {
                v0 = ReT[(size_t)f * HDIM + u];
                v1 = ReT[(size_t)f * HDIM + u + 64];
            }
            xr[grp][u]      = v0;
            xr[grp][u + 64] = v1;
        }
        __syncthreads();

        // hidden layer: thread -> one (f, u)
        {
            float a = b1[u];
            const float* x = xr[grp];
            #pragma unroll 16
            for (int d = 0; d < 128; d++)
                a = fmaf(x[d], W1sT[d * 65 + u], a);
            h1[grp][u] = fmaxf(a, 0.f);
        }
        __syncthreads();

        // output layer + gumbel: 16 threads (8 freqs x 2 classes)
        if (tid < SEL_FPB * 2) {
            int f2 = tid >> 1, c = tid & 1;
            int fo = fbase + f2;
            if (fo < FLEN) {
                float acc2 = b2[c];
                const float* w2 = W2 + c * 64;
                #pragma unroll 8
                for (int j2 = 0; j2 < 64; j2++) acc2 += h1[f2][j2] * w2[j2];
                float n = nz[((size_t)b * FLEN + fo) * 2 + c];
                float gg = -logf(-logf(n + GEPS) + GEPS);
                lg[f2][c] = acc2 + gg;
            }
        }
        __syncthreads();
        if (tid < SEL_FPB) {
            int fo = fbase + tid;
            if (fo < FLEN)
                z[b * FLEN + fo] = 1.f / (1.f + expf(lg[tid][0] - lg[tid][1]));
        }
        __syncthreads();
    }
}

// inverse: pack 2 filtered rows per complex iFFT; store bf16.
__global__ __launch_bounds__(FFT_NT) void fft_inv_kernel()
{
    __shared__ float2 s[4096];
    __shared__ float2 tw[1024];
    const int blk = blockIdx.x;
    const int tensor = blk >> 7;
    const int pr = blk & 127;
    const int b = pr >> 6;
    const int j = pr & 63;
    const int row0 = b * 128 + 2 * j;
    const float2* src0 = (tensor ? g_Kf : g_Qf) + (size_t)row0 * FLEN;
    const float2* src1 = src0 + FLEN;
    const float* z = (tensor ? g_zk : g_zq) + (size_t)b * FLEN;
    __nv_bfloat16* dst0 = (tensor ? g_kf_bf : g_qf_bf) + (size_t)row0 * LSEQ;
    __nv_bfloat16* dst1 = dst0 + LSEQ;
    const int tid = threadIdx.x;

    fill_tw(tw, tid);
    for (int i = tid; i < 4096; i += FFT_NT) {
        int f = (i <= 2048) ? i : (4096 - i);
        float zz = z[f];
        float2 a = src0[f];
        float2 bb = src1[f];
        if (i > 2048) { a.y = -a.y; bb.y = -bb.y; }
        a.x *= zz; a.y *= zz; bb.x *= zz; bb.y *= zz;
        s[dr12(i)] = make_float2(a.x - bb.y, a.y + bb.x);
    }
    __syncthreads();
    fft4096_r4(s, tw, tid, true);
    const float inv = 1.f / 4096.f;
    for (int i = tid; i < 4096; i += FFT_NT) {
        float2 v = s[i];
        dst0[i] = __float2bfloat16(v.x * inv);
        dst1[i] = __float2bfloat16(v.y * inv);
    }
}

// ---------------- zero row sums ----------------
__global__ void zero_sums()
{
    g_rowsum[blockIdx.x * 512 + threadIdx.x] = 0.f;
}

// ---------------- scores GEMM + fused mask/exp/rowsum epilogue ----------------
__global__ __launch_bounds__(256) void gemm_scores_bf16(float* __restrict__ out,
                                                        const int* __restrict__ mask)
{
    __shared__ __align__(16) __nv_bfloat16 Qs[2][32][136];
    __shared__ __align__(16) __nv_bfloat16 Ks[2][32][136];

    const int b  = blockIdx.z;
    const int l0 = blockIdx.y * 128;
    const int m0 = blockIdx.x * 128;
    const __nv_bfloat16* A  = g_qf_bf + (size_t)b * HDIM * LSEQ;
    const __nv_bfloat16* Bm = g_kf_bf + (size_t)b * HDIM * LSEQ;
    const int* mrow = mask + (size_t)b * LSEQ;

    const int tid  = threadIdx.x;
    const int warp = tid >> 5, lane = tid & 31;
    const int g = lane >> 2, tg = lane & 3;
    const int wl = (warp & 1) * 64;
    const int wn = (warp >> 1) * 32;

    const int lr   = lane & 7;
    const int koff = lr + ((lane & 16) ? 8 : 0);
    const int coff = (lane & 8) ? 8 : 0;
    const int kb   = lr + ((lane & 8) ? 8 : 0);
    const int cb   = (lane & 16) ? 8 : 0;

    float acc[4][4][4];
    #pragma unroll
    for (int i = 0; i < 4; i++)
        #pragma unroll
        for (int j = 0; j < 4; j++)
            #pragma unroll
            for (int c = 0; c < 4; c++) acc[i][j][c] = 0.f;

    auto load_chunk = [&](int kc, int bufi) {
        #pragma unroll
        for (int it = 0; it < 2; it++) {
            int idx = tid + 256 * it;
            int k  = idx >> 4;
            int c8 = (idx & 15) << 3;
            cp16(&Qs[bufi][k][c8], A  + (size_t)(kc * 32 + k) * LSEQ + l0 + c8);
            cp16(&Ks[bufi][k][c8], Bm + (size_t)(kc * 32 + k) * LSEQ + m0 + c8);
        }
        asm volatile("cp.async.commit_group;");
    };

    load_chunk(0, 0);

    #pragma unroll 1
    for (int kc = 0; kc < 4; kc++) {
        const int buf = kc & 1;
        if (kc < 3) load_chunk(kc + 1, buf ^ 1);
        if (kc < 3) asm volatile("cp.async.wait_group 1;");
        else        asm volatile("cp.async.wait_group 0;");
        __syncthreads();

        #pragma unroll
        for (int ks = 0; ks < 2; ks++) {
            const int k0 = ks * 16;
            uint32_t a[4][4];
            #pragma unroll
            for (int i = 0; i < 4; i++) {
                uint32_t addr = sptr(&Qs[buf][k0 + koff][wl + 16 * i + coff]);
                asm volatile(
                    "ldmatrix.sync.aligned.m8n8.x4.trans.shared.b16 {%0,%1,%2,%3}, [%4];"
                    : "=r"(a[i][0]), "=r"(a[i][1]), "=r"(a[i][2]), "=r"(a[i][3])
                    : "r"(addr));
            }
            uint32_t bfr[2][4];
            #pragma unroll
            for (int jj = 0; jj < 2; jj++) {
                uint32_t addr = sptr(&Ks[buf][k0 + kb][wn + 16 * jj + cb]);
                asm volatile(
                    "ldmatrix.sync.aligned.m8n8.x4.trans.shared.b16 {%0,%1,%2,%3}, [%4];"
                    : "=r"(bfr[jj][0]), "=r"(bfr[jj][1]), "=r"(bfr[jj][2]), "=r"(bfr[jj][3])
                    : "r"(addr));
            }
            #pragma unroll
            for (int i = 0; i < 4; i++)
                #pragma unroll
                for (int j = 0; j < 4; j++) {
                    uint32_t b0 = bfr[j >> 1][2 * (j & 1)];
                    uint32_t b1 = bfr[j >> 1][2 * (j & 1) + 1];
                    asm volatile(
                        "mma.sync.aligned.m16n8k16.row.col.f32.bf16.bf16.f32 "
                        "{%0,%1,%2,%3},{%4,%5,%6,%7},{%8,%9},{%0,%1,%2,%3};"
                        : "+f"(acc[i][j][0]), "+f"(acc[i][j][1]),
                          "+f"(acc[i][j][2]), "+f"(acc[i][j][3])
                        : "r"(a[i][0]), "r"(a[i][1]), "r"(a[i][2]), "r"(a[i][3]),
                          "r"(b0), "r"(b1));
                }
        }
        __syncthreads();
    }

    #pragma unroll
    for (int i = 0; i < 4; i++) {
        int row0 = l0 + wl + i * 16 + g;
        float rs0 = 0.f, rs1 = 0.f;
        #pragma unroll
        for (int j = 0; j < 4; j++) {
            int col = m0 + wn + j * 8 + 2 * tg;
            int mv0 = mrow[col], mv1 = mrow[col + 1];
            float p00 = mv0 ? __expf(acc[i][j][0] * INV_SQRT_DK) : 0.f;
            float p01 = mv1 ? __expf(acc[i][j][1] * INV_SQRT_DK) : 0.f;
            float p10 = mv0 ? __expf(acc[i][j][2] * INV_SQRT_DK) : 0.f;
            float p11 = mv1 ? __expf(acc[i][j][3] * INV_SQRT_DK) : 0.f;
            *(float2*)(out + ((size_t)b * LSEQ + row0    ) * LSEQ + col) = make_float2(p00, p01);
            *(float2*)(out + ((size_t)b * LSEQ + row0 + 8) * LSEQ + col) = make_float2(p10, p11);
            rs0 += p00 + p01;
            rs1 += p10 + p11;
        }
        rs0 += __shfl_xor_sync(0xffffffffu, rs0, 1);
        rs0 += __shfl_xor_sync(0xffffffffu, rs0, 2);
        rs1 += __shfl_xor_sync(0xffffffffu, rs1, 1);
        rs1 += __shfl_xor_sync(0xffffffffu, rs1, 2);
        if (tg == 0) {
            atomicAdd(&g_rowsum[b * LSEQ + row0    ], rs0);
            atomicAdd(&g_rowsum[b * LSEQ + row0 + 8], rs1);
        }
    }
}

// ---------------- final normalize ----------------
__global__ __launch_bounds__(512) void scale_kernel(float* __restrict__ out)
{
    size_t i4 = (size_t)blockIdx.x * 512 + threadIdx.x;
    int row = (int)(i4 >> 10);
    float inv = 1.f / g_rowsum[row];
    float4 v = ((const float4*)out)[i4];
    v.x *= inv; v.y *= inv; v.z *= inv; v.w *= inv;
    ((float4*)out)[i4] = v;
}

// ---------------- launch ----------------
extern "C" void kernel_launch(void* const* d_in, const int* in_sizes, int n_in,
                              void* d_out, int out_size)
{
    const float* query   = (const float*)d_in[0];
    const float* key     = (const float*)d_in[1];
    const int*   mask    = (const int*)  d_in[2];
    const float* Wq      = (const float*)d_in[3];
    const float* bq      = (const float*)d_in[4];
    const float* Wk      = (const float*)d_in[5];
    const float* bk      = (const float*)d_in[6];
    const float* qW1     = (const float*)d_in[7];
    const float* qb1     = (const float*)d_in[8];
    const float* qW2     = (const float*)d_in[9];
    const float* qb2     = (const float*)d_in[10];
    const float* kW1     = (const float*)d_in[11];
    const float* kb1     = (const float*)d_in[12];
    const float* kW2     = (const float*)d_in[13];
    const float* kb2     = (const float*)d_in[14];
    const float* q_noise = (const float*)d_in[15];
    const float* k_noise = (const float*)d_in[16];
    float* out = (float*)d_out;

    cudaFuncSetAttribute(proj_tc, cudaFuncAttributeMaxDynamicSharedMemorySize,
                         PROJ_SMEM_BYTES);

    zero_sums<<<BATCH * LSEQ / 512, 512>>>();
    proj_tc<<<dim3(64, 2), 256, PROJ_SMEM_BYTES>>>(query, key, Wq, bq, Wk, bk);
    fft_fwd_kernel<<<256, FFT_NT>>>();
    selector_kernel<<<dim3((FLEN + SEL_CHUNK - 1) / SEL_CHUNK, BATCH, 2), SEL_NT>>>(
        qW1, qb1, qW2, qb2, kW1, kb1, kW2, kb2, q_noise, k_noise);
    fft_inv_kernel<<<256, FFT_NT>>>();
    gemm_scores_bf16<<<dim3(32, 32, BATCH), 256>>>(out, mask);
    scale_kernel<<<(int)((size_t)BATCH * LSEQ * LSEQ / 4 / 512), 512>>>(out);
}

// round 9
// speedup vs baseline: 5.7551x; 1.0818x over previous
#include <cuda_runtime.h>
#include <cuda_bf16.h>
#include <cstdint>

#define BATCH 2
#define LSEQ 4096
#define DMODEL 768
#define HDIM 128
#define FLEN 2049
#define INV_SQRT_DK 0.08838834764831845f
#define GEPS 1e-9f
#define PI_F 3.14159265358979323846f

// ---------------- scratch ----------------
__device__ float  g_q [BATCH*HDIM*LSEQ];   // projected q, layout [b][d][l]
__device__ float  g_k [BATCH*HDIM*LSEQ];
__device__ float2 g_Qf[BATCH*HDIM*FLEN];   // rfft of q rows
__device__ float2 g_Kf[BATCH*HDIM*FLEN];
__device__ float  g_ReT[2*BATCH*FLEN*HDIM]; // real parts, freq-major
__device__ float  g_zq[BATCH*FLEN];        // selector gains
__device__ float  g_zk[BATCH*FLEN];
__device__ __nv_bfloat16 g_qf_bf[BATCH*HDIM*LSEQ];  // filtered q (bf16)
__device__ __nv_bfloat16 g_kf_bf[BATCH*HDIM*LSEQ];
__device__ float  g_rowsum[BATCH*LSEQ];

__device__ __forceinline__ uint32_t sptr(const void* p) {
    return (uint32_t)__cvta_generic_to_shared(p);
}
__device__ __forceinline__ void cp16(void* smem_dst, const void* gmem_src) {
    asm volatile("cp.async.ca.shared.global [%0], [%1], 16;"
                 :: "r"(sptr(smem_dst)), "l"(gmem_src));
}

// ---------------- projection GEMM: tf32 mma + 3-stage cp.async ----------------
#define PROJ_STAGES 3
#define PROJ_BK 32
#define PROJ_KP 36
#define PROJ_MAT (128 * PROJ_KP)
#define PROJ_SMEM_FLOATS (PROJ_STAGES * PROJ_MAT * 2)
#define PROJ_SMEM_BYTES (PROJ_SMEM_FLOATS * 4)

__global__ __launch_bounds__(256) void proj_tc(
    const float* __restrict__ query, const float* __restrict__ key,
    const float* __restrict__ Wq, const float* __restrict__ bq,
    const float* __restrict__ Wk, const float* __restrict__ bk)
{
    extern __shared__ float dsm[];
    float* Wbase = dsm;
    float* Xbase = dsm + PROJ_STAGES * PROJ_MAT;

    const int tensor = blockIdx.y;
    const float* X  = tensor ? key : query;
    const float* W  = tensor ? Wk  : Wq;
    const float* bi = tensor ? bk  : bq;
    float* dst = tensor ? g_k : g_q;

    const int l0 = blockIdx.x * 128;
    const int tid  = threadIdx.x;
    const int warp = tid >> 5, lane = tid & 31;
    const int g = lane >> 2, tg = lane & 3;
    const int wd = (warp & 1) * 64;
    const int wn = (warp >> 1) * 32;

    float acc[4][4][4];
    #pragma unroll
    for (int i = 0; i < 4; i++)
        #pragma unroll
        for (int j = 0; j < 4; j++)
            #pragma unroll
            for (int c = 0; c < 4; c++) acc[i][j][c] = 0.f;

    auto load_stage = [&](int kc, int st) {
        const int k0 = kc * PROJ_BK;
        float* Ws = Wbase + st * PROJ_MAT;
        float* Xs = Xbase + st * PROJ_MAT;
        #pragma unroll
        for (int it = 0; it < 4; it++) {
            int idx = tid + 256 * it;
            int row = idx >> 3;
            int seg = (idx & 7) << 2;
            cp16(Ws + row * PROJ_KP + seg, W + (size_t)row * DMODEL + k0 + seg);
            cp16(Xs + row * PROJ_KP + seg, X + (size_t)(l0 + row) * DMODEL + k0 + seg);
        }
        asm volatile("cp.async.commit_group;");
    };

    load_stage(0, 0);
    load_stage(1, 1);

    const int NCHUNK = DMODEL / PROJ_BK;
    #pragma unroll 1
    for (int kc = 0; kc < NCHUNK; kc++) {
        const int st = kc % PROJ_STAGES;
        asm volatile("cp.async.wait_group 1;");
        __syncthreads();
        if (kc + 2 < NCHUNK) load_stage(kc + 2, (kc + 2) % PROJ_STAGES);

        const float* Ws = Wbase + st * PROJ_MAT;
        const float* Xs = Xbase + st * PROJ_MAT;

        #pragma unroll
        for (int ks = 0; ks < 4; ks++) {
            const int k = ks * 8;
            uint32_t a[4][4], bf[4][2];
            #pragma unroll
            for (int i = 0; i < 4; i++) {
                int d = wd + i * 16 + g;
                a[i][0] = __float_as_uint(Ws[(d    ) * PROJ_KP + k + tg    ]);
                a[i][1] = __float_as_uint(Ws[(d + 8) * PROJ_KP + k + tg    ]);
                a[i][2] = __float_as_uint(Ws[(d    ) * PROJ_KP + k + tg + 4]);
                a[i][3] = __float_as_uint(Ws[(d + 8) * PROJ_KP + k + tg + 4]);
            }
            #pragma unroll
            for (int j = 0; j < 4; j++) {
                int n = wn + j * 8 + g;
                bf[j][0] = __float_as_uint(Xs[n * PROJ_KP + k + tg    ]);
                bf[j][1] = __float_as_uint(Xs[n * PROJ_KP + k + tg + 4]);
            }
            #pragma unroll
            for (int i = 0; i < 4; i++)
                #pragma unroll
                for (int j = 0; j < 4; j++) {
                    asm volatile(
                        "mma.sync.aligned.m16n8k8.row.col.f32.tf32.tf32.f32 "
                        "{%0,%1,%2,%3},{%4,%5,%6,%7},{%8,%9},{%0,%1,%2,%3};"
                        : "+f"(acc[i][j][0]), "+f"(acc[i][j][1]),
                          "+f"(acc[i][j][2]), "+f"(acc[i][j][3])
                        : "r"(a[i][0]), "r"(a[i][1]), "r"(a[i][2]), "r"(a[i][3]),
                          "r"(bf[j][0]), "r"(bf[j][1]));
                }
        }
        __syncthreads();
    }

    #pragma unroll
    for (int i = 0; i < 4; i++) {
        int d0 = wd + i * 16 + g;
        float bv0 = bi[d0], bv1 = bi[d0 + 8];
        #pragma unroll
        for (int j = 0; j < 4; j++) {
            int gl = l0 + wn + j * 8 + 2 * tg;
            int b  = gl >> 12;
            int l  = gl & 4095;
            float* o0 = dst + (size_t)((b << 7) + d0    ) * LSEQ + l;
            float* o1 = dst + (size_t)((b << 7) + d0 + 8) * LSEQ + l;
            *(float2*)o0 = make_float2(acc[i][j][0] + bv0, acc[i][j][1] + bv0);
            *(float2*)o1 = make_float2(acc[i][j][2] + bv1, acc[i][j][3] + bv1);
        }
    }
}

// ---------------- radix-4 4096-pt FFT ----------------
#define FFT_NT 512
__device__ __forceinline__ void fill_tw(float2* tw, int tid)
{
    for (int j = tid; j < 1024; j += FFT_NT) {
        float ang = -PI_F * (float)j / 2048.0f;
        float s, c;
        __sincosf(ang, &s, &c);
        tw[j] = make_float2(c, s);
    }
}

__device__ __forceinline__ float2 cmul(float2 a, float2 b) {
    return make_float2(a.x*b.x - a.y*b.y, a.x*b.y + a.y*b.x);
}

__device__ __forceinline__ int dr12(int i) {
    unsigned y = __brev((unsigned)i) >> 20;
    return (int)(((y & 0x555u) << 1) | ((y >> 1) & 0x555u));
}

__device__ __forceinline__ void fft4096_r4(float2* s, const float2* tw, int tid, bool inv)
{
    #pragma unroll 1
    for (int st = 0; st < 6; st++) {
        const int twoSt = 2 * st;
        const int L = 1 << twoSt;
        const int shift = 10 - twoSt;
        #pragma unroll
        for (int tt = 0; tt < 1024 / FFT_NT; tt++) {
            int t = tid + tt * FFT_NT;
            int j  = t & (L - 1);
            int i0 = ((t >> twoSt) << (twoSt + 2)) + j;
            int e  = j << shift;
            float2 w1 = tw[e];
            if (inv) w1.y = -w1.y;
            float2 w2 = cmul(w1, w1);
            float2 w3 = cmul(w1, w2);

            float2 u0 = s[i0];
            float2 u1 = cmul(s[i0 + L],   w1);
            float2 u2 = cmul(s[i0 + 2*L], w2);
            float2 u3 = cmul(s[i0 + 3*L], w3);

            float2 v0 = make_float2(u0.x + u2.x, u0.y + u2.y);
            float2 v1 = make_float2(u0.x - u2.x, u0.y - u2.y);
            float2 v2 = make_float2(u1.x + u3.x, u1.y + u3.y);
            float2 v3 = make_float2(u1.x - u3.x, u1.y - u3.y);

            s[i0]       = make_float2(v0.x + v2.x, v0.y + v2.y);
            s[i0 + 2*L] = make_float2(v0.x - v2.x, v0.y - v2.y);
            if (!inv) {
                s[i0 + L]   = make_float2(v1.x + v3.y, v1.y - v3.x);
                s[i0 + 3*L] = make_float2(v1.x - v3.y, v1.y + v3.x);
            } else {
                s[i0 + L]   = make_float2(v1.x - v3.y, v1.y + v3.x);
                s[i0 + 3*L] = make_float2(v1.x + v3.y, v1.y - v3.x);
            }
        }
        __syncthreads();
    }
}

// forward: pack 2 real rows per complex FFT, Hermitian unpack; emit freq-major
// real parts for the selector.
__global__ __launch_bounds__(FFT_NT) void fft_fwd_kernel()
{
    __shared__ float2 s[4096];
    __shared__ float2 tw[1024];
    const int blk = blockIdx.x;
    const int tensor = blk >> 7;
    const int pr = blk & 127;
    const int b = pr >> 6;
    const int j = pr & 63;
    const int row0 = b * 128 + 2 * j;
    const float* src0 = (tensor ? g_k : g_q) + (size_t)row0 * LSEQ;
    const float* src1 = src0 + LSEQ;
    float2* dst0 = (tensor ? g_Kf : g_Qf) + (size_t)row0 * FLEN;
    float2* dst1 = dst0 + FLEN;
    float* rt = g_ReT + ((size_t)(tensor * BATCH + b) * FLEN) * HDIM;
    const int tid = threadIdx.x;

    fill_tw(tw, tid);
    for (int i = tid; i < 4096; i += FFT_NT) {
        s[dr12(i)] = make_float2(src0[i], src1[i]);
    }
    __syncthreads();
    fft4096_r4(s, tw, tid, false);

    for (int f = tid; f < FLEN; f += FFT_NT) {
        float2 cf = s[f];
        float2 cn = s[(4096 - f) & 4095];
        float re0 = 0.5f * (cf.x + cn.x);
        float re1 = 0.5f * (cf.y + cn.y);
        dst0[f] = make_float2(re0, 0.5f * (cf.y - cn.y));
        dst1[f] = make_float2(re1, 0.5f * (cn.x - cf.x));
        rt[(size_t)f * HDIM + 2 * j    ] = re0;
        rt[(size_t)f * HDIM + 2 * j + 1] = re1;
    }
}

// ---------------- selector: tf32 tensor-core MLP ----------------
// h1[64, f] = relu(W1[64,128] @ ReT[f,128]^T + b1); logits = W2 @ h1 + b2;
// z = softmax(logits + gumbel)[1]. One block per 128-freq tile.
#define SELG_KP 132
#define SELG_AS (64 * SELG_KP)
#define SELG_BS (128 * SELG_KP)
#define SELG_SMEM_BYTES ((SELG_AS + SELG_BS) * 4)

__global__ __launch_bounds__(256) void selector_tc(
    const float* __restrict__ qW1, const float* __restrict__ qb1,
    const float* __restrict__ qW2, const float* __restrict__ qb2,
    const float* __restrict__ kW1, const float* __restrict__ kb1,
    const float* __restrict__ kW2, const float* __restrict__ kb2,
    const float* __restrict__ q_noise, const float* __restrict__ k_noise)
{
    extern __shared__ float ssm[];
    float* As  = ssm;                 // [64][132]  W1
    float* Bs  = ssm + SELG_AS;       // [128][132] xr tile
    float* h1s = ssm;                 // reuse As region: [128][65]
    __shared__ float lgs[128][2];

    const int tile = blockIdx.x;
    const int b = blockIdx.y;
    const int tensor = blockIdx.z;
    const int f0 = tile * 128;
    const float* ReT = g_ReT + ((size_t)(tensor * BATCH + b) * FLEN) * HDIM;
    const float* W1 = tensor ? kW1 : qW1;
    const float* b1 = tensor ? kb1 : qb1;
    const float* W2 = tensor ? kW2 : qW2;
    const float* b2 = tensor ? kb2 : qb2;
    const float* nz = tensor ? k_noise : q_noise;
    float* z = tensor ? g_zk : g_zq;

    const int tid  = threadIdx.x;
    const int warp = tid >> 5, lane = tid & 31;
    const int g = lane >> 2, tg = lane & 3;
    const int wu = (warp & 1) * 32;    // u offset (m)
    const int wf = (warp >> 1) * 32;   // f offset (n)

    // stage W1 [64][128] and xr tile [128][128] (zero-pad past FLEN)
    for (int idx = tid; idx < 64 * 32; idx += 256) {
        int row = idx >> 5, seg = (idx & 31) << 2;
        *(float4*)(As + row * SELG_KP + seg) = *(const float4*)(W1 + row * 128 + seg);
    }
    for (int idx = tid; idx < 128 * 32; idx += 256) {
        int row = idx >> 5, seg = (idx & 31) << 2;
        int f = f0 + row;
        float4 v = make_float4(0.f, 0.f, 0.f, 0.f);
        if (f < FLEN) v = *(const float4*)(ReT + (size_t)f * HDIM + seg);
        *(float4*)(Bs + row * SELG_KP + seg) = v;
    }
    __syncthreads();

    float acc[2][4][4];
    #pragma unroll
    for (int i = 0; i < 2; i++)
        #pragma unroll
        for (int j = 0; j < 4; j++)
            #pragma unroll
            for (int c = 0; c < 4; c++) acc[i][j][c] = 0.f;

    #pragma unroll
    for (int ks = 0; ks < 16; ks++) {
        const int k = ks * 8;
        uint32_t a[2][4], bf[4][2];
        #pragma unroll
        for (int i = 0; i < 2; i++) {
            int u = wu + i * 16 + g;
            a[i][0] = __float_as_uint(As[(u    ) * SELG_KP + k + tg    ]);
            a[i][1] = __float_as_uint(As[(u + 8) * SELG_KP + k + tg    ]);
            a[i][2] = __float_as_uint(As[(u    ) * SELG_KP + k + tg + 4]);
            a[i][3] = __float_as_uint(As[(u + 8) * SELG_KP + k + tg + 4]);
        }
        #pragma unroll
        for (int j = 0; j < 4; j++) {
            int n = wf + j * 8 + g;
            bf[j][0] = __float_as_uint(Bs[n * SELG_KP + k + tg    ]);
            bf[j][1] = __float_as_uint(Bs[n * SELG_KP + k + tg + 4]);
        }
        #pragma unroll
        for (int i = 0; i < 2; i++)
            #pragma unroll
            for (int j = 0; j < 4; j++) {
                asm volatile(
                    "mma.sync.aligned.m16n8k8.row.col.f32.tf32.tf32.f32 "
                    "{%0,%1,%2,%3},{%4,%5,%6,%7},{%8,%9},{%0,%1,%2,%3};"
                    : "+f"(acc[i][j][0]), "+f"(acc[i][j][1]),
                      "+f"(acc[i][j][2]), "+f"(acc[i][j][3])
                    : "r"(a[i][0]), "r"(a[i][1]), "r"(a[i][2]), "r"(a[i][3]),
                      "r"(bf[j][0]), "r"(bf[j][1]));
            }
    }
    __syncthreads();   // all reads of As done before reuse as h1s

    // bias + relu -> h1s[f][u] (pad 65)
    #pragma unroll
    for (int i = 0; i < 2; i++) {
        int u0 = wu + i * 16 + g;
        float bv0 = b1[u0], bv1 = b1[u0 + 8];
        #pragma unroll
        for (int j = 0; j < 4; j++) {
            int f = wf + j * 8 + 2 * tg;
            h1s[(f    ) * 65 + u0    ] = fmaxf(acc[i][j][0] + bv0, 0.f);
            h1s[(f + 1) * 65 + u0    ] = fmaxf(acc[i][j][1] + bv0, 0.f);
            h1s[(f    ) * 65 + u0 + 8] = fmaxf(acc[i][j][2] + bv1, 0.f);
            h1s[(f + 1) * 65 + u0 + 8] = fmaxf(acc[i][j][3] + bv1, 0.f);
        }
    }
    __syncthreads();

    // output layer + gumbel
    {
        int fl = tid >> 1, c = tid & 1;
        int f = f0 + fl;
        if (f < FLEN) {
            float acc2 = b2[c];
            const float* w2 = W2 + c * 64;
            const float* h = h1s + fl * 65;
            #pragma unroll 16
            for (int u = 0; u < 64; u++) acc2 = fmaf(h[u], w2[u], acc2);
            float n = nz[((size_t)b * FLEN + f) * 2 + c];
            lgs[fl][c] = acc2 + (-logf(-logf(n + GEPS) + GEPS));
        }
    }
    __syncthreads();
    if (tid < 128) {
        int f = f0 + tid;
        if (f < FLEN) z[b * FLEN + f] = 1.f / (1.f + expf(lgs[tid][0] - lgs[tid][1]));
    }
}

// inverse: pack 2 filtered rows per complex iFFT; store bf16.
__global__ __launch_bounds__(FFT_NT) void fft_inv_kernel()
{
    __shared__ float2 s[4096];
    __shared__ float2 tw[1024];
    const int blk = blockIdx.x;
    const int tensor = blk >> 7;
    const int pr = blk & 127;
    const int b = pr >> 6;
    const int j = pr & 63;
    const int row0 = b * 128 + 2 * j;
    const float2* src0 = (tensor ? g_Kf : g_Qf) + (size_t)row0 * FLEN;
    const float2* src1 = src0 + FLEN;
    const float* z = (tensor ? g_zk : g_zq) + (size_t)b * FLEN;
    __nv_bfloat16* dst0 = (tensor ? g_kf_bf : g_qf_bf) + (size_t)row0 * LSEQ;
    __nv_bfloat16* dst1 = dst0 + LSEQ;
    const int tid = threadIdx.x;

    fill_tw(tw, tid);
    for (int i = tid; i < 4096; i += FFT_NT) {
        int f = (i <= 2048) ? i : (4096 - i);
        float zz = z[f];
        float2 a = src0[f];
        float2 bb = src1[f];
        if (i > 2048) { a.y = -a.y; bb.y = -bb.y; }
        a.x *= zz; a.y *= zz; bb.x *= zz; bb.y *= zz;
        s[dr12(i)] = make_float2(a.x - bb.y, a.y + bb.x);
    }
    __syncthreads();
    fft4096_r4(s, tw, tid, true);
    const float inv = 1.f / 4096.f;
    for (int i = tid; i < 4096; i += FFT_NT) {
        float2 v = s[i];
        dst0[i] = __float2bfloat16(v.x * inv);
        dst1[i] = __float2bfloat16(v.y * inv);
    }
}

// ---------------- zero row sums ----------------
__global__ void zero_sums()
{
    g_rowsum[blockIdx.x * 512 + threadIdx.x] = 0.f;
}

// ---------------- scores GEMM + fused mask/exp/rowsum epilogue ----------------
__global__ __launch_bounds__(256) void gemm_scores_bf16(float* __restrict__ out,
                                                        const int* __restrict__ mask)
{
    __shared__ __align__(16) __nv_bfloat16 Qs[2][32][136];
    __shared__ __align__(16) __nv_bfloat16 Ks[2][32][136];

    const int b  = blockIdx.z;
    const int l0 = blockIdx.y * 128;
    const int m0 = blockIdx.x * 128;
    const __nv_bfloat16* A  = g_qf_bf + (size_t)b * HDIM * LSEQ;
    const __nv_bfloat16* Bm = g_kf_bf + (size_t)b * HDIM * LSEQ;
    const int* mrow = mask + (size_t)b * LSEQ;

    const int tid  = threadIdx.x;
    const int warp = tid >> 5, lane = tid & 31;
    const int g = lane >> 2, tg = lane & 3;
    const int wl = (warp & 1) * 64;
    const int wn = (warp >> 1) * 32;

    const int lr   = lane & 7;
    const int koff = lr + ((lane & 16) ? 8 : 0);
    const int coff = (lane & 8) ? 8 : 0;
    const int kb   = lr + ((lane & 8) ? 8 : 0);
    const int cb   = (lane & 16) ? 8 : 0;

    float acc[4][4][4];
    #pragma unroll
    for (int i = 0; i < 4; i++)
        #pragma unroll
        for (int j = 0; j < 4; j++)
            #pragma unroll
            for (int c = 0; c < 4; c++) acc[i][j][c] = 0.f;

    auto load_chunk = [&](int kc, int bufi) {
        #pragma unroll
        for (int it = 0; it < 2; it++) {
            int idx = tid + 256 * it;
            int k  = idx >> 4;
            int c8 = (idx & 15) << 3;
            cp16(&Qs[bufi][k][c8], A  + (size_t)(kc * 32 + k) * LSEQ + l0 + c8);
            cp16(&Ks[bufi][k][c8], Bm + (size_t)(kc * 32 + k) * LSEQ + m0 + c8);
        }
        asm volatile("cp.async.commit_group;");
    };

    load_chunk(0, 0);

    #pragma unroll 1
    for (int kc = 0; kc < 4; kc++) {
        const int buf = kc & 1;
        if (kc < 3) load_chunk(kc + 1, buf ^ 1);
        if (kc < 3) asm volatile("cp.async.wait_group 1;");
        else        asm volatile("cp.async.wait_group 0;");
        __syncthreads();

        #pragma unroll
        for (int ks = 0; ks < 2; ks++) {
            const int k0 = ks * 16;
            uint32_t a[4][4];
            #pragma unroll
            for (int i = 0; i < 4; i++) {
                uint32_t addr = sptr(&Qs[buf][k0 + koff][wl + 16 * i + coff]);
                asm volatile(
                    "ldmatrix.sync.aligned.m8n8.x4.trans.shared.b16 {%0,%1,%2,%3}, [%4];"
                    : "=r"(a[i][0]), "=r"(a[i][1]), "=r"(a[i][2]), "=r"(a[i][3])
                    : "r"(addr));
            }
            uint32_t bfr[2][4];
            #pragma unroll
            for (int jj = 0; jj < 2; jj++) {
                uint32_t addr = sptr(&Ks[buf][k0 + kb][wn + 16 * jj + cb]);
                asm volatile(
                    "ldmatrix.sync.aligned.m8n8.x4.trans.shared.b16 {%0,%1,%2,%3}, [%4];"
                    : "=r"(bfr[jj][0]), "=r"(bfr[jj][1]), "=r"(bfr[jj][2]), "=r"(bfr[jj][3])
                    : "r"(addr));
            }
            #pragma unroll
            for (int i = 0; i < 4; i++)
                #pragma unroll
                for (int j = 0; j < 4; j++) {
                    uint32_t b0 = bfr[j >> 1][2 * (j & 1)];
                    uint32_t b1 = bfr[j >> 1][2 * (j & 1) + 1];
                    asm volatile(
                        "mma.sync.aligned.m16n8k16.row.col.f32.bf16.bf16.f32 "
                        "{%0,%1,%2,%3},{%4,%5,%6,%7},{%8,%9},{%0,%1,%2,%3};"
                        : "+f"(acc[i][j][0]), "+f"(acc[i][j][1]),
                          "+f"(acc[i][j][2]), "+f"(acc[i][j][3])
                        : "r"(a[i][0]), "r"(a[i][1]), "r"(a[i][2]), "r"(a[i][3]),
                          "r"(b0), "r"(b1));
                }
        }
        __syncthreads();
    }

    #pragma unroll
    for (int i = 0; i < 4; i++) {
        int row0 = l0 + wl + i * 16 + g;
        float rs0 = 0.f, rs1 = 0.f;
        #pragma unroll
        for (int j = 0; j < 4; j++) {
            int col = m0 + wn + j * 8 + 2 * tg;
            int mv0 = mrow[col], mv1 = mrow[col + 1];
            float p00 = mv0 ? __expf(acc[i][j][0] * INV_SQRT_DK) : 0.f;
            float p01 = mv1 ? __expf(acc[i][j][1] * INV_SQRT_DK) : 0.f;
            float p10 = mv0 ? __expf(acc[i][j][2] * INV_SQRT_DK) : 0.f;
            float p11 = mv1 ? __expf(acc[i][j][3] * INV_SQRT_DK) : 0.f;
            *(float2*)(out + ((size_t)b * LSEQ + row0    ) * LSEQ + col) = make_float2(p00, p01);
            *(float2*)(out + ((size_t)b * LSEQ + row0 + 8) * LSEQ + col) = make_float2(p10, p11);
            rs0 += p00 + p01;
            rs1 += p10 + p11;
        }
        rs0 += __shfl_xor_sync(0xffffffffu, rs0, 1);
        rs0 += __shfl_xor_sync(0xffffffffu, rs0, 2);
        rs1 += __shfl_xor_sync(0xffffffffu, rs1, 1);
        rs1 += __shfl_xor_sync(0xffffffffu, rs1, 2);
        if (tg == 0) {
            atomicAdd(&g_rowsum[b * LSEQ + row0    ], rs0);
            atomicAdd(&g_rowsum[b * LSEQ + row0 + 8], rs1);
        }
    }
}

// ---------------- final normalize ----------------
__global__ __launch_bounds__(512) void scale_kernel(float* __restrict__ out)
{
    size_t i4 = (size_t)blockIdx.x * 512 + threadIdx.x;
    int row = (int)(i4 >> 10);
    float inv = 1.f / g_rowsum[row];
    float4 v = ((const float4*)out)[i4];
    v.x *= inv; v.y *= inv; v.z *= inv; v.w *= inv;
    ((float4*)out)[i4] = v;
}

// ---------------- launch ----------------
extern "C" void kernel_launch(void* const* d_in, const int* in_sizes, int n_in,
                              void* d_out, int out_size)
{
    const float* query   = (const float*)d_in[0];
    const float* key     = (const float*)d_in[1];
    const int*   mask    = (const int*)  d_in[2];
    const float* Wq      = (const float*)d_in[3];
    const float* bq      = (const float*)d_in[4];
    const float* Wk      = (const float*)d_in[5];
    const float* bk      = (const float*)d_in[6];
    const float* qW1     = (const float*)d_in[7];
    const float* qb1     = (const float*)d_in[8];
    const float* qW2     = (const float*)d_in[9];
    const float* qb2     = (const float*)d_in[10];
    const float* kW1     = (const float*)d_in[11];
    const float* kb1     = (const float*)d_in[12];
    const float* kW2     = (const float*)d_in[13];
    const float* kb2     = (const float*)d_in[14];
    const float* q_noise = (const float*)d_in[15];
    const float* k_noise = (const float*)d_in[16];
    float* out = (float*)d_out;

    cudaFuncSetAttribute(proj_tc, cudaFuncAttributeMaxDynamicSharedMemorySize,
                         PROJ_SMEM_BYTES);
    cudaFuncSetAttribute(selector_tc, cudaFuncAttributeMaxDynamicSharedMemorySize,
                         SELG_SMEM_BYTES);

    zero_sums<<<BATCH * LSEQ / 512, 512>>>();
    proj_tc<<<dim3(64, 2), 256, PROJ_SMEM_BYTES>>>(query, key, Wq, bq, Wk, bk);
    fft_fwd_kernel<<<256, FFT_NT>>>();
    selector_tc<<<dim3((FLEN + 127) / 128, BATCH, 2), 256, SELG_SMEM_BYTES>>>(
        qW1, qb1, qW2, qb2, kW1, kb1, kW2, kb2, q_noise, k_noise);
    fft_inv_kernel<<<256, FFT_NT>>>();
    gemm_scores_bf16<<<dim3(32, 32, BATCH), 256>>>(out, mask);
    scale_kernel<<<(int)((size_t)BATCH * LSEQ * LSEQ / 4 / 512), 512>>>(out);
}

// round 10
// speedup vs baseline: 6.0239x; 1.0467x over previous
#include <cuda_runtime.h>
#include <cuda_bf16.h>
#include <cstdint>

#define BATCH 2
#define LSEQ 4096
#define DMODEL 768
#define HDIM 128
#define FLEN 2049
#define INV_SQRT_DK 0.08838834764831845f
#define GEPS 1e-9f
#define PI_F 3.14159265358979323846f

// ---------------- scratch ----------------
__device__ float  g_q [BATCH*HDIM*LSEQ];
__device__ float  g_k [BATCH*HDIM*LSEQ];
__device__ float2 g_Qf[BATCH*HDIM*FLEN];
__device__ float2 g_Kf[BATCH*HDIM*FLEN];
__device__ float  g_ReT[2*BATCH*FLEN*HDIM];
__device__ float  g_zq[BATCH*FLEN];
__device__ float  g_zk[BATCH*FLEN];
__device__ __nv_bfloat16 g_qf_bf[BATCH*HDIM*LSEQ];
__device__ __nv_bfloat16 g_kf_bf[BATCH*HDIM*LSEQ];
__device__ float  g_rowsum[BATCH*LSEQ];

__device__ __forceinline__ uint32_t sptr(const void* p) {
    return (uint32_t)__cvta_generic_to_shared(p);
}
__device__ __forceinline__ void cp16(void* smem_dst, const void* gmem_src) {
    asm volatile("cp.async.ca.shared.global [%0], [%1], 16;"
                 :: "r"(sptr(smem_dst)), "l"(gmem_src));
}

// ---------------- projection GEMM: tf32 mma + 3-stage cp.async ----------------
#define PROJ_STAGES 3
#define PROJ_BK 32
#define PROJ_KP 36
#define PROJ_MAT (128 * PROJ_KP)
#define PROJ_SMEM_FLOATS (PROJ_STAGES * PROJ_MAT * 2)
#define PROJ_SMEM_BYTES (PROJ_SMEM_FLOATS * 4)

__global__ __launch_bounds__(256) void proj_tc(
    const float* __restrict__ query, const float* __restrict__ key,
    const float* __restrict__ Wq, const float* __restrict__ bq,
    const float* __restrict__ Wk, const float* __restrict__ bk)
{
    extern __shared__ float dsm[];
    float* Wbase = dsm;
    float* Xbase = dsm + PROJ_STAGES * PROJ_MAT;

    const int tensor = blockIdx.y;
    const float* X  = tensor ? key : query;
    const float* W  = tensor ? Wk  : Wq;
    const float* bi = tensor ? bk  : bq;
    float* dst = tensor ? g_k : g_q;

    const int l0 = blockIdx.x * 128;
    const int tid  = threadIdx.x;
    const int warp = tid >> 5, lane = tid & 31;
    const int g = lane >> 2, tg = lane & 3;
    const int wd = (warp & 1) * 64;
    const int wn = (warp >> 1) * 32;

    float acc[4][4][4];
    #pragma unroll
    for (int i = 0; i < 4; i++)
        #pragma unroll
        for (int j = 0; j < 4; j++)
            #pragma unroll
            for (int c = 0; c < 4; c++) acc[i][j][c] = 0.f;

    auto load_stage = [&](int kc, int st) {
        const int k0 = kc * PROJ_BK;
        float* Ws = Wbase + st * PROJ_MAT;
        float* Xs = Xbase + st * PROJ_MAT;
        #pragma unroll
        for (int it = 0; it < 4; it++) {
            int idx = tid + 256 * it;
            int row = idx >> 3;
            int seg = (idx & 7) << 2;
            cp16(Ws + row * PROJ_KP + seg, W + (size_t)row * DMODEL + k0 + seg);
            cp16(Xs + row * PROJ_KP + seg, X + (size_t)(l0 + row) * DMODEL + k0 + seg);
        }
        asm volatile("cp.async.commit_group;");
    };

    load_stage(0, 0);
    load_stage(1, 1);

    const int NCHUNK = DMODEL / PROJ_BK;
    #pragma unroll 1
    for (int kc = 0; kc < NCHUNK; kc++) {
        const int st = kc % PROJ_STAGES;
        asm volatile("cp.async.wait_group 1;");
        __syncthreads();
        if (kc + 2 < NCHUNK) load_stage(kc + 2, (kc + 2) % PROJ_STAGES);

        const float* Ws = Wbase + st * PROJ_MAT;
        const float* Xs = Xbase + st * PROJ_MAT;

        #pragma unroll
        for (int ks = 0; ks < 4; ks++) {
            const int k = ks * 8;
            uint32_t a[4][4], bf[4][2];
            #pragma unroll
            for (int i = 0; i < 4; i++) {
                int d = wd + i * 16 + g;
                a[i][0] = __float_as_uint(Ws[(d    ) * PROJ_KP + k + tg    ]);
                a[i][1] = __float_as_uint(Ws[(d + 8) * PROJ_KP + k + tg    ]);
                a[i][2] = __float_as_uint(Ws[(d    ) * PROJ_KP + k + tg + 4]);
                a[i][3] = __float_as_uint(Ws[(d + 8) * PROJ_KP + k + tg + 4]);
            }
            #pragma unroll
            for (int j = 0; j < 4; j++) {
                int n = wn + j * 8 + g;
                bf[j][0] = __float_as_uint(Xs[n * PROJ_KP + k + tg    ]);
                bf[j][1] = __float_as_uint(Xs[n * PROJ_KP + k + tg + 4]);
            }
            #pragma unroll
            for (int i = 0; i < 4; i++)
                #pragma unroll
                for (int j = 0; j < 4; j++) {
                    asm volatile(
                        "mma.sync.aligned.m16n8k8.row.col.f32.tf32.tf32.f32 "
                        "{%0,%1,%2,%3},{%4,%5,%6,%7},{%8,%9},{%0,%1,%2,%3};"
                        : "+f"(acc[i][j][0]), "+f"(acc[i][j][1]),
                          "+f"(acc[i][j][2]), "+f"(acc[i][j][3])
                        : "r"(a[i][0]), "r"(a[i][1]), "r"(a[i][2]), "r"(a[i][3]),
                          "r"(bf[j][0]), "r"(bf[j][1]));
                }
        }
        __syncthreads();
    }

    #pragma unroll
    for (int i = 0; i < 4; i++) {
        int d0 = wd + i * 16 + g;
        float bv0 = bi[d0], bv1 = bi[d0 + 8];
        #pragma unroll
        for (int j = 0; j < 4; j++) {
            int gl = l0 + wn + j * 8 + 2 * tg;
            int b  = gl >> 12;
            int l  = gl & 4095;
            float* o0 = dst + (size_t)((b << 7) + d0    ) * LSEQ + l;
            float* o1 = dst + (size_t)((b << 7) + d0 + 8) * LSEQ + l;
            *(float2*)o0 = make_float2(acc[i][j][0] + bv0, acc[i][j][1] + bv0);
            *(float2*)o1 = make_float2(acc[i][j][2] + bv1, acc[i][j][3] + bv1);
        }
    }
}

// ---------------- radix-4 4096-pt FFT ----------------
#define FFT_NT 512
__device__ __forceinline__ void fill_tw(float2* tw, int tid)
{
    for (int j = tid; j < 1024; j += FFT_NT) {
        float ang = -PI_F * (float)j / 2048.0f;
        float s, c;
        __sincosf(ang, &s, &c);
        tw[j] = make_float2(c, s);
    }
}

__device__ __forceinline__ float2 cmul(float2 a, float2 b) {
    return make_float2(a.x*b.x - a.y*b.y, a.x*b.y + a.y*b.x);
}

__device__ __forceinline__ int dr12(int i) {
    unsigned y = __brev((unsigned)i) >> 20;
    return (int)(((y & 0x555u) << 1) | ((y >> 1) & 0x555u));
}

__device__ __forceinline__ void fft4096_r4(float2* s, const float2* tw, int tid, bool inv)
{
    #pragma unroll 1
    for (int st = 0; st < 6; st++) {
        const int twoSt = 2 * st;
        const int L = 1 << twoSt;
        const int shift = 10 - twoSt;
        #pragma unroll
        for (int tt = 0; tt < 1024 / FFT_NT; tt++) {
            int t = tid + tt * FFT_NT;
            int j  = t & (L - 1);
            int i0 = ((t >> twoSt) << (twoSt + 2)) + j;
            int e  = j << shift;
            float2 w1 = tw[e];
            if (inv) w1.y = -w1.y;
            float2 w2 = cmul(w1, w1);
            float2 w3 = cmul(w1, w2);

            float2 u0 = s[i0];
            float2 u1 = cmul(s[i0 + L],   w1);
            float2 u2 = cmul(s[i0 + 2*L], w2);
            float2 u3 = cmul(s[i0 + 3*L], w3);

            float2 v0 = make_float2(u0.x + u2.x, u0.y + u2.y);
            float2 v1 = make_float2(u0.x - u2.x, u0.y - u2.y);
            float2 v2 = make_float2(u1.x + u3.x, u1.y + u3.y);
            float2 v3 = make_float2(u1.x - u3.x, u1.y - u3.y);

            s[i0]       = make_float2(v0.x + v2.x, v0.y + v2.y);
            s[i0 + 2*L] = make_float2(v0.x - v2.x, v0.y - v2.y);
            if (!inv) {
                s[i0 + L]   = make_float2(v1.x + v3.y, v1.y - v3.x);
                s[i0 + 3*L] = make_float2(v1.x - v3.y, v1.y + v3.x);
            } else {
                s[i0 + L]   = make_float2(v1.x - v3.y, v1.y + v3.x);
                s[i0 + 3*L] = make_float2(v1.x + v3.y, v1.y - v3.x);
            }
        }
        __syncthreads();
    }
}

// forward FFT + zero rowsums (first 16 blocks) + freq-major real parts
__global__ __launch_bounds__(FFT_NT) void fft_fwd_kernel()
{
    __shared__ float2 s[4096];
    __shared__ float2 tw[1024];
    const int blk = blockIdx.x;
    const int tensor = blk >> 7;
    const int pr = blk & 127;
    const int b = pr >> 6;
    const int j = pr & 63;
    const int row0 = b * 128 + 2 * j;
    const float* src0 = (tensor ? g_k : g_q) + (size_t)row0 * LSEQ;
    const float* src1 = src0 + LSEQ;
    float2* dst0 = (tensor ? g_Kf : g_Qf) + (size_t)row0 * FLEN;
    float2* dst1 = dst0 + FLEN;
    float* rt = g_ReT + ((size_t)(tensor * BATCH + b) * FLEN) * HDIM;
    const int tid = threadIdx.x;

    if (blk < 16) g_rowsum[blk * FFT_NT + tid] = 0.f;

    fill_tw(tw, tid);
    for (int i = tid; i < 4096; i += FFT_NT) {
        s[dr12(i)] = make_float2(src0[i], src1[i]);
    }
    __syncthreads();
    fft4096_r4(s, tw, tid, false);

    for (int f = tid; f < FLEN; f += FFT_NT) {
        float2 cf = s[f];
        float2 cn = s[(4096 - f) & 4095];
        float re0 = 0.5f * (cf.x + cn.x);
        float re1 = 0.5f * (cf.y + cn.y);
        dst0[f] = make_float2(re0, 0.5f * (cf.y - cn.y));
        dst1[f] = make_float2(re1, 0.5f * (cn.x - cf.x));
        rt[(size_t)f * HDIM + 2 * j    ] = re0;
        rt[(size_t)f * HDIM + 2 * j + 1] = re1;
    }
}

// ---------------- selector: tf32 tensor-core MLP, 64-freq tiles + cp.async ----------------
#define SELG_KP 132
#define SELG_AS (64 * SELG_KP)
#define SELG_BS (64 * SELG_KP)
#define SELG_SMEM_BYTES ((SELG_AS + SELG_BS) * 4)

__global__ __launch_bounds__(256) void selector_tc(
    const float* __restrict__ qW1, const float* __restrict__ qb1,
    const float* __restrict__ qW2, const float* __restrict__ qb2,
    const float* __restrict__ kW1, const float* __restrict__ kb1,
    const float* __restrict__ kW2, const float* __restrict__ kb2,
    const float* __restrict__ q_noise, const float* __restrict__ k_noise)
{
    extern __shared__ float ssm[];
    float* As  = ssm;                 // [64][132]  W1
    float* Bs  = ssm + SELG_AS;       // [64][132]  xr tile
    float* h1s = ssm;                 // reuse As region: [64][65]
    __shared__ float lgs[64][2];

    const int tile = blockIdx.x;
    const int b = blockIdx.y;
    const int tensor = blockIdx.z;
    const int f0 = tile * 64;
    const float* ReT = g_ReT + ((size_t)(tensor * BATCH + b) * FLEN) * HDIM;
    const float* W1 = tensor ? kW1 : qW1;
    const float* b1 = tensor ? kb1 : qb1;
    const float* W2 = tensor ? kW2 : qW2;
    const float* b2 = tensor ? kb2 : qb2;
    const float* nz = tensor ? k_noise : q_noise;
    float* z = tensor ? g_zk : g_zq;

    const int tid  = threadIdx.x;
    const int warp = tid >> 5, lane = tid & 31;
    const int g = lane >> 2, tg = lane & 3;
    const int wu = (warp & 1) * 32;    // u offset (m)
    const int wf = (warp >> 1) * 16;   // f offset (n)

    // async stage W1 [64][128] and xr tile [64][128]
    #pragma unroll
    for (int it = 0; it < 8; it++) {
        int idx = tid + 256 * it;          // 0..2047
        int row = idx >> 5;                // 0..63
        int seg = (idx & 31) << 2;         // 0..124
        cp16(As + row * SELG_KP + seg, W1 + row * 128 + seg);
        int f = f0 + row;
        if (f < FLEN) {
            cp16(Bs + row * SELG_KP + seg, ReT + (size_t)f * HDIM + seg);
        } else {
            *(float4*)(Bs + row * SELG_KP + seg) = make_float4(0.f, 0.f, 0.f, 0.f);
        }
    }
    asm volatile("cp.async.commit_group;");
    asm volatile("cp.async.wait_group 0;");
    __syncthreads();

    float acc[2][2][4];
    #pragma unroll
    for (int i = 0; i < 2; i++)
        #pragma unroll
        for (int j = 0; j < 2; j++)
            #pragma unroll
            for (int c = 0; c < 4; c++) acc[i][j][c] = 0.f;

    #pragma unroll
    for (int ks = 0; ks < 16; ks++) {
        const int k = ks * 8;
        uint32_t a[2][4], bf[2][2];
        #pragma unroll
        for (int i = 0; i < 2; i++) {
            int u = wu + i * 16 + g;
            a[i][0] = __float_as_uint(As[(u    ) * SELG_KP + k + tg    ]);
            a[i][1] = __float_as_uint(As[(u + 8) * SELG_KP + k + tg    ]);
            a[i][2] = __float_as_uint(As[(u    ) * SELG_KP + k + tg + 4]);
            a[i][3] = __float_as_uint(As[(u + 8) * SELG_KP + k + tg + 4]);
        }
        #pragma unroll
        for (int j = 0; j < 2; j++) {
            int n = wf + j * 8 + g;
            bf[j][0] = __float_as_uint(Bs[n * SELG_KP + k + tg    ]);
            bf[j][1] = __float_as_uint(Bs[n * SELG_KP + k + tg + 4]);
        }
        #pragma unroll
        for (int i = 0; i < 2; i++)
            #pragma unroll
            for (int j = 0; j < 2; j++) {
                asm volatile(
                    "mma.sync.aligned.m16n8k8.row.col.f32.tf32.tf32.f32 "
                    "{%0,%1,%2,%3},{%4,%5,%6,%7},{%8,%9},{%0,%1,%2,%3};"
                    : "+f"(acc[i][j][0]), "+f"(acc[i][j][1]),
                      "+f"(acc[i][j][2]), "+f"(acc[i][j][3])
                    : "r"(a[i][0]), "r"(a[i][1]), "r"(a[i][2]), "r"(a[i][3]),
                      "r"(bf[j][0]), "r"(bf[j][1]));
            }
    }
    __syncthreads();

    // bias + relu -> h1s[f][u] (pad 65)
    #pragma unroll
    for (int i = 0; i < 2; i++) {
        int u0 = wu + i * 16 + g;
        float bv0 = b1[u0], bv1 = b1[u0 + 8];
        #pragma unroll
        for (int j = 0; j < 2; j++) {
            int f = wf + j * 8 + 2 * tg;
            h1s[(f    ) * 65 + u0    ] = fmaxf(acc[i][j][0] + bv0, 0.f);
            h1s[(f + 1) * 65 + u0    ] = fmaxf(acc[i][j][1] + bv0, 0.f);
            h1s[(f    ) * 65 + u0 + 8] = fmaxf(acc[i][j][2] + bv1, 0.f);
            h1s[(f + 1) * 65 + u0 + 8] = fmaxf(acc[i][j][3] + bv1, 0.f);
        }
    }
    __syncthreads();

    // output layer + gumbel (128 threads: 64 freqs x 2 classes)
    if (tid < 128) {
        int fl = tid >> 1, c = tid & 1;
        int f = f0 + fl;
        if (f < FLEN) {
            float acc2 = b2[c];
            const float* w2 = W2 + c * 64;
            const float* h = h1s + fl * 65;
            #pragma unroll 16
            for (int u = 0; u < 64; u++) acc2 = fmaf(h[u], w2[u], acc2);
            float n = nz[((size_t)b * FLEN + f) * 2 + c];
            lgs[fl][c] = acc2 + (-logf(-logf(n + GEPS) + GEPS));
        }
    }
    __syncthreads();
    if (tid < 64) {
        int f = f0 + tid;
        if (f < FLEN) z[b * FLEN + f] = 1.f / (1.f + expf(lgs[tid][0] - lgs[tid][1]));
    }
}

// inverse FFT; store bf16.
__global__ __launch_bounds__(FFT_NT) void fft_inv_kernel()
{
    __shared__ float2 s[4096];
    __shared__ float2 tw[1024];
    const int blk = blockIdx.x;
    const int tensor = blk >> 7;
    const int pr = blk & 127;
    const int b = pr >> 6;
    const int j = pr & 63;
    const int row0 = b * 128 + 2 * j;
    const float2* src0 = (tensor ? g_Kf : g_Qf) + (size_t)row0 * FLEN;
    const float2* src1 = src0 + FLEN;
    const float* z = (tensor ? g_zk : g_zq) + (size_t)b * FLEN;
    __nv_bfloat16* dst0 = (tensor ? g_kf_bf : g_qf_bf) + (size_t)row0 * LSEQ;
    __nv_bfloat16* dst1 = dst0 + LSEQ;
    const int tid = threadIdx.x;

    fill_tw(tw, tid);
    for (int i = tid; i < 4096; i += FFT_NT) {
        int f = (i <= 2048) ? i : (4096 - i);
        float zz = z[f];
        float2 a = src0[f];
        float2 bb = src1[f];
        if (i > 2048) { a.y = -a.y; bb.y = -bb.y; }
        a.x *= zz; a.y *= zz; bb.x *= zz; bb.y *= zz;
        s[dr12(i)] = make_float2(a.x - bb.y, a.y + bb.x);
    }
    __syncthreads();
    fft4096_r4(s, tw, tid, true);
    const float inv = 1.f / 4096.f;
    for (int i = tid; i < 4096; i += FFT_NT) {
        float2 v = s[i];
        dst0[i] = __float2bfloat16(v.x * inv);
        dst1[i] = __float2bfloat16(v.y * inv);
    }
}

// ---------------- scores GEMM + fused mask/exp/rowsum epilogue ----------------
__global__ __launch_bounds__(256) void gemm_scores_bf16(float* __restrict__ out,
                                                        const int* __restrict__ mask)
{
    __shared__ __align__(16) __nv_bfloat16 Qs[2][32][136];
    __shared__ __align__(16) __nv_bfloat16 Ks[2][32][136];

    const int b  = blockIdx.z;
    const int l0 = blockIdx.y * 128;
    const int m0 = blockIdx.x * 128;
    const __nv_bfloat16* A  = g_qf_bf + (size_t)b * HDIM * LSEQ;
    const __nv_bfloat16* Bm = g_kf_bf + (size_t)b * HDIM * LSEQ;
    const int* mrow = mask + (size_t)b * LSEQ;

    const int tid  = threadIdx.x;
    const int warp = tid >> 5, lane = tid & 31;
    const int g = lane >> 2, tg = lane & 3;
    const int wl = (warp & 1) * 64;
    const int wn = (warp >> 1) * 32;

    const int lr   = lane & 7;
    const int koff = lr + ((lane & 16) ? 8 : 0);
    const int coff = (lane & 8) ? 8 : 0;
    const int kb   = lr + ((lane & 8) ? 8 : 0);
    const int cb   = (lane & 16) ? 8 : 0;

    float acc[4][4][4];
    #pragma unroll
    for (int i = 0; i < 4; i++)
        #pragma unroll
        for (int j = 0; j < 4; j++)
            #pragma unroll
            for (int c = 0; c < 4; c++) acc[i][j][c] = 0.f;

    auto load_chunk = [&](int kc, int bufi) {
        #pragma unroll
        for (int it = 0; it < 2; it++) {
            int idx = tid + 256 * it;
            int k  = idx >> 4;
            int c8 = (idx & 15) << 3;
            cp16(&Qs[bufi][k][c8], A  + (size_t)(kc * 32 + k) * LSEQ + l0 + c8);
            cp16(&Ks[bufi][k][c8], Bm + (size_t)(kc * 32 + k) * LSEQ + m0 + c8);
        }
        asm volatile("cp.async.commit_group;");
    };

    load_chunk(0, 0);

    #pragma unroll 1
    for (int kc = 0; kc < 4; kc++) {
        const int buf = kc & 1;
        if (kc < 3) load_chunk(kc + 1, buf ^ 1);
        if (kc < 3) asm volatile("cp.async.wait_group 1;");
        else        asm volatile("cp.async.wait_group 0;");
        __syncthreads();

        #pragma unroll
        for (int ks = 0; ks < 2; ks++) {
            const int k0 = ks * 16;
            uint32_t a[4][4];
            #pragma unroll
            for (int i = 0; i < 4; i++) {
                uint32_t addr = sptr(&Qs[buf][k0 + koff][wl + 16 * i + coff]);
                asm volatile(
                    "ldmatrix.sync.aligned.m8n8.x4.trans.shared.b16 {%0,%1,%2,%3}, [%4];"
                    : "=r"(a[i][0]), "=r"(a[i][1]), "=r"(a[i][2]), "=r"(a[i][3])
                    : "r"(addr));
            }
            uint32_t bfr[2][4];
            #pragma unroll
            for (int jj = 0; jj < 2; jj++) {
                uint32_t addr = sptr(&Ks[buf][k0 + kb][wn + 16 * jj + cb]);
                asm volatile(
                    "ldmatrix.sync.aligned.m8n8.x4.trans.shared.b16 {%0,%1,%2,%3}, [%4];"
                    : "=r"(bfr[jj][0]), "=r"(bfr[jj][1]), "=r"(bfr[jj][2]), "=r"(bfr[jj][3])
                    : "r"(addr));
            }
            #pragma unroll
            for (int i = 0; i < 4; i++)
                #pragma unroll
                for (int j = 0; j < 4; j++) {
                    uint32_t b0 = bfr[j >> 1][2 * (j & 1)];
                    uint32_t b1 = bfr[j >> 1][2 * (j & 1) + 1];
                    asm volatile(
                        "mma.sync.aligned.m16n8k16.row.col.f32.bf16.bf16.f32 "
                        "{%0,%1,%2,%3},{%4,%5,%6,%7},{%8,%9},{%0,%1,%2,%3};"
                        : "+f"(acc[i][j][0]), "+f"(acc[i][j][1]),
                          "+f"(acc[i][j][2]), "+f"(acc[i][j][3])
                        : "r"(a[i][0]), "r"(a[i][1]), "r"(a[i][2]), "r"(a[i][3]),
                          "r"(b0), "r"(b1));
                }
        }
        __syncthreads();
    }

    #pragma unroll
    for (int i = 0; i < 4; i++) {
        int row0 = l0 + wl + i * 16 + g;
        float rs0 = 0.f, rs1 = 0.f;
        #pragma unroll
        for (int j = 0; j < 4; j++) {
            int col = m0 + wn + j * 8 + 2 * tg;
            int mv0 = mrow[col], mv1 = mrow[col + 1];
            float p00 = mv0 ? __expf(acc[i][j][0] * INV_SQRT_DK) : 0.f;
            float p01 = mv1 ? __expf(acc[i][j][1] * INV_SQRT_DK) : 0.f;
            float p10 = mv0 ? __expf(acc[i][j][2] * INV_SQRT_DK) : 0.f;
            float p11 = mv1 ? __expf(acc[i][j][3] * INV_SQRT_DK) : 0.f;
            *(float2*)(out + ((size_t)b * LSEQ + row0    ) * LSEQ + col) = make_float2(p00, p01);
            *(float2*)(out + ((size_t)b * LSEQ + row0 + 8) * LSEQ + col) = make_float2(p10, p11);
            rs0 += p00 + p01;
            rs1 += p10 + p11;
        }
        rs0 += __shfl_xor_sync(0xffffffffu, rs0, 1);
        rs0 += __shfl_xor_sync(0xffffffffu, rs0, 2);
        rs1 += __shfl_xor_sync(0xffffffffu, rs1, 1);
        rs1 += __shfl_xor_sync(0xffffffffu, rs1, 2);
        if (tg == 0) {
            atomicAdd(&g_rowsum[b * LSEQ + row0    ], rs0);
            atomicAdd(&g_rowsum[b * LSEQ + row0 + 8], rs1);
        }
    }
}

// ---------------- final normalize ----------------
__global__ __launch_bounds__(512) void scale_kernel(float* __restrict__ out)
{
    size_t i4 = (size_t)blockIdx.x * 512 + threadIdx.x;
    int row = (int)(i4 >> 10);
    float inv = 1.f / g_rowsum[row];
    float4 v = ((const float4*)out)[i4];
    v.x *= inv; v.y *= inv; v.z *= inv; v.w *= inv;
    ((float4*)out)[i4] = v;
}

// ---------------- launch ----------------
extern "C" void kernel_launch(void* const* d_in, const int* in_sizes, int n_in,
                              void* d_out, int out_size)
{
    const float* query   = (const float*)d_in[0];
    const float* key     = (const float*)d_in[1];
    const int*   mask    = (const int*)  d_in[2];
    const float* Wq      = (const float*)d_in[3];
    const float* bq      = (const float*)d_in[4];
    const float* Wk      = (const float*)d_in[5];
    const float* bk      = (const float*)d_in[6];
    const float* qW1     = (const float*)d_in[7];
    const float* qb1     = (const float*)d_in[8];
    const float* qW2     = (const float*)d_in[9];
    const float* qb2     = (const float*)d_in[10];
    const float* kW1     = (const float*)d_in[11];
    const float* kb1     = (const float*)d_in[12];
    const float* kW2     = (const float*)d_in[13];
    const float* kb2     = (const float*)d_in[14];
    const float* q_noise = (const float*)d_in[15];
    const float* k_noise = (const float*)d_in[16];
    float* out = (float*)d_out;

    cudaFuncSetAttribute(proj_tc, cudaFuncAttributeMaxDynamicSharedMemorySize,
                         PROJ_SMEM_BYTES);
    cudaFuncSetAttribute(selector_tc, cudaFuncAttributeMaxDynamicSharedMemorySize,
                         SELG_SMEM_BYTES);

    proj_tc<<<dim3(64, 2), 256, PROJ_SMEM_BYTES>>>(query, key, Wq, bq, Wk, bk);
    fft_fwd_kernel<<<256, FFT_NT>>>();
    selector_tc<<<dim3((FLEN + 63) / 64, BATCH, 2), 256, SELG_SMEM_BYTES>>>(
        qW1, qb1, qW2, qb2, kW1, kb1, kW2, kb2, q_noise, k_noise);
    fft_inv_kernel<<<256, FFT_NT>>>();
    gemm_scores_bf16<<<dim3(32, 32, BATCH), 256>>>(out, mask);
    scale_kernel<<<(int)((size_t)BATCH * LSEQ * LSEQ / 4 / 512), 512>>>(out);
}

// round 11
// speedup vs baseline: 6.1870x; 1.0271x over previous
#include <cuda_runtime.h>
#include <cuda_bf16.h>
#include <cstdint>

#define BATCH 2
#define LSEQ 4096
#define DMODEL 768
#define HDIM 128
#define FLEN 2049
#define INV_SQRT_DK 0.08838834764831845f
#define GEPS 1e-9f
#define PI_F 3.14159265358979323846f

// ---------------- scratch ----------------
__device__ float  g_q [BATCH*HDIM*LSEQ];
__device__ float  g_k [BATCH*HDIM*LSEQ];
__device__ float2 g_Qf[BATCH*HDIM*FLEN];
__device__ float2 g_Kf[BATCH*HDIM*FLEN];
__device__ float  g_ReT[2*BATCH*FLEN*HDIM];
__device__ float  g_zq[BATCH*FLEN];
__device__ float  g_zk[BATCH*FLEN];
__device__ __nv_bfloat16 g_qf_bf[BATCH*HDIM*LSEQ];
__device__ __nv_bfloat16 g_kf_bf[BATCH*HDIM*LSEQ];
__device__ float  g_rowsum[BATCH*LSEQ];

__device__ __forceinline__ uint32_t sptr(const void* p) {
    return (uint32_t)__cvta_generic_to_shared(p);
}
__device__ __forceinline__ void cp16(void* smem_dst, const void* gmem_src) {
    asm volatile("cp.async.ca.shared.global [%0], [%1], 16;"
                 :: "r"(sptr(smem_dst)), "l"(gmem_src));
}

// ---------------- projection GEMM: tf32 mma + 3-stage cp.async ----------------
#define PROJ_STAGES 3
#define PROJ_BK 32
#define PROJ_KP 36
#define PROJ_MAT (128 * PROJ_KP)
#define PROJ_SMEM_FLOATS (PROJ_STAGES * PROJ_MAT * 2)
#define PROJ_SMEM_BYTES (PROJ_SMEM_FLOATS * 4)

__global__ __launch_bounds__(256) void proj_tc(
    const float* __restrict__ query, const float* __restrict__ key,
    const float* __restrict__ Wq, const float* __restrict__ bq,
    const float* __restrict__ Wk, const float* __restrict__ bk)
{
    extern __shared__ float dsm[];
    float* Wbase = dsm;
    float* Xbase = dsm + PROJ_STAGES * PROJ_MAT;

    const int tensor = blockIdx.y;
    const float* X  = tensor ? key : query;
    const float* W  = tensor ? Wk  : Wq;
    const float* bi = tensor ? bk  : bq;
    float* dst = tensor ? g_k : g_q;

    const int l0 = blockIdx.x * 128;
    const int tid  = threadIdx.x;
    const int warp = tid >> 5, lane = tid & 31;
    const int g = lane >> 2, tg = lane & 3;
    const int wd = (warp & 1) * 64;
    const int wn = (warp >> 1) * 32;

    float acc[4][4][4];
    #pragma unroll
    for (int i = 0; i < 4; i++)
        #pragma unroll
        for (int j = 0; j < 4; j++)
            #pragma unroll
            for (int c = 0; c < 4; c++) acc[i][j][c] = 0.f;

    auto load_stage = [&](int kc, int st) {
        const int k0 = kc * PROJ_BK;
        float* Ws = Wbase + st * PROJ_MAT;
        float* Xs = Xbase + st * PROJ_MAT;
        #pragma unroll
        for (int it = 0; it < 4; it++) {
            int idx = tid + 256 * it;
            int row = idx >> 3;
            int seg = (idx & 7) << 2;
            cp16(Ws + row * PROJ_KP + seg, W + (size_t)row * DMODEL + k0 + seg);
            cp16(Xs + row * PROJ_KP + seg, X + (size_t)(l0 + row) * DMODEL + k0 + seg);
        }
        asm volatile("cp.async.commit_group;");
    };

    load_stage(0, 0);
    load_stage(1, 1);

    const int NCHUNK = DMODEL / PROJ_BK;
    #pragma unroll 1
    for (int kc = 0; kc < NCHUNK; kc++) {
        const int st = kc % PROJ_STAGES;
        asm volatile("cp.async.wait_group 1;");
        __syncthreads();
        if (kc + 2 < NCHUNK) load_stage(kc + 2, (kc + 2) % PROJ_STAGES);

        const float* Ws = Wbase + st * PROJ_MAT;
        const float* Xs = Xbase + st * PROJ_MAT;

        #pragma unroll
        for (int ks = 0; ks < 4; ks++) {
            const int k = ks * 8;
            uint32_t a[4][4], bf[4][2];
            #pragma unroll
            for (int i = 0; i < 4; i++) {
                int d = wd + i * 16 + g;
                a[i][0] = __float_as_uint(Ws[(d    ) * PROJ_KP + k + tg    ]);
                a[i][1] = __float_as_uint(Ws[(d + 8) * PROJ_KP + k + tg    ]);
                a[i][2] = __float_as_uint(Ws[(d    ) * PROJ_KP + k + tg + 4]);
                a[i][3] = __float_as_uint(Ws[(d + 8) * PROJ_KP + k + tg + 4]);
            }
            #pragma unroll
            for (int j = 0; j < 4; j++) {
                int n = wn + j * 8 + g;
                bf[j][0] = __float_as_uint(Xs[n * PROJ_KP + k + tg    ]);
                bf[j][1] = __float_as_uint(Xs[n * PROJ_KP + k + tg + 4]);
            }
            #pragma unroll
            for (int i = 0; i < 4; i++)
                #pragma unroll
                for (int j = 0; j < 4; j++) {
                    asm volatile(
                        "mma.sync.aligned.m16n8k8.row.col.f32.tf32.tf32.f32 "
                        "{%0,%1,%2,%3},{%4,%5,%6,%7},{%8,%9},{%0,%1,%2,%3};"
                        : "+f"(acc[i][j][0]), "+f"(acc[i][j][1]),
                          "+f"(acc[i][j][2]), "+f"(acc[i][j][3])
                        : "r"(a[i][0]), "r"(a[i][1]), "r"(a[i][2]), "r"(a[i][3]),
                          "r"(bf[j][0]), "r"(bf[j][1]));
                }
        }
        __syncthreads();
    }

    #pragma unroll
    for (int i = 0; i < 4; i++) {
        int d0 = wd + i * 16 + g;
        float bv0 = bi[d0], bv1 = bi[d0 + 8];
        #pragma unroll
        for (int j = 0; j < 4; j++) {
            int gl = l0 + wn + j * 8 + 2 * tg;
            int b  = gl >> 12;
            int l  = gl & 4095;
            float* o0 = dst + (size_t)((b << 7) + d0    ) * LSEQ + l;
            float* o1 = dst + (size_t)((b << 7) + d0 + 8) * LSEQ + l;
            *(float2*)o0 = make_float2(acc[i][j][0] + bv0, acc[i][j][1] + bv0);
            *(float2*)o1 = make_float2(acc[i][j][2] + bv1, acc[i][j][3] + bv1);
        }
    }
}

// ---------------- radix-4 4096-pt FFT ----------------
#define FFT_NT 512
__device__ __forceinline__ void fill_tw(float2* tw, int tid)
{
    for (int j = tid; j < 1024; j += FFT_NT) {
        float ang = -PI_F * (float)j / 2048.0f;
        float s, c;
        __sincosf(ang, &s, &c);
        tw[j] = make_float2(c, s);
    }
}

__device__ __forceinline__ float2 cmul(float2 a, float2 b) {
    return make_float2(a.x*b.x - a.y*b.y, a.x*b.y + a.y*b.x);
}

__device__ __forceinline__ int dr12(int i) {
    unsigned y = __brev((unsigned)i) >> 20;
    return (int)(((y & 0x555u) << 1) | ((y >> 1) & 0x555u));
}

__device__ __forceinline__ void fft4096_r4(float2* s, const float2* tw, int tid, bool inv)
{
    #pragma unroll 1
    for (int st = 0; st < 6; st++) {
        const int twoSt = 2 * st;
        const int L = 1 << twoSt;
        const int shift = 10 - twoSt;
        #pragma unroll
        for (int tt = 0; tt < 1024 / FFT_NT; tt++) {
            int t = tid + tt * FFT_NT;
            int j  = t & (L - 1);
            int i0 = ((t >> twoSt) << (twoSt + 2)) + j;
            int e  = j << shift;
            float2 w1 = tw[e];
            if (inv) w1.y = -w1.y;
            float2 w2 = cmul(w1, w1);
            float2 w3 = cmul(w1, w2);

            float2 u0 = s[i0];
            float2 u1 = cmul(s[i0 + L],   w1);
            float2 u2 = cmul(s[i0 + 2*L], w2);
            float2 u3 = cmul(s[i0 + 3*L], w3);

            float2 v0 = make_float2(u0.x + u2.x, u0.y + u2.y);
            float2 v1 = make_float2(u0.x - u2.x, u0.y - u2.y);
            float2 v2 = make_float2(u1.x + u3.x, u1.y + u3.y);
            float2 v3 = make_float2(u1.x - u3.x, u1.y - u3.y);

            s[i0]       = make_float2(v0.x + v2.x, v0.y + v2.y);
            s[i0 + 2*L] = make_float2(v0.x - v2.x, v0.y - v2.y);
            if (!inv) {
                s[i0 + L]   = make_float2(v1.x + v3.y, v1.y - v3.x);
                s[i0 + 3*L] = make_float2(v1.x - v3.y, v1.y + v3.x);
            } else {
                s[i0 + L]   = make_float2(v1.x - v3.y, v1.y + v3.x);
                s[i0 + 3*L] = make_float2(v1.x + v3.y, v1.y - v3.x);
            }
        }
        __syncthreads();
    }
}

// forward FFT + zero rowsums (first 16 blocks) + freq-major real parts
__global__ __launch_bounds__(FFT_NT) void fft_fwd_kernel()
{
    __shared__ float2 s[4096];
    __shared__ float2 tw[1024];
    const int blk = blockIdx.x;
    const int tensor = blk >> 7;
    const int pr = blk & 127;
    const int b = pr >> 6;
    const int j = pr & 63;
    const int row0 = b * 128 + 2 * j;
    const float* src0 = (tensor ? g_k : g_q) + (size_t)row0 * LSEQ;
    const float* src1 = src0 + LSEQ;
    float2* dst0 = (tensor ? g_Kf : g_Qf) + (size_t)row0 * FLEN;
    float2* dst1 = dst0 + FLEN;
    float* rt = g_ReT + ((size_t)(tensor * BATCH + b) * FLEN) * HDIM;
    const int tid = threadIdx.x;

    if (blk < 16) g_rowsum[blk * FFT_NT + tid] = 0.f;

    fill_tw(tw, tid);
    for (int i = tid; i < 4096; i += FFT_NT) {
        s[dr12(i)] = make_float2(src0[i], src1[i]);
    }
    __syncthreads();
    fft4096_r4(s, tw, tid, false);

    for (int f = tid; f < FLEN; f += FFT_NT) {
        float2 cf = s[f];
        float2 cn = s[(4096 - f) & 4095];
        float re0 = 0.5f * (cf.x + cn.x);
        float re1 = 0.5f * (cf.y + cn.y);
        dst0[f] = make_float2(re0, 0.5f * (cf.y - cn.y));
        dst1[f] = make_float2(re1, 0.5f * (cn.x - cf.x));
        rt[(size_t)f * HDIM + 2 * j    ] = re0;
        rt[(size_t)f * HDIM + 2 * j + 1] = re1;
    }
}

// ---------------- selector: tf32 tensor-core MLP, 64-freq tiles + cp.async ----------------
#define SELG_KP 132
#define SELG_AS (64 * SELG_KP)
#define SELG_BS (64 * SELG_KP)
#define SELG_SMEM_BYTES ((SELG_AS + SELG_BS) * 4)

__global__ __launch_bounds__(256) void selector_tc(
    const float* __restrict__ qW1, const float* __restrict__ qb1,
    const float* __restrict__ qW2, const float* __restrict__ qb2,
    const float* __restrict__ kW1, const float* __restrict__ kb1,
    const float* __restrict__ kW2, const float* __restrict__ kb2,
    const float* __restrict__ q_noise, const float* __restrict__ k_noise)
{
    extern __shared__ float ssm[];
    float* As  = ssm;
    float* Bs  = ssm + SELG_AS;
    float* h1s = ssm;
    __shared__ float lgs[64][2];

    const int tile = blockIdx.x;
    const int b = blockIdx.y;
    const int tensor = blockIdx.z;
    const int f0 = tile * 64;
    const float* ReT = g_ReT + ((size_t)(tensor * BATCH + b) * FLEN) * HDIM;
    const float* W1 = tensor ? kW1 : qW1;
    const float* b1 = tensor ? kb1 : qb1;
    const float* W2 = tensor ? kW2 : qW2;
    const float* b2 = tensor ? kb2 : qb2;
    const float* nz = tensor ? k_noise : q_noise;
    float* z = tensor ? g_zk : g_zq;

    const int tid  = threadIdx.x;
    const int warp = tid >> 5, lane = tid & 31;
    const int g = lane >> 2, tg = lane & 3;
    const int wu = (warp & 1) * 32;
    const int wf = (warp >> 1) * 16;

    #pragma unroll
    for (int it = 0; it < 8; it++) {
        int idx = tid + 256 * it;
        int row = idx >> 5;
        int seg = (idx & 31) << 2;
        cp16(As + row * SELG_KP + seg, W1 + row * 128 + seg);
        int f = f0 + row;
        if (f < FLEN) {
            cp16(Bs + row * SELG_KP + seg, ReT + (size_t)f * HDIM + seg);
        } else {
            *(float4*)(Bs + row * SELG_KP + seg) = make_float4(0.f, 0.f, 0.f, 0.f);
        }
    }
    asm volatile("cp.async.commit_group;");
    asm volatile("cp.async.wait_group 0;");
    __syncthreads();

    float acc[2][2][4];
    #pragma unroll
    for (int i = 0; i < 2; i++)
        #pragma unroll
        for (int j = 0; j < 2; j++)
            #pragma unroll
            for (int c = 0; c < 4; c++) acc[i][j][c] = 0.f;

    #pragma unroll
    for (int ks = 0; ks < 16; ks++) {
        const int k = ks * 8;
        uint32_t a[2][4], bf[2][2];
        #pragma unroll
        for (int i = 0; i < 2; i++) {
            int u = wu + i * 16 + g;
            a[i][0] = __float_as_uint(As[(u    ) * SELG_KP + k + tg    ]);
            a[i][1] = __float_as_uint(As[(u + 8) * SELG_KP + k + tg    ]);
            a[i][2] = __float_as_uint(As[(u    ) * SELG_KP + k + tg + 4]);
            a[i][3] = __float_as_uint(As[(u + 8) * SELG_KP + k + tg + 4]);
        }
        #pragma unroll
        for (int j = 0; j < 2; j++) {
            int n = wf + j * 8 + g;
            bf[j][0] = __float_as_uint(Bs[n * SELG_KP + k + tg    ]);
            bf[j][1] = __float_as_uint(Bs[n * SELG_KP + k + tg + 4]);
        }
        #pragma unroll
        for (int i = 0; i < 2; i++)
            #pragma unroll
            for (int j = 0; j < 2; j++) {
                asm volatile(
                    "mma.sync.aligned.m16n8k8.row.col.f32.tf32.tf32.f32 "
                    "{%0,%1,%2,%3},{%4,%5,%6,%7},{%8,%9},{%0,%1,%2,%3};"
                    : "+f"(acc[i][j][0]), "+f"(acc[i][j][1]),
                      "+f"(acc[i][j][2]), "+f"(acc[i][j][3])
                    : "r"(a[i][0]), "r"(a[i][1]), "r"(a[i][2]), "r"(a[i][3]),
                      "r"(bf[j][0]), "r"(bf[j][1]));
            }
    }
    __syncthreads();

    #pragma unroll
    for (int i = 0; i < 2; i++) {
        int u0 = wu + i * 16 + g;
        float bv0 = b1[u0], bv1 = b1[u0 + 8];
        #pragma unroll
        for (int j = 0; j < 2; j++) {
            int f = wf + j * 8 + 2 * tg;
            h1s[(f    ) * 65 + u0    ] = fmaxf(acc[i][j][0] + bv0, 0.f);
            h1s[(f + 1) * 65 + u0    ] = fmaxf(acc[i][j][1] + bv0, 0.f);
            h1s[(f    ) * 65 + u0 + 8] = fmaxf(acc[i][j][2] + bv1, 0.f);
            h1s[(f + 1) * 65 + u0 + 8] = fmaxf(acc[i][j][3] + bv1, 0.f);
        }
    }
    __syncthreads();

    if (tid < 128) {
        int fl = tid >> 1, c = tid & 1;
        int f = f0 + fl;
        if (f < FLEN) {
            float acc2 = b2[c];
            const float* w2 = W2 + c * 64;
            const float* h = h1s + fl * 65;
            #pragma unroll 16
            for (int u = 0; u < 64; u++) acc2 = fmaf(h[u], w2[u], acc2);
            float n = nz[((size_t)b * FLEN + f) * 2 + c];
            lgs[fl][c] = acc2 + (-logf(-logf(n + GEPS) + GEPS));
        }
    }
    __syncthreads();
    if (tid < 64) {
        int f = f0 + tid;
        if (f < FLEN) z[b * FLEN + f] = 1.f / (1.f + expf(lgs[tid][0] - lgs[tid][1]));
    }
}

// inverse FFT; store bf16.
__global__ __launch_bounds__(FFT_NT) void fft_inv_kernel()
{
    __shared__ float2 s[4096];
    __shared__ float2 tw[1024];
    const int blk = blockIdx.x;
    const int tensor = blk >> 7;
    const int pr = blk & 127;
    const int b = pr >> 6;
    const int j = pr & 63;
    const int row0 = b * 128 + 2 * j;
    const float2* src0 = (tensor ? g_Kf : g_Qf) + (size_t)row0 * FLEN;
    const float2* src1 = src0 + FLEN;
    const float* z = (tensor ? g_zk : g_zq) + (size_t)b * FLEN;
    __nv_bfloat16* dst0 = (tensor ? g_kf_bf : g_qf_bf) + (size_t)row0 * LSEQ;
    __nv_bfloat16* dst1 = dst0 + LSEQ;
    const int tid = threadIdx.x;

    fill_tw(tw, tid);
    for (int i = tid; i < 4096; i += FFT_NT) {
        int f = (i <= 2048) ? i : (4096 - i);
        float zz = z[f];
        float2 a = src0[f];
        float2 bb = src1[f];
        if (i > 2048) { a.y = -a.y; bb.y = -bb.y; }
        a.x *= zz; a.y *= zz; bb.x *= zz; bb.y *= zz;
        s[dr12(i)] = make_float2(a.x - bb.y, a.y + bb.x);
    }
    __syncthreads();
    fft4096_r4(s, tw, tid, true);
    const float inv = 1.f / 4096.f;
    for (int i = tid; i < 4096; i += FFT_NT) {
        float2 v = s[i];
        dst0[i] = __float2bfloat16(v.x * inv);
        dst1[i] = __float2bfloat16(v.y * inv);
    }
}

// ---------------- scores GEMM: pass 1 = rowsums only, pass 2 = normalized write ----------------
template<int WRITE>
__global__ __launch_bounds__(256) void gemm_scores_bf16(float* __restrict__ out,
                                                        const int* __restrict__ mask)
{
    __shared__ __align__(16) __nv_bfloat16 Qs[2][32][136];
    __shared__ __align__(16) __nv_bfloat16 Ks[2][32][136];

    const int b  = blockIdx.z;
    const int l0 = blockIdx.y * 128;
    const int m0 = blockIdx.x * 128;
    const __nv_bfloat16* A  = g_qf_bf + (size_t)b * HDIM * LSEQ;
    const __nv_bfloat16* Bm = g_kf_bf + (size_t)b * HDIM * LSEQ;
    const int* mrow = mask + (size_t)b * LSEQ;

    const int tid  = threadIdx.x;
    const int warp = tid >> 5, lane = tid & 31;
    const int g = lane >> 2, tg = lane & 3;
    const int wl = (warp & 1) * 64;
    const int wn = (warp >> 1) * 32;

    const int lr   = lane & 7;
    const int koff = lr + ((lane & 16) ? 8 : 0);
    const int coff = (lane & 8) ? 8 : 0;
    const int kb   = lr + ((lane & 8) ? 8 : 0);
    const int cb   = (lane & 16) ? 8 : 0;

    float acc[4][4][4];
    #pragma unroll
    for (int i = 0; i < 4; i++)
        #pragma unroll
        for (int j = 0; j < 4; j++)
            #pragma unroll
            for (int c = 0; c < 4; c++) acc[i][j][c] = 0.f;

    auto load_chunk = [&](int kc, int bufi) {
        #pragma unroll
        for (int it = 0; it < 2; it++) {
            int idx = tid + 256 * it;
            int k  = idx >> 4;
            int c8 = (idx & 15) << 3;
            cp16(&Qs[bufi][k][c8], A  + (size_t)(kc * 32 + k) * LSEQ + l0 + c8);
            cp16(&Ks[bufi][k][c8], Bm + (size_t)(kc * 32 + k) * LSEQ + m0 + c8);
        }
        asm volatile("cp.async.commit_group;");
    };

    load_chunk(0, 0);

    #pragma unroll 1
    for (int kc = 0; kc < 4; kc++) {
        const int buf = kc & 1;
        if (kc < 3) load_chunk(kc + 1, buf ^ 1);
        if (kc < 3) asm volatile("cp.async.wait_group 1;");
        else        asm volatile("cp.async.wait_group 0;");
        __syncthreads();

        #pragma unroll
        for (int ks = 0; ks < 2; ks++) {
            const int k0 = ks * 16;
            uint32_t a[4][4];
            #pragma unroll
            for (int i = 0; i < 4; i++) {
                uint32_t addr = sptr(&Qs[buf][k0 + koff][wl + 16 * i + coff]);
                asm volatile(
                    "ldmatrix.sync.aligned.m8n8.x4.trans.shared.b16 {%0,%1,%2,%3}, [%4];"
                    : "=r"(a[i][0]), "=r"(a[i][1]), "=r"(a[i][2]), "=r"(a[i][3])
                    : "r"(addr));
            }
            uint32_t bfr[2][4];
            #pragma unroll
            for (int jj = 0; jj < 2; jj++) {
                uint32_t addr = sptr(&Ks[buf][k0 + kb][wn + 16 * jj + cb]);
                asm volatile(
                    "ldmatrix.sync.aligned.m8n8.x4.trans.shared.b16 {%0,%1,%2,%3}, [%4];"
                    : "=r"(bfr[jj][0]), "=r"(bfr[jj][1]), "=r"(bfr[jj][2]), "=r"(bfr[jj][3])
                    : "r"(addr));
            }
            #pragma unroll
            for (int i = 0; i < 4; i++)
                #pragma unroll
                for (int j = 0; j < 4; j++) {
                    uint32_t b0 = bfr[j >> 1][2 * (j & 1)];
                    uint32_t b1 = bfr[j >> 1][2 * (j & 1) + 1];
                    asm volatile(
                        "mma.sync.aligned.m16n8k16.row.col.f32.bf16.bf16.f32 "
                        "{%0,%1,%2,%3},{%4,%5,%6,%7},{%8,%9},{%0,%1,%2,%3};"
                        : "+f"(acc[i][j][0]), "+f"(acc[i][j][1]),
                          "+f"(acc[i][j][2]), "+f"(acc[i][j][3])
                        : "r"(a[i][0]), "r"(a[i][1]), "r"(a[i][2]), "r"(a[i][3]),
                          "r"(b0), "r"(b1));
                }
        }
        __syncthreads();
    }

    #pragma unroll
    for (int i = 0; i < 4; i++) {
        int row0 = l0 + wl + i * 16 + g;
        if (WRITE) {
            float inv0 = 1.f / g_rowsum[b * LSEQ + row0    ];
            float inv1 = 1.f / g_rowsum[b * LSEQ + row0 + 8];
            #pragma unroll
            for (int j = 0; j < 4; j++) {
                int col = m0 + wn + j * 8 + 2 * tg;
                int mv0 = mrow[col], mv1 = mrow[col + 1];
                float p00 = mv0 ? __expf(acc[i][j][0] * INV_SQRT_DK) : 0.f;
                float p01 = mv1 ? __expf(acc[i][j][1] * INV_SQRT_DK) : 0.f;
                float p10 = mv0 ? __expf(acc[i][j][2] * INV_SQRT_DK) : 0.f;
                float p11 = mv1 ? __expf(acc[i][j][3] * INV_SQRT_DK) : 0.f;
                *(float2*)(out + ((size_t)b * LSEQ + row0    ) * LSEQ + col) =
                    make_float2(p00 * inv0, p01 * inv0);
                *(float2*)(out + ((size_t)b * LSEQ + row0 + 8) * LSEQ + col) =
                    make_float2(p10 * inv1, p11 * inv1);
            }
        } else {
            float rs0 = 0.f, rs1 = 0.f;
            #pragma unroll
            for (int j = 0; j < 4; j++) {
                int col = m0 + wn + j * 8 + 2 * tg;
                int mv0 = mrow[col], mv1 = mrow[col + 1];
                float p00 = mv0 ? __expf(acc[i][j][0] * INV_SQRT_DK) : 0.f;
                float p01 = mv1 ? __expf(acc[i][j][1] * INV_SQRT_DK) : 0.f;
                float p10 = mv0 ? __expf(acc[i][j][2] * INV_SQRT_DK) : 0.f;
                float p11 = mv1 ? __expf(acc[i][j][3] * INV_SQRT_DK) : 0.f;
                rs0 += p00 + p01;
                rs1 += p10 + p11;
            }
            rs0 += __shfl_xor_sync(0xffffffffu, rs0, 1);
            rs0 += __shfl_xor_sync(0xffffffffu, rs0, 2);
            rs1 += __shfl_xor_sync(0xffffffffu, rs1, 1);
            rs1 += __shfl_xor_sync(0xffffffffu, rs1, 2);
            if (tg == 0) {
                atomicAdd(&g_rowsum[b * LSEQ + row0    ], rs0);
                atomicAdd(&g_rowsum[b * LSEQ + row0 + 8], rs1);
            }
        }
    }
}

// ---------------- launch ----------------
extern "C" void kernel_launch(void* const* d_in, const int* in_sizes, int n_in,
                              void* d_out, int out_size)
{
    const float* query   = (const float*)d_in[0];
    const float* key     = (const float*)d_in[1];
    const int*   mask    = (const int*)  d_in[2];
    const float* Wq      = (const float*)d_in[3];
    const float* bq      = (const float*)d_in[4];
    const float* Wk      = (const float*)d_in[5];
    const float* bk      = (const float*)d_in[6];
    const float* qW1     = (const float*)d_in[7];
    const float* qb1     = (const float*)d_in[8];
    const float* qW2     = (const float*)d_in[9];
    const float* qb2     = (const float*)d_in[10];
    const float* kW1     = (const float*)d_in[11];
    const float* kb1     = (const float*)d_in[12];
    const float* kW2     = (const float*)d_in[13];
    const float* kb2     = (const float*)d_in[14];
    const float* q_noise = (const float*)d_in[15];
    const float* k_noise = (const float*)d_in[16];
    float* out = (float*)d_out;

    cudaFuncSetAttribute(proj_tc, cudaFuncAttributeMaxDynamicSharedMemorySize,
                         PROJ_SMEM_BYTES);
    cudaFuncSetAttribute(selector_tc, cudaFuncAttributeMaxDynamicSharedMemorySize,
                         SELG_SMEM_BYTES);

    proj_tc<<<dim3(64, 2), 256, PROJ_SMEM_BYTES>>>(query, key, Wq, bq, Wk, bk);
    fft_fwd_kernel<<<256, FFT_NT>>>();
    selector_tc<<<dim3((FLEN + 63) / 64, BATCH, 2), 256, SELG_SMEM_BYTES>>>(
        qW1, qb1, qW2, qb2, kW1, kb1, kW2, kb2, q_noise, k_noise);
    fft_inv_kernel<<<256, FFT_NT>>>();
    gemm_scores_bf16<0><<<dim3(32, 32, BATCH), 256>>>(out, mask);  // rowsums
    gemm_scores_bf16<1><<<dim3(32, 32, BATCH), 256>>>(out, mask);  // normalized write
}

// round 12
// speedup vs baseline: 6.3627x; 1.0284x over previous
#include <cuda_runtime.h>
#include <cuda_bf16.h>
#include <cstdint>

#define BATCH 2
#define LSEQ 4096
#define DMODEL 768
#define HDIM 128
#define FLEN 2049
#define INV_SQRT_DK 0.08838834764831845f
#define GEPS 1e-9f
#define PI_F 3.14159265358979323846f

// ---------------- scratch ----------------
__device__ float  g_q [BATCH*HDIM*LSEQ];
__device__ float  g_k [BATCH*HDIM*LSEQ];
__device__ float2 g_Qf[BATCH*HDIM*FLEN];
__device__ float2 g_Kf[BATCH*HDIM*FLEN];
__device__ float  g_ReT[2*BATCH*FLEN*HDIM];
__device__ float  g_zq[BATCH*FLEN];
__device__ float  g_zk[BATCH*FLEN];
__device__ __nv_bfloat16 g_qf_bf[BATCH*HDIM*LSEQ];
__device__ __nv_bfloat16 g_kf_bf[BATCH*HDIM*LSEQ];
__device__ float  g_rowsum[BATCH*LSEQ];

__device__ __forceinline__ uint32_t sptr(const void* p) {
    return (uint32_t)__cvta_generic_to_shared(p);
}
__device__ __forceinline__ void cp16(void* smem_dst, const void* gmem_src) {
    asm volatile("cp.async.ca.shared.global [%0], [%1], 16;"
                 :: "r"(sptr(smem_dst)), "l"(gmem_src));
}

// ---------------- projection GEMM: tf32 mma + 3-stage cp.async ----------------
#define PROJ_STAGES 3
#define PROJ_BK 32
#define PROJ_KP 36
#define PROJ_MAT (128 * PROJ_KP)
#define PROJ_SMEM_FLOATS (PROJ_STAGES * PROJ_MAT * 2)
#define PROJ_SMEM_BYTES (PROJ_SMEM_FLOATS * 4)

__global__ __launch_bounds__(256) void proj_tc(
    const float* __restrict__ query, const float* __restrict__ key,
    const float* __restrict__ Wq, const float* __restrict__ bq,
    const float* __restrict__ Wk, const float* __restrict__ bk)
{
    extern __shared__ float dsm[];
    float* Wbase = dsm;
    float* Xbase = dsm + PROJ_STAGES * PROJ_MAT;

    const int tensor = blockIdx.y;
    const float* X  = tensor ? key : query;
    const float* W  = tensor ? Wk  : Wq;
    const float* bi = tensor ? bk  : bq;
    float* dst = tensor ? g_k : g_q;

    const int l0 = blockIdx.x * 128;
    const int tid  = threadIdx.x;
    const int warp = tid >> 5, lane = tid & 31;
    const int g = lane >> 2, tg = lane & 3;
    const int wd = (warp & 1) * 64;
    const int wn = (warp >> 1) * 32;

    float acc[4][4][4];
    #pragma unroll
    for (int i = 0; i < 4; i++)
        #pragma unroll
        for (int j = 0; j < 4; j++)
            #pragma unroll
            for (int c = 0; c < 4; c++) acc[i][j][c] = 0.f;

    auto load_stage = [&](int kc, int st) {
        const int k0 = kc * PROJ_BK;
        float* Ws = Wbase + st * PROJ_MAT;
        float* Xs = Xbase + st * PROJ_MAT;
        #pragma unroll
        for (int it = 0; it < 4; it++) {
            int idx = tid + 256 * it;
            int row = idx >> 3;
            int seg = (idx & 7) << 2;
            cp16(Ws + row * PROJ_KP + seg, W + (size_t)row * DMODEL + k0 + seg);
            cp16(Xs + row * PROJ_KP + seg, X + (size_t)(l0 + row) * DMODEL + k0 + seg);
        }
        asm volatile("cp.async.commit_group;");
    };

    load_stage(0, 0);
    load_stage(1, 1);

    const int NCHUNK = DMODEL / PROJ_BK;
    #pragma unroll 1
    for (int kc = 0; kc < NCHUNK; kc++) {
        const int st = kc % PROJ_STAGES;
        asm volatile("cp.async.wait_group 1;");
        __syncthreads();
        if (kc + 2 < NCHUNK) load_stage(kc + 2, (kc + 2) % PROJ_STAGES);

        const float* Ws = Wbase + st * PROJ_MAT;
        const float* Xs = Xbase + st * PROJ_MAT;

        #pragma unroll
        for (int ks = 0; ks < 4; ks++) {
            const int k = ks * 8;
            uint32_t a[4][4], bf[4][2];
            #pragma unroll
            for (int i = 0; i < 4; i++) {
                int d = wd + i * 16 + g;
                a[i][0] = __float_as_uint(Ws[(d    ) * PROJ_KP + k + tg    ]);
                a[i][1] = __float_as_uint(Ws[(d + 8) * PROJ_KP + k + tg    ]);
                a[i][2] = __float_as_uint(Ws[(d    ) * PROJ_KP + k + tg + 4]);
                a[i][3] = __float_as_uint(Ws[(d + 8) * PROJ_KP + k + tg + 4]);
            }
            #pragma unroll
            for (int j = 0; j < 4; j++) {
                int n = wn + j * 8 + g;
                bf[j][0] = __float_as_uint(Xs[n * PROJ_KP + k + tg    ]);
                bf[j][1] = __float_as_uint(Xs[n * PROJ_KP + k + tg + 4]);
            }
            #pragma unroll
            for (int i = 0; i < 4; i++)
                #pragma unroll
                for (int j = 0; j < 4; j++) {
                    asm volatile(
                        "mma.sync.aligned.m16n8k8.row.col.f32.tf32.tf32.f32 "
                        "{%0,%1,%2,%3},{%4,%5,%6,%7},{%8,%9},{%0,%1,%2,%3};"
                        : "+f"(acc[i][j][0]), "+f"(acc[i][j][1]),
                          "+f"(acc[i][j][2]), "+f"(acc[i][j][3])
                        : "r"(a[i][0]), "r"(a[i][1]), "r"(a[i][2]), "r"(a[i][3]),
                          "r"(bf[j][0]), "r"(bf[j][1]));
                }
        }
        __syncthreads();
    }

    #pragma unroll
    for (int i = 0; i < 4; i++) {
        int d0 = wd + i * 16 + g;
        float bv0 = bi[d0], bv1 = bi[d0 + 8];
        #pragma unroll
        for (int j = 0; j < 4; j++) {
            int gl = l0 + wn + j * 8 + 2 * tg;
            int b  = gl >> 12;
            int l  = gl & 4095;
            float* o0 = dst + (size_t)((b << 7) + d0    ) * LSEQ + l;
            float* o1 = dst + (size_t)((b << 7) + d0 + 8) * LSEQ + l;
            *(float2*)o0 = make_float2(acc[i][j][0] + bv0, acc[i][j][1] + bv0);
            *(float2*)o1 = make_float2(acc[i][j][2] + bv1, acc[i][j][3] + bv1);
        }
    }
}

// ---------------- radix-4 4096-pt FFT ----------------
#define FFT_NT 512
__device__ __forceinline__ void fill_tw(float2* tw, int tid)
{
    for (int j = tid; j < 1024; j += FFT_NT) {
        float ang = -PI_F * (float)j / 2048.0f;
        float s, c;
        __sincosf(ang, &s, &c);
        tw[j] = make_float2(c, s);
    }
}

__device__ __forceinline__ float2 cmul(float2 a, float2 b) {
    return make_float2(a.x*b.x - a.y*b.y, a.x*b.y + a.y*b.x);
}

__device__ __forceinline__ int dr12(int i) {
    unsigned y = __brev((unsigned)i) >> 20;
    return (int)(((y & 0x555u) << 1) | ((y >> 1) & 0x555u));
}

__device__ __forceinline__ void fft4096_r4(float2* s, const float2* tw, int tid, bool inv)
{
    #pragma unroll 1
    for (int st = 0; st < 6; st++) {
        const int twoSt = 2 * st;
        const int L = 1 << twoSt;
        const int shift = 10 - twoSt;
        #pragma unroll
        for (int tt = 0; tt < 1024 / FFT_NT; tt++) {
            int t = tid + tt * FFT_NT;
            int j  = t & (L - 1);
            int i0 = ((t >> twoSt) << (twoSt + 2)) + j;
            int e  = j << shift;
            float2 w1 = tw[e];
            if (inv) w1.y = -w1.y;
            float2 w2 = cmul(w1, w1);
            float2 w3 = cmul(w1, w2);

            float2 u0 = s[i0];
            float2 u1 = cmul(s[i0 + L],   w1);
            float2 u2 = cmul(s[i0 + 2*L], w2);
            float2 u3 = cmul(s[i0 + 3*L], w3);

            float2 v0 = make_float2(u0.x + u2.x, u0.y + u2.y);
            float2 v1 = make_float2(u0.x - u2.x, u0.y - u2.y);
            float2 v2 = make_float2(u1.x + u3.x, u1.y + u3.y);
            float2 v3 = make_float2(u1.x - u3.x, u1.y - u3.y);

            s[i0]       = make_float2(v0.x + v2.x, v0.y + v2.y);
            s[i0 + 2*L] = make_float2(v0.x - v2.x, v0.y - v2.y);
            if (!inv) {
                s[i0 + L]   = make_float2(v1.x + v3.y, v1.y - v3.x);
                s[i0 + 3*L] = make_float2(v1.x - v3.y, v1.y + v3.x);
            } else {
                s[i0 + L]   = make_float2(v1.x - v3.y, v1.y + v3.x);
                s[i0 + 3*L] = make_float2(v1.x + v3.y, v1.y - v3.x);
            }
        }
        __syncthreads();
    }
}

// forward FFT + zero rowsums (first 16 blocks) + freq-major real parts
__global__ __launch_bounds__(FFT_NT) void fft_fwd_kernel()
{
    __shared__ float2 s[4096];
    __shared__ float2 tw[1024];
    const int blk = blockIdx.x;
    const int tensor = blk >> 7;
    const int pr = blk & 127;
    const int b = pr >> 6;
    const int j = pr & 63;
    const int row0 = b * 128 + 2 * j;
    const float* src0 = (tensor ? g_k : g_q) + (size_t)row0 * LSEQ;
    const float* src1 = src0 + LSEQ;
    float2* dst0 = (tensor ? g_Kf : g_Qf) + (size_t)row0 * FLEN;
    float2* dst1 = dst0 + FLEN;
    float* rt = g_ReT + ((size_t)(tensor * BATCH + b) * FLEN) * HDIM;
    const int tid = threadIdx.x;

    if (blk < 16) g_rowsum[blk * FFT_NT + tid] = 0.f;

    fill_tw(tw, tid);
    for (int i = tid; i < 4096; i += FFT_NT) {
        s[dr12(i)] = make_float2(src0[i], src1[i]);
    }
    __syncthreads();
    fft4096_r4(s, tw, tid, false);

    for (int f = tid; f < FLEN; f += FFT_NT) {
        float2 cf = s[f];
        float2 cn = s[(4096 - f) & 4095];
        float re0 = 0.5f * (cf.x + cn.x);
        float re1 = 0.5f * (cf.y + cn.y);
        dst0[f] = make_float2(re0, 0.5f * (cf.y - cn.y));
        dst1[f] = make_float2(re1, 0.5f * (cn.x - cf.x));
        rt[(size_t)f * HDIM + 2 * j    ] = re0;
        rt[(size_t)f * HDIM + 2 * j + 1] = re1;
    }
}

// ---------------- selector: tf32 tensor-core MLP, 64-freq tiles + cp.async ----------------
#define SELG_KP 132
#define SELG_AS (64 * SELG_KP)
#define SELG_BS (64 * SELG_KP)
#define SELG_SMEM_BYTES ((SELG_AS + SELG_BS) * 4)

__global__ __launch_bounds__(256) void selector_tc(
    const float* __restrict__ qW1, const float* __restrict__ qb1,
    const float* __restrict__ qW2, const float* __restrict__ qb2,
    const float* __restrict__ kW1, const float* __restrict__ kb1,
    const float* __restrict__ kW2, const float* __restrict__ kb2,
    const float* __restrict__ q_noise, const float* __restrict__ k_noise)
{
    extern __shared__ float ssm[];
    float* As  = ssm;
    float* Bs  = ssm + SELG_AS;
    float* h1s = ssm;
    __shared__ float lgs[64][2];

    const int tile = blockIdx.x;
    const int b = blockIdx.y;
    const int tensor = blockIdx.z;
    const int f0 = tile * 64;
    const float* ReT = g_ReT + ((size_t)(tensor * BATCH + b) * FLEN) * HDIM;
    const float* W1 = tensor ? kW1 : qW1;
    const float* b1 = tensor ? kb1 : qb1;
    const float* W2 = tensor ? kW2 : qW2;
    const float* b2 = tensor ? kb2 : qb2;
    const float* nz = tensor ? k_noise : q_noise;
    float* z = tensor ? g_zk : g_zq;

    const int tid  = threadIdx.x;
    const int warp = tid >> 5, lane = tid & 31;
    const int g = lane >> 2, tg = lane & 3;
    const int wu = (warp & 1) * 32;
    const int wf = (warp >> 1) * 16;

    #pragma unroll
    for (int it = 0; it < 8; it++) {
        int idx = tid + 256 * it;
        int row = idx >> 5;
        int seg = (idx & 31) << 2;
        cp16(As + row * SELG_KP + seg, W1 + row * 128 + seg);
        int f = f0 + row;
        if (f < FLEN) {
            cp16(Bs + row * SELG_KP + seg, ReT + (size_t)f * HDIM + seg);
        } else {
            *(float4*)(Bs + row * SELG_KP + seg) = make_float4(0.f, 0.f, 0.f, 0.f);
        }
    }
    asm volatile("cp.async.commit_group;");
    asm volatile("cp.async.wait_group 0;");
    __syncthreads();

    float acc[2][2][4];
    #pragma unroll
    for (int i = 0; i < 2; i++)
        #pragma unroll
        for (int j = 0; j < 2; j++)
            #pragma unroll
            for (int c = 0; c < 4; c++) acc[i][j][c] = 0.f;

    #pragma unroll
    for (int ks = 0; ks < 16; ks++) {
        const int k = ks * 8;
        uint32_t a[2][4], bf[2][2];
        #pragma unroll
        for (int i = 0; i < 2; i++) {
            int u = wu + i * 16 + g;
            a[i][0] = __float_as_uint(As[(u    ) * SELG_KP + k + tg    ]);
            a[i][1] = __float_as_uint(As[(u + 8) * SELG_KP + k + tg    ]);
            a[i][2] = __float_as_uint(As[(u    ) * SELG_KP + k + tg + 4]);
            a[i][3] = __float_as_uint(As[(u + 8) * SELG_KP + k + tg + 4]);
        }
        #pragma unroll
        for (int j = 0; j < 2; j++) {
            int n = wf + j * 8 + g;
            bf[j][0] = __float_as_uint(Bs[n * SELG_KP + k + tg    ]);
            bf[j][1] = __float_as_uint(Bs[n * SELG_KP + k + tg + 4]);
        }
        #pragma unroll
        for (int i = 0; i < 2; i++)
            #pragma unroll
            for (int j = 0; j < 2; j++) {
                asm volatile(
                    "mma.sync.aligned.m16n8k8.row.col.f32.tf32.tf32.f32 "
                    "{%0,%1,%2,%3},{%4,%5,%6,%7},{%8,%9},{%0,%1,%2,%3};"
                    : "+f"(acc[i][j][0]), "+f"(acc[i][j][1]),
                      "+f"(acc[i][j][2]), "+f"(acc[i][j][3])
                    : "r"(a[i][0]), "r"(a[i][1]), "r"(a[i][2]), "r"(a[i][3]),
                      "r"(bf[j][0]), "r"(bf[j][1]));
            }
    }
    __syncthreads();

    #pragma unroll
    for (int i = 0; i < 2; i++) {
        int u0 = wu + i * 16 + g;
        float bv0 = b1[u0], bv1 = b1[u0 + 8];
        #pragma unroll
        for (int j = 0; j < 2; j++) {
            int f = wf + j * 8 + 2 * tg;
            h1s[(f    ) * 65 + u0    ] = fmaxf(acc[i][j][0] + bv0, 0.f);
            h1s[(f + 1) * 65 + u0    ] = fmaxf(acc[i][j][1] + bv0, 0.f);
            h1s[(f    ) * 65 + u0 + 8] = fmaxf(acc[i][j][2] + bv1, 0.f);
            h1s[(f + 1) * 65 + u0 + 8] = fmaxf(acc[i][j][3] + bv1, 0.f);
        }
    }
    __syncthreads();

    if (tid < 128) {
        int fl = tid >> 1, c = tid & 1;
        int f = f0 + fl;
        if (f < FLEN) {
            float acc2 = b2[c];
            const float* w2 = W2 + c * 64;
            const float* h = h1s + fl * 65;
            #pragma unroll 16
            for (int u = 0; u < 64; u++) acc2 = fmaf(h[u], w2[u], acc2);
            float n = nz[((size_t)b * FLEN + f) * 2 + c];
            lgs[fl][c] = acc2 + (-logf(-logf(n + GEPS) + GEPS));
        }
    }
    __syncthreads();
    if (tid < 64) {
        int f = f0 + tid;
        if (f < FLEN) z[b * FLEN + f] = 1.f / (1.f + expf(lgs[tid][0] - lgs[tid][1]));
    }
}

// inverse FFT; store bf16.
__global__ __launch_bounds__(FFT_NT) void fft_inv_kernel()
{
    __shared__ float2 s[4096];
    __shared__ float2 tw[1024];
    const int blk = blockIdx.x;
    const int tensor = blk >> 7;
    const int pr = blk & 127;
    const int b = pr >> 6;
    const int j = pr & 63;
    const int row0 = b * 128 + 2 * j;
    const float2* src0 = (tensor ? g_Kf : g_Qf) + (size_t)row0 * FLEN;
    const float2* src1 = src0 + FLEN;
    const float* z = (tensor ? g_zk : g_zq) + (size_t)b * FLEN;
    __nv_bfloat16* dst0 = (tensor ? g_kf_bf : g_qf_bf) + (size_t)row0 * LSEQ;
    __nv_bfloat16* dst1 = dst0 + LSEQ;
    const int tid = threadIdx.x;

    fill_tw(tw, tid);
    for (int i = tid; i < 4096; i += FFT_NT) {
        int f = (i <= 2048) ? i : (4096 - i);
        float zz = z[f];
        float2 a = src0[f];
        float2 bb = src1[f];
        if (i > 2048) { a.y = -a.y; bb.y = -bb.y; }
        a.x *= zz; a.y *= zz; bb.x *= zz; bb.y *= zz;
        s[dr12(i)] = make_float2(a.x - bb.y, a.y + bb.x);
    }
    __syncthreads();
    fft4096_r4(s, tw, tid, true);
    const float inv = 1.f / 4096.f;
    for (int i = tid; i < 4096; i += FFT_NT) {
        float2 v = s[i];
        dst0[i] = __float2bfloat16(v.x * inv);
        dst1[i] = __float2bfloat16(v.y * inv);
    }
}

// ---------------- scores GEMM: single-stage full-K smem, 2 passes ----------------
// smem: Qs[128][136] + Ks[128][136] bf16 = 68 KB (dynamic)
#define GSK 136
#define GS_Q 0
#define GS_K (128 * GSK)
#define GEMM_SMEM_BYTES (2 * 128 * GSK * 2)

template<int WRITE>
__global__ __launch_bounds__(256) void gemm_scores_bf16(float* __restrict__ out,
                                                        const int* __restrict__ mask)
{
    extern __shared__ __nv_bfloat16 gsm[];
    __nv_bfloat16* Qs = gsm + GS_Q;   // [k][l] stride 136
    __nv_bfloat16* Ks = gsm + GS_K;   // [k][m] stride 136

    const int b  = blockIdx.z;
    const int l0 = blockIdx.y * 128;
    const int m0 = blockIdx.x * 128;
    const __nv_bfloat16* A  = g_qf_bf + (size_t)b * HDIM * LSEQ;
    const __nv_bfloat16* Bm = g_kf_bf + (size_t)b * HDIM * LSEQ;
    const int* mrow = mask + (size_t)b * LSEQ;

    const int tid  = threadIdx.x;
    const int warp = tid >> 5, lane = tid & 31;
    const int g = lane >> 2, tg = lane & 3;
    const int wl = (warp & 1) * 64;
    const int wn = (warp >> 1) * 32;

    const int lr   = lane & 7;
    const int koff = lr + ((lane & 16) ? 8 : 0);
    const int coff = (lane & 8) ? 8 : 0;
    const int kb   = lr + ((lane & 8) ? 8 : 0);
    const int cb   = (lane & 16) ? 8 : 0;

    // stage all K=128 rows of both tiles, one group, one wait
    #pragma unroll
    for (int it = 0; it < 8; it++) {
        int idx = tid + 256 * it;           // 0..2047
        int k  = idx >> 4;                  // 0..127
        int c8 = (idx & 15) << 3;           // 0..120
        cp16(Qs + k * GSK + c8, A  + (size_t)k * LSEQ + l0 + c8);
        cp16(Ks + k * GSK + c8, Bm + (size_t)k * LSEQ + m0 + c8);
    }
    asm volatile("cp.async.commit_group;");

    float acc[4][4][4];
    #pragma unroll
    for (int i = 0; i < 4; i++)
        #pragma unroll
        for (int j = 0; j < 4; j++)
            #pragma unroll
            for (int c = 0; c < 4; c++) acc[i][j][c] = 0.f;

    asm volatile("cp.async.wait_group 0;");
    __syncthreads();

    #pragma unroll
    for (int ks = 0; ks < 8; ks++) {
        const int k0 = ks * 16;
        uint32_t a[4][4];
        #pragma unroll
        for (int i = 0; i < 4; i++) {
            uint32_t addr = sptr(Qs + (k0 + koff) * GSK + wl + 16 * i + coff);
            asm volatile(
                "ldmatrix.sync.aligned.m8n8.x4.trans.shared.b16 {%0,%1,%2,%3}, [%4];"
                : "=r"(a[i][0]), "=r"(a[i][1]), "=r"(a[i][2]), "=r"(a[i][3])
                : "r"(addr));
        }
        uint32_t bfr[2][4];
        #pragma unroll
        for (int jj = 0; jj < 2; jj++) {
            uint32_t addr = sptr(Ks + (k0 + kb) * GSK + wn + 16 * jj + cb);
            asm volatile(
                "ldmatrix.sync.aligned.m8n8.x4.trans.shared.b16 {%0,%1,%2,%3}, [%4];"
                : "=r"(bfr[jj][0]), "=r"(bfr[jj][1]), "=r"(bfr[jj][2]), "=r"(bfr[jj][3])
                : "r"(addr));
        }
        #pragma unroll
        for (int i = 0; i < 4; i++)
            #pragma unroll
            for (int j = 0; j < 4; j++) {
                uint32_t b0 = bfr[j >> 1][2 * (j & 1)];
                uint32_t b1 = bfr[j >> 1][2 * (j & 1) + 1];
                asm volatile(
                    "mma.sync.aligned.m16n8k16.row.col.f32.bf16.bf16.f32 "
                    "{%0,%1,%2,%3},{%4,%5,%6,%7},{%8,%9},{%0,%1,%2,%3};"
                    : "+f"(acc[i][j][0]), "+f"(acc[i][j][1]),
                      "+f"(acc[i][j][2]), "+f"(acc[i][j][3])
                    : "r"(a[i][0]), "r"(a[i][1]), "r"(a[i][2]), "r"(a[i][3]),
                      "r"(b0), "r"(b1));
            }
    }

    #pragma unroll
    for (int i = 0; i < 4; i++) {
        int row0 = l0 + wl + i * 16 + g;
        if (WRITE) {
            float inv0 = 1.f / g_rowsum[b * LSEQ + row0    ];
            float inv1 = 1.f / g_rowsum[b * LSEQ + row0 + 8];
            #pragma unroll
            for (int j = 0; j < 4; j++) {
                int col = m0 + wn + j * 8 + 2 * tg;
                int mv0 = mrow[col], mv1 = mrow[col + 1];
                float p00 = mv0 ? __expf(acc[i][j][0] * INV_SQRT_DK) : 0.f;
                float p01 = mv1 ? __expf(acc[i][j][1] * INV_SQRT_DK) : 0.f;
                float p10 = mv0 ? __expf(acc[i][j][2] * INV_SQRT_DK) : 0.f;
                float p11 = mv1 ? __expf(acc[i][j][3] * INV_SQRT_DK) : 0.f;
                *(float2*)(out + ((size_t)b * LSEQ + row0    ) * LSEQ + col) =
                    make_float2(p00 * inv0, p01 * inv0);
                *(float2*)(out + ((size_t)b * LSEQ + row0 + 8) * LSEQ + col) =
                    make_float2(p10 * inv1, p11 * inv1);
            }
        } else {
            float rs0 = 0.f, rs1 = 0.f;
            #pragma unroll
            for (int j = 0; j < 4; j++) {
                int col = m0 + wn + j * 8 + 2 * tg;
                int mv0 = mrow[col], mv1 = mrow[col + 1];
                float p00 = mv0 ? __expf(acc[i][j][0] * INV_SQRT_DK) : 0.f;
                float p01 = mv1 ? __expf(acc[i][j][1] * INV_SQRT_DK) : 0.f;
                float p10 = mv0 ? __expf(acc[i][j][2] * INV_SQRT_DK) : 0.f;
                float p11 = mv1 ? __expf(acc[i][j][3] * INV_SQRT_DK) : 0.f;
                rs0 += p00 + p01;
                rs1 += p10 + p11;
            }
            rs0 += __shfl_xor_sync(0xffffffffu, rs0, 1);
            rs0 += __shfl_xor_sync(0xffffffffu, rs0, 2);
            rs1 += __shfl_xor_sync(0xffffffffu, rs1, 1);
            rs1 += __shfl_xor_sync(0xffffffffu, rs1, 2);
            if (tg == 0) {
                atomicAdd(&g_rowsum[b * LSEQ + row0    ], rs0);
                atomicAdd(&g_rowsum[b * LSEQ + row0 + 8], rs1);
            }
        }
    }
}

// ---------------- launch ----------------
extern "C" void kernel_launch(void* const* d_in, const int* in_sizes, int n_in,
                              void* d_out, int out_size)
{
    const float* query   = (const float*)d_in[0];
    const float* key     = (const float*)d_in[1];
    const int*   mask    = (const int*)  d_in[2];
    const float* Wq      = (const float*)d_in[3];
    const float* bq      = (const float*)d_in[4];
    const float* Wk      = (const float*)d_in[5];
    const float* bk      = (const float*)d_in[6];
    const float* qW1     = (const float*)d_in[7];
    const float* qb1     = (const float*)d_in[8];
    const float* qW2     = (const float*)d_in[9];
    const float* qb2     = (const float*)d_in[10];
    const float* kW1     = (const float*)d_in[11];
    const float* kb1     = (const float*)d_in[12];
    const float* kW2     = (const float*)d_in[13];
    const float* kb2     = (const float*)d_in[14];
    const float* q_noise = (const float*)d_in[15];
    const float* k_noise = (const float*)d_in[16];
    float* out = (float*)d_out;

    cudaFuncSetAttribute(proj_tc, cudaFuncAttributeMaxDynamicSharedMemorySize,
                         PROJ_SMEM_BYTES);
    cudaFuncSetAttribute(selector_tc, cudaFuncAttributeMaxDynamicSharedMemorySize,
                         SELG_SMEM_BYTES);
    cudaFuncSetAttribute(gemm_scores_bf16<0>, cudaFuncAttributeMaxDynamicSharedMemorySize,
                         GEMM_SMEM_BYTES);
    cudaFuncSetAttribute(gemm_scores_bf16<1>, cudaFuncAttributeMaxDynamicSharedMemorySize,
                         GEMM_SMEM_BYTES);

    proj_tc<<<dim3(64, 2), 256, PROJ_SMEM_BYTES>>>(query, key, Wq, bq, Wk, bk);
    fft_fwd_kernel<<<256, FFT_NT>>>();
    selector_tc<<<dim3((FLEN + 63) / 64, BATCH, 2), 256, SELG_SMEM_BYTES>>>(
        qW1, qb1, qW2, qb2, kW1, kb1, kW2, kb2, q_noise, k_noise);
    fft_inv_kernel<<<256, FFT_NT>>>();
    gemm_scores_bf16<0><<<dim3(32, 32, BATCH), 256, GEMM_SMEM_BYTES>>>(out, mask);
    gemm_scores_bf16<1><<<dim3(32, 32, BATCH), 256, GEMM_SMEM_BYTES>>>(out, mask);
}

// round 13
// speedup vs baseline: 6.3649x; 1.0004x over previous
#include <cuda_runtime.h>
#include <cuda_bf16.h>
#include <cstdint>

#define BATCH 2
#define LSEQ 4096
#define DMODEL 768
#define HDIM 128
#define FLEN 2049
#define INV_SQRT_DK 0.08838834764831845f
#define GEPS 1e-9f
#define PI_F 3.14159265358979323846f

// ---------------- scratch ----------------
__device__ float  g_q [BATCH*HDIM*LSEQ];
__device__ float  g_k [BATCH*HDIM*LSEQ];
__device__ float2 g_Qf[BATCH*HDIM*FLEN];
__device__ float2 g_Kf[BATCH*HDIM*FLEN];
__device__ float  g_ReT[2*BATCH*FLEN*HDIM];
__device__ float  g_zq[BATCH*FLEN];
__device__ float  g_zk[BATCH*FLEN];
__device__ __nv_bfloat16 g_qf_bf[BATCH*HDIM*LSEQ];
__device__ __nv_bfloat16 g_kf_bf[BATCH*HDIM*LSEQ];
__device__ float  g_rowsum[BATCH*LSEQ];

__device__ __forceinline__ uint32_t sptr(const void* p) {
    return (uint32_t)__cvta_generic_to_shared(p);
}
__device__ __forceinline__ void cp16(void* smem_dst, const void* gmem_src) {
    asm volatile("cp.async.ca.shared.global [%0], [%1], 16;"
                 :: "r"(sptr(smem_dst)), "l"(gmem_src));
}

// ---------------- projection GEMM: tf32 mma + 3-stage cp.async ----------------
#define PROJ_STAGES 3
#define PROJ_BK 32
#define PROJ_KP 36
#define PROJ_MAT (128 * PROJ_KP)
#define PROJ_SMEM_FLOATS (PROJ_STAGES * PROJ_MAT * 2)
#define PROJ_SMEM_BYTES (PROJ_SMEM_FLOATS * 4)

__global__ __launch_bounds__(256) void proj_tc(
    const float* __restrict__ query, const float* __restrict__ key,
    const float* __restrict__ Wq, const float* __restrict__ bq,
    const float* __restrict__ Wk, const float* __restrict__ bk)
{
    extern __shared__ float dsm[];
    float* Wbase = dsm;
    float* Xbase = dsm + PROJ_STAGES * PROJ_MAT;

    const int tensor = blockIdx.y;
    const float* X  = tensor ? key : query;
    const float* W  = tensor ? Wk  : Wq;
    const float* bi = tensor ? bk  : bq;
    float* dst = tensor ? g_k : g_q;

    const int l0 = blockIdx.x * 128;
    const int tid  = threadIdx.x;
    const int warp = tid >> 5, lane = tid & 31;
    const int g = lane >> 2, tg = lane & 3;
    const int wd = (warp & 1) * 64;
    const int wn = (warp >> 1) * 32;

    float acc[4][4][4];
    #pragma unroll
    for (int i = 0; i < 4; i++)
        #pragma unroll
        for (int j = 0; j < 4; j++)
            #pragma unroll
            for (int c = 0; c < 4; c++) acc[i][j][c] = 0.f;

    auto load_stage = [&](int kc, int st) {
        const int k0 = kc * PROJ_BK;
        float* Ws = Wbase + st * PROJ_MAT;
        float* Xs = Xbase + st * PROJ_MAT;
        #pragma unroll
        for (int it = 0; it < 4; it++) {
            int idx = tid + 256 * it;
            int row = idx >> 3;
            int seg = (idx & 7) << 2;
            cp16(Ws + row * PROJ_KP + seg, W + (size_t)row * DMODEL + k0 + seg);
            cp16(Xs + row * PROJ_KP + seg, X + (size_t)(l0 + row) * DMODEL + k0 + seg);
        }
        asm volatile("cp.async.commit_group;");
    };

    load_stage(0, 0);
    load_stage(1, 1);

    const int NCHUNK = DMODEL / PROJ_BK;
    #pragma unroll 1
    for (int kc = 0; kc < NCHUNK; kc++) {
        const int st = kc % PROJ_STAGES;
        asm volatile("cp.async.wait_group 1;");
        __syncthreads();
        if (kc + 2 < NCHUNK) load_stage(kc + 2, (kc + 2) % PROJ_STAGES);

        const float* Ws = Wbase + st * PROJ_MAT;
        const float* Xs = Xbase + st * PROJ_MAT;

        #pragma unroll
        for (int ks = 0; ks < 4; ks++) {
            const int k = ks * 8;
            uint32_t a[4][4], bf[4][2];
            #pragma unroll
            for (int i = 0; i < 4; i++) {
                int d = wd + i * 16 + g;
                a[i][0] = __float_as_uint(Ws[(d    ) * PROJ_KP + k + tg    ]);
                a[i][1] = __float_as_uint(Ws[(d + 8) * PROJ_KP + k + tg    ]);
                a[i][2] = __float_as_uint(Ws[(d    ) * PROJ_KP + k + tg + 4]);
                a[i][3] = __float_as_uint(Ws[(d + 8) * PROJ_KP + k + tg + 4]);
            }
            #pragma unroll
            for (int j = 0; j < 4; j++) {
                int n = wn + j * 8 + g;
                bf[j][0] = __float_as_uint(Xs[n * PROJ_KP + k + tg    ]);
                bf[j][1] = __float_as_uint(Xs[n * PROJ_KP + k + tg + 4]);
            }
            #pragma unroll
            for (int i = 0; i < 4; i++)
                #pragma unroll
                for (int j = 0; j < 4; j++) {
                    asm volatile(
                        "mma.sync.aligned.m16n8k8.row.col.f32.tf32.tf32.f32 "
                        "{%0,%1,%2,%3},{%4,%5,%6,%7},{%8,%9},{%0,%1,%2,%3};"
                        : "+f"(acc[i][j][0]), "+f"(acc[i][j][1]),
                          "+f"(acc[i][j][2]), "+f"(acc[i][j][3])
                        : "r"(a[i][0]), "r"(a[i][1]), "r"(a[i][2]), "r"(a[i][3]),
                          "r"(bf[j][0]), "r"(bf[j][1]));
                }
        }
        __syncthreads();
    }

    #pragma unroll
    for (int i = 0; i < 4; i++) {
        int d0 = wd + i * 16 + g;
        float bv0 = bi[d0], bv1 = bi[d0 + 8];
        #pragma unroll
        for (int j = 0; j < 4; j++) {
            int gl = l0 + wn + j * 8 + 2 * tg;
            int b  = gl >> 12;
            int l  = gl & 4095;
            float* o0 = dst + (size_t)((b << 7) + d0    ) * LSEQ + l;
            float* o1 = dst + (size_t)((b << 7) + d0 + 8) * LSEQ + l;
            *(float2*)o0 = make_float2(acc[i][j][0] + bv0, acc[i][j][1] + bv0);
            *(float2*)o1 = make_float2(acc[i][j][2] + bv1, acc[i][j][3] + bv1);
        }
    }
}

// ---------------- radix-4 4096-pt FFT ----------------
#define FFT_NT 512
__device__ __forceinline__ void fill_tw(float2* tw, int tid)
{
    for (int j = tid; j < 1024; j += FFT_NT) {
        float ang = -PI_F * (float)j / 2048.0f;
        float s, c;
        __sincosf(ang, &s, &c);
        tw[j] = make_float2(c, s);
    }
}

__device__ __forceinline__ float2 cmul(float2 a, float2 b) {
    return make_float2(a.x*b.x - a.y*b.y, a.x*b.y + a.y*b.x);
}

__device__ __forceinline__ int dr12(int i) {
    unsigned y = __brev((unsigned)i) >> 20;
    return (int)(((y & 0x555u) << 1) | ((y >> 1) & 0x555u));
}

__device__ __forceinline__ void fft4096_r4(float2* s, const float2* tw, int tid, bool inv)
{
    #pragma unroll 1
    for (int st = 0; st < 6; st++) {
        const int twoSt = 2 * st;
        const int L = 1 << twoSt;
        const int shift = 10 - twoSt;
        #pragma unroll
        for (int tt = 0; tt < 1024 / FFT_NT; tt++) {
            int t = tid + tt * FFT_NT;
            int j  = t & (L - 1);
            int i0 = ((t >> twoSt) << (twoSt + 2)) + j;
            int e  = j << shift;
            float2 w1 = tw[e];
            if (inv) w1.y = -w1.y;
            float2 w2 = cmul(w1, w1);
            float2 w3 = cmul(w1, w2);

            float2 u0 = s[i0];
            float2 u1 = cmul(s[i0 + L],   w1);
            float2 u2 = cmul(s[i0 + 2*L], w2);
            float2 u3 = cmul(s[i0 + 3*L], w3);

            float2 v0 = make_float2(u0.x + u2.x, u0.y + u2.y);
            float2 v1 = make_float2(u0.x - u2.x, u0.y - u2.y);
            float2 v2 = make_float2(u1.x + u3.x, u1.y + u3.y);
            float2 v3 = make_float2(u1.x - u3.x, u1.y - u3.y);

            s[i0]       = make_float2(v0.x + v2.x, v0.y + v2.y);
            s[i0 + 2*L] = make_float2(v0.x - v2.x, v0.y - v2.y);
            if (!inv) {
                s[i0 + L]   = make_float2(v1.x + v3.y, v1.y - v3.x);
                s[i0 + 3*L] = make_float2(v1.x - v3.y, v1.y + v3.x);
            } else {
                s[i0 + L]   = make_float2(v1.x - v3.y, v1.y + v3.x);
                s[i0 + 3*L] = make_float2(v1.x + v3.y, v1.y - v3.x);
            }
        }
        __syncthreads();
    }
}

// forward FFT + zero rowsums (first 16 blocks) + freq-major real parts
__global__ __launch_bounds__(FFT_NT) void fft_fwd_kernel()
{
    __shared__ float2 s[4096];
    __shared__ float2 tw[1024];
    const int blk = blockIdx.x;
    const int tensor = blk >> 7;
    const int pr = blk & 127;
    const int b = pr >> 6;
    const int j = pr & 63;
    const int row0 = b * 128 + 2 * j;
    const float* src0 = (tensor ? g_k : g_q) + (size_t)row0 * LSEQ;
    const float* src1 = src0 + LSEQ;
    float2* dst0 = (tensor ? g_Kf : g_Qf) + (size_t)row0 * FLEN;
    float2* dst1 = dst0 + FLEN;
    float* rt = g_ReT + ((size_t)(tensor * BATCH + b) * FLEN) * HDIM;
    const int tid = threadIdx.x;

    if (blk < 16) g_rowsum[blk * FFT_NT + tid] = 0.f;

    fill_tw(tw, tid);
    for (int i = tid; i < 4096; i += FFT_NT) {
        s[dr12(i)] = make_float2(src0[i], src1[i]);
    }
    __syncthreads();
    fft4096_r4(s, tw, tid, false);

    for (int f = tid; f < FLEN; f += FFT_NT) {
        float2 cf = s[f];
        float2 cn = s[(4096 - f) & 4095];
        float re0 = 0.5f * (cf.x + cn.x);
        float re1 = 0.5f * (cf.y + cn.y);
        dst0[f] = make_float2(re0, 0.5f * (cf.y - cn.y));
        dst1[f] = make_float2(re1, 0.5f * (cn.x - cf.x));
        rt[(size_t)f * HDIM + 2 * j    ] = re0;
        rt[(size_t)f * HDIM + 2 * j + 1] = re1;
    }
}

// ---------------- selector: tf32 tensor-core MLP, 64-freq tiles + cp.async ----------------
#define SELG_KP 132
#define SELG_AS (64 * SELG_KP)
#define SELG_BS (64 * SELG_KP)
#define SELG_SMEM_BYTES ((SELG_AS + SELG_BS) * 4)

__global__ __launch_bounds__(256) void selector_tc(
    const float* __restrict__ qW1, const float* __restrict__ qb1,
    const float* __restrict__ qW2, const float* __restrict__ qb2,
    const float* __restrict__ kW1, const float* __restrict__ kb1,
    const float* __restrict__ kW2, const float* __restrict__ kb2,
    const float* __restrict__ q_noise, const float* __restrict__ k_noise)
{
    extern __shared__ float ssm[];
    float* As  = ssm;
    float* Bs  = ssm + SELG_AS;
    float* h1s = ssm;
    __shared__ float lgs[64][2];

    const int tile = blockIdx.x;
    const int b = blockIdx.y;
    const int tensor = blockIdx.z;
    const int f0 = tile * 64;
    const float* ReT = g_ReT + ((size_t)(tensor * BATCH + b) * FLEN) * HDIM;
    const float* W1 = tensor ? kW1 : qW1;
    const float* b1 = tensor ? kb1 : qb1;
    const float* W2 = tensor ? kW2 : qW2;
    const float* b2 = tensor ? kb2 : qb2;
    const float* nz = tensor ? k_noise : q_noise;
    float* z = tensor ? g_zk : g_zq;

    const int tid  = threadIdx.x;
    const int warp = tid >> 5, lane = tid & 31;
    const int g = lane >> 2, tg = lane & 3;
    const int wu = (warp & 1) * 32;
    const int wf = (warp >> 1) * 16;

    #pragma unroll
    for (int it = 0; it < 8; it++) {
        int idx = tid + 256 * it;
        int row = idx >> 5;
        int seg = (idx & 31) << 2;
        cp16(As + row * SELG_KP + seg, W1 + row * 128 + seg);
        int f = f0 + row;
        if (f < FLEN) {
            cp16(Bs + row * SELG_KP + seg, ReT + (size_t)f * HDIM + seg);
        } else {
            *(float4*)(Bs + row * SELG_KP + seg) = make_float4(0.f, 0.f, 0.f, 0.f);
        }
    }
    asm volatile("cp.async.commit_group;");
    asm volatile("cp.async.wait_group 0;");
    __syncthreads();

    float acc[2][2][4];
    #pragma unroll
    for (int i = 0; i < 2; i++)
        #pragma unroll
        for (int j = 0; j < 2; j++)
            #pragma unroll
            for (int c = 0; c < 4; c++) acc[i][j][c] = 0.f;

    #pragma unroll
    for (int ks = 0; ks < 16; ks++) {
        const int k = ks * 8;
        uint32_t a[2][4], bf[2][2];
        #pragma unroll
        for (int i = 0; i < 2; i++) {
            int u = wu + i * 16 + g;
            a[i][0] = __float_as_uint(As[(u    ) * SELG_KP + k + tg    ]);
            a[i][1] = __float_as_uint(As[(u + 8) * SELG_KP + k + tg    ]);
            a[i][2] = __float_as_uint(As[(u    ) * SELG_KP + k + tg + 4]);
            a[i][3] = __float_as_uint(As[(u + 8) * SELG_KP + k + tg + 4]);
        }
        #pragma unroll
        for (int j = 0; j < 2; j++) {
            int n = wf + j * 8 + g;
            bf[j][0] = __float_as_uint(Bs[n * SELG_KP + k + tg    ]);
            bf[j][1] = __float_as_uint(Bs[n * SELG_KP + k + tg + 4]);
        }
        #pragma unroll
        for (int i = 0; i < 2; i++)
            #pragma unroll
            for (int j = 0; j < 2; j++) {
                asm volatile(
                    "mma.sync.aligned.m16n8k8.row.col.f32.tf32.tf32.f32 "
                    "{%0,%1,%2,%3},{%4,%5,%6,%7},{%8,%9},{%0,%1,%2,%3};"
                    : "+f"(acc[i][j][0]), "+f"(acc[i][j][1]),
                      "+f"(acc[i][j][2]), "+f"(acc[i][j][3])
                    : "r"(a[i][0]), "r"(a[i][1]), "r"(a[i][2]), "r"(a[i][3]),
                      "r"(bf[j][0]), "r"(bf[j][1]));
            }
    }
    __syncthreads();

    #pragma unroll
    for (int i = 0; i < 2; i++) {
        int u0 = wu + i * 16 + g;
        float bv0 = b1[u0], bv1 = b1[u0 + 8];
        #pragma unroll
        for (int j = 0; j < 2; j++) {
            int f = wf + j * 8 + 2 * tg;
            h1s[(f    ) * 65 + u0    ] = fmaxf(acc[i][j][0] + bv0, 0.f);
            h1s[(f + 1) * 65 + u0    ] = fmaxf(acc[i][j][1] + bv0, 0.f);
            h1s[(f    ) * 65 + u0 + 8] = fmaxf(acc[i][j][2] + bv1, 0.f);
            h1s[(f + 1) * 65 + u0 + 8] = fmaxf(acc[i][j][3] + bv1, 0.f);
        }
    }
    __syncthreads();

    if (tid < 128) {
        int fl = tid >> 1, c = tid & 1;
        int f = f0 + fl;
        if (f < FLEN) {
            float acc2 = b2[c];
            const float* w2 = W2 + c * 64;
            const float* h = h1s + fl * 65;
            #pragma unroll 16
            for (int u = 0; u < 64; u++) acc2 = fmaf(h[u], w2[u], acc2);
            float n = nz[((size_t)b * FLEN + f) * 2 + c];
            lgs[fl][c] = acc2 + (-logf(-logf(n + GEPS) + GEPS));
        }
    }
    __syncthreads();
    if (tid < 64) {
        int f = f0 + tid;
        if (f < FLEN) z[b * FLEN + f] = 1.f / (1.f + expf(lgs[tid][0] - lgs[tid][1]));
    }
}

// inverse FFT; store bf16.
__global__ __launch_bounds__(FFT_NT) void fft_inv_kernel()
{
    __shared__ float2 s[4096];
    __shared__ float2 tw[1024];
    const int blk = blockIdx.x;
    const int tensor = blk >> 7;
    const int pr = blk & 127;
    const int b = pr >> 6;
    const int j = pr & 63;
    const int row0 = b * 128 + 2 * j;
    const float2* src0 = (tensor ? g_Kf : g_Qf) + (size_t)row0 * FLEN;
    const float2* src1 = src0 + FLEN;
    const float* z = (tensor ? g_zk : g_zq) + (size_t)b * FLEN;
    __nv_bfloat16* dst0 = (tensor ? g_kf_bf : g_qf_bf) + (size_t)row0 * LSEQ;
    __nv_bfloat16* dst1 = dst0 + LSEQ;
    const int tid = threadIdx.x;

    fill_tw(tw, tid);
    for (int i = tid; i < 4096; i += FFT_NT) {
        int f = (i <= 2048) ? i : (4096 - i);
        float zz = z[f];
        float2 a = src0[f];
        float2 bb = src1[f];
        if (i > 2048) { a.y = -a.y; bb.y = -bb.y; }
        a.x *= zz; a.y *= zz; bb.x *= zz; bb.y *= zz;
        s[dr12(i)] = make_float2(a.x - bb.y, a.y + bb.x);
    }
    __syncthreads();
    fft4096_r4(s, tw, tid, true);
    const float inv = 1.f / 4096.f;
    for (int i = tid; i < 4096; i += FFT_NT) {
        float2 v = s[i];
        dst0[i] = __float2bfloat16(v.x * inv);
        dst1[i] = __float2bfloat16(v.y * inv);
    }
}

// ---------------- scores GEMM: single-stage full-K smem, 2 passes ----------------
// smem: Qs[128][136] + Ks[128][136] bf16 = 68 KB (dynamic)
#define GSK 136
#define GS_Q 0
#define GS_K (128 * GSK)
#define GEMM_SMEM_BYTES (2 * 128 * GSK * 2)

template<int WRITE>
__global__ __launch_bounds__(256) void gemm_scores_bf16(float* __restrict__ out,
                                                        const int* __restrict__ mask)
{
    extern __shared__ __nv_bfloat16 gsm[];
    __nv_bfloat16* Qs = gsm + GS_Q;   // [k][l] stride 136
    __nv_bfloat16* Ks = gsm + GS_K;   // [k][m] stride 136

    const int b  = blockIdx.z;
    const int l0 = blockIdx.y * 128;
    const int m0 = blockIdx.x * 128;
    const __nv_bfloat16* A  = g_qf_bf + (size_t)b * HDIM * LSEQ;
    const __nv_bfloat16* Bm = g_kf_bf + (size_t)b * HDIM * LSEQ;
    const int* mrow = mask + (size_t)b * LSEQ;

    const int tid  = threadIdx.x;
    const int warp = tid >> 5, lane = tid & 31;
    const int g = lane >> 2, tg = lane & 3;
    const int wl = (warp & 1) * 64;
    const int wn = (warp >> 1) * 32;

    const int lr   = lane & 7;
    const int koff = lr + ((lane & 16) ? 8 : 0);
    const int coff = (lane & 8) ? 8 : 0;
    const int kb   = lr + ((lane & 8) ? 8 : 0);
    const int cb   = (lane & 16) ? 8 : 0;

    // stage all K=128 rows of both tiles, one group, one wait
    #pragma unroll
    for (int it = 0; it < 8; it++) {
        int idx = tid + 256 * it;           // 0..2047
        int k  = idx >> 4;                  // 0..127
        int c8 = (idx & 15) << 3;           // 0..120
        cp16(Qs + k * GSK + c8, A  + (size_t)k * LSEQ + l0 + c8);
        cp16(Ks + k * GSK + c8, Bm + (size_t)k * LSEQ + m0 + c8);
    }
    asm volatile("cp.async.commit_group;");

    float acc[4][4][4];
    #pragma unroll
    for (int i = 0; i < 4; i++)
        #pragma unroll
        for (int j = 0; j < 4; j++)
            #pragma unroll
            for (int c = 0; c < 4; c++) acc[i][j][c] = 0.f;

    asm volatile("cp.async.wait_group 0;");
    __syncthreads();

    #pragma unroll
    for (int ks = 0; ks < 8; ks++) {
        const int k0 = ks * 16;
        uint32_t a[4][4];
        #pragma unroll
        for (int i = 0; i < 4; i++) {
            uint32_t addr = sptr(Qs + (k0 + koff) * GSK + wl + 16 * i + coff);
            asm volatile(
                "ldmatrix.sync.aligned.m8n8.x4.trans.shared.b16 {%0,%1,%2,%3}, [%4];"
                : "=r"(a[i][0]), "=r"(a[i][1]), "=r"(a[i][2]), "=r"(a[i][3])
                : "r"(addr));
        }
        uint32_t bfr[2][4];
        #pragma unroll
        for (int jj = 0; jj < 2; jj++) {
            uint32_t addr = sptr(Ks + (k0 + kb) * GSK + wn + 16 * jj + cb);
            asm volatile(
                "ldmatrix.sync.aligned.m8n8.x4.trans.shared.b16 {%0,%1,%2,%3}, [%4];"
                : "=r"(bfr[jj][0]), "=r"(bfr[jj][1]), "=r"(bfr[jj][2]), "=r"(bfr[jj][3])
                : "r"(addr));
        }
        #pragma unroll
        for (int i = 0; i < 4; i++)
            #pragma unroll
            for (int j = 0; j < 4; j++) {
                uint32_t b0 = bfr[j >> 1][2 * (j & 1)];
                uint32_t b1 = bfr[j >> 1][2 * (j & 1) + 1];
                asm volatile(
                    "mma.sync.aligned.m16n8k16.row.col.f32.bf16.bf16.f32 "
                    "{%0,%1,%2,%3},{%4,%5,%6,%7},{%8,%9},{%0,%1,%2,%3};"
                    : "+f"(acc[i][j][0]), "+f"(acc[i][j][1]),
                      "+f"(acc[i][j][2]), "+f"(acc[i][j][3])
                    : "r"(a[i][0]), "r"(a[i][1]), "r"(a[i][2]), "r"(a[i][3]),
                      "r"(b0), "r"(b1));
            }
    }

    #pragma unroll
    for (int i = 0; i < 4; i++) {
        int row0 = l0 + wl + i * 16 + g;
        if (WRITE) {
            float inv0 = 1.f / g_rowsum[b * LSEQ + row0    ];
            float inv1 = 1.f / g_rowsum[b * LSEQ + row0 + 8];
            #pragma unroll
            for (int j = 0; j < 4; j++) {
                int col = m0 + wn + j * 8 + 2 * tg;
                int mv0 = mrow[col], mv1 = mrow[col + 1];
                float p00 = mv0 ? __expf(acc[i][j][0] * INV_SQRT_DK) : 0.f;
                float p01 = mv1 ? __expf(acc[i][j][1] * INV_SQRT_DK) : 0.f;
                float p10 = mv0 ? __expf(acc[i][j][2] * INV_SQRT_DK) : 0.f;
                float p11 = mv1 ? __expf(acc[i][j][3] * INV_SQRT_DK) : 0.f;
                *(float2*)(out + ((size_t)b * LSEQ + row0    ) * LSEQ + col) =
                    make_float2(p00 * inv0, p01 * inv0);
                *(float2*)(out + ((size_t)b * LSEQ + row0 + 8) * LSEQ + col) =
                    make_float2(p10 * inv1, p11 * inv1);
            }
        } else {
            float rs0 = 0.f, rs1 = 0.f;
            #pragma unroll
            for (int j = 0; j < 4; j++) {
                int col = m0 + wn + j * 8 + 2 * tg;
                int mv0 = mrow[col], mv1 = mrow[col + 1];
                float p00 = mv0 ? __expf(acc[i][j][0] * INV_SQRT_DK) : 0.f;
                float p01 = mv1 ? __expf(acc[i][j][1] * INV_SQRT_DK) : 0.f;
                float p10 = mv0 ? __expf(acc[i][j][2] * INV_SQRT_DK) : 0.f;
                float p11 = mv1 ? __expf(acc[i][j][3] * INV_SQRT_DK) : 0.f;
                rs0 += p00 + p01;
                rs1 += p10 + p11;
            }
            rs0 += __shfl_xor_sync(0xffffffffu, rs0, 1);
            rs0 += __shfl_xor_sync(0xffffffffu, rs0, 2);
            rs1 += __shfl_xor_sync(0xffffffffu, rs1, 1);
            rs1 += __shfl_xor_sync(0xffffffffu, rs1, 2);
            if (tg == 0) {
                atomicAdd(&g_rowsum[b * LSEQ + row0    ], rs0);
                atomicAdd(&g_rowsum[b * LSEQ + row0 + 8], rs1);
            }
        }
    }
}

// ---------------- launch ----------------
extern "C" void kernel_launch(void* const* d_in, const int* in_sizes, int n_in,
                              void* d_out, int out_size)
{
    const float* query   = (const float*)d_in[0];
    const float* key     = (const float*)d_in[1];
    const int*   mask    = (const int*)  d_in[2];
    const float* Wq      = (const float*)d_in[3];
    const float* bq      = (const float*)d_in[4];
    const float* Wk      = (const float*)d_in[5];
    const float* bk      = (const float*)d_in[6];
    const float* qW1     = (const float*)d_in[7];
    const float* qb1     = (const float*)d_in[8];
    const float* qW2     = (const float*)d_in[9];
    const float* qb2     = (const float*)d_in[10];
    const float* kW1     = (const float*)d_in[11];
    const float* kb1     = (const float*)d_in[12];
    const float* kW2     = (const float*)d_in[13];
    const float* kb2     = (const float*)d_in[14];
    const float* q_noise = (const float*)d_in[15];
    const float* k_noise = (const float*)d_in[16];
    float* out = (float*)d_out;

    cudaFuncSetAttribute(proj_tc, cudaFuncAttributeMaxDynamicSharedMemorySize,
                         PROJ_SMEM_BYTES);
    cudaFuncSetAttribute(selector_tc, cudaFuncAttributeMaxDynamicSharedMemorySize,
                         SELG_SMEM_BYTES);
    cudaFuncSetAttribute(gemm_scores_bf16<0>, cudaFuncAttributeMaxDynamicSharedMemorySize,
                         GEMM_SMEM_BYTES);
    cudaFuncSetAttribute(gemm_scores_bf16<1>, cudaFuncAttributeMaxDynamicSharedMemorySize,
                         GEMM_SMEM_BYTES);

    proj_tc<<<dim3(64, 2), 256, PROJ_SMEM_BYTES>>>(query, key, Wq, bq, Wk, bk);
    fft_fwd_kernel<<<256, FFT_NT>>>();
    selector_tc<<<dim3((FLEN + 63) / 64, BATCH, 2), 256, SELG_SMEM_BYTES>>>(
        qW1, qb1, qW2, qb2, kW1, kb1, kW2, kb2, q_noise, k_noise);
    fft_inv_kernel<<<256, FFT_NT>>>();
    gemm_scores_bf16<0><<<dim3(32, 32, BATCH), 256, GEMM_SMEM_BYTES>>>(out, mask);
    gemm_scores_bf16<1><<<dim3(32, 32, BATCH), 256, GEMM_SMEM_BYTES>>>(out, mask);
}

// round 15
// speedup vs baseline: 6.3661x; 1.0002x over previous
#include <cuda_runtime.h>
#include <cuda_bf16.h>
#include <cstdint>

#define BATCH 2
#define LSEQ 4096
#define DMODEL 768
#define HDIM 128
#define FLEN 2049
#define INV_SQRT_DK 0.08838834764831845f
#define GEPS 1e-9f
#define PI_F 3.14159265358979323846f

// ---------------- scratch ----------------
__device__ float  g_q [BATCH*HDIM*LSEQ];
__device__ float  g_k [BATCH*HDIM*LSEQ];
__device__ float2 g_Qf[BATCH*HDIM*FLEN];
__device__ float2 g_Kf[BATCH*HDIM*FLEN];
__device__ float  g_ReT[2*BATCH*FLEN*HDIM];
__device__ float  g_zq[BATCH*FLEN];
__device__ float  g_zk[BATCH*FLEN];
__device__ __nv_bfloat16 g_qf_bf[BATCH*HDIM*LSEQ];
__device__ __nv_bfloat16 g_kf_bf[BATCH*HDIM*LSEQ];
__device__ float  g_rowsum[BATCH*LSEQ];

__device__ __forceinline__ uint32_t sptr(const void* p) {
    return (uint32_t)__cvta_generic_to_shared(p);
}
__device__ __forceinline__ void cp16(void* smem_dst, const void* gmem_src) {
    asm volatile("cp.async.ca.shared.global [%0], [%1], 16;"
                 :: "r"(sptr(smem_dst)), "l"(gmem_src));
}

// ---------------- projection GEMM: tf32 mma + 3-stage cp.async ----------------
#define PROJ_STAGES 3
#define PROJ_BK 32
#define PROJ_KP 36
#define PROJ_MAT (128 * PROJ_KP)
#define PROJ_SMEM_FLOATS (PROJ_STAGES * PROJ_MAT * 2)
#define PROJ_SMEM_BYTES (PROJ_SMEM_FLOATS * 4)

__global__ __launch_bounds__(256) void proj_tc(
    const float* __restrict__ query, const float* __restrict__ key,
    const float* __restrict__ Wq, const float* __restrict__ bq,
    const float* __restrict__ Wk, const float* __restrict__ bk)
{
    extern __shared__ float dsm[];
    float* Wbase = dsm;
    float* Xbase = dsm + PROJ_STAGES * PROJ_MAT;

    const int tensor = blockIdx.y;
    const float* X  = tensor ? key : query;
    const float* W  = tensor ? Wk  : Wq;
    const float* bi = tensor ? bk  : bq;
    float* dst = tensor ? g_k : g_q;

    const int l0 = blockIdx.x * 128;
    const int tid  = threadIdx.x;
    const int warp = tid >> 5, lane = tid & 31;
    const int g = lane >> 2, tg = lane & 3;
    const int wd = (warp & 1) * 64;
    const int wn = (warp >> 1) * 32;

    float acc[4][4][4];
    #pragma unroll
    for (int i = 0; i < 4; i++)
        #pragma unroll
        for (int j = 0; j < 4; j++)
            #pragma unroll
            for (int c = 0; c < 4; c++) acc[i][j][c] = 0.f;

    auto load_stage = [&](int kc, int st) {
        const int k0 = kc * PROJ_BK;
        float* Ws = Wbase + st * PROJ_MAT;
        float* Xs = Xbase + st * PROJ_MAT;
        #pragma unroll
        for (int it = 0; it < 4; it++) {
            int idx = tid + 256 * it;
            int row = idx >> 3;
            int seg = (idx & 7) << 2;
            cp16(Ws + row * PROJ_KP + seg, W + (size_t)row * DMODEL + k0 + seg);
            cp16(Xs + row * PROJ_KP + seg, X + (size_t)(l0 + row) * DMODEL + k0 + seg);
        }
        asm volatile("cp.async.commit_group;");
    };

    load_stage(0, 0);
    load_stage(1, 1);

    const int NCHUNK = DMODEL / PROJ_BK;
    #pragma unroll 1
    for (int kc = 0; kc < NCHUNK; kc++) {
        const int st = kc % PROJ_STAGES;
        asm volatile("cp.async.wait_group 1;");
        __syncthreads();
        if (kc + 2 < NCHUNK) load_stage(kc + 2, (kc + 2) % PROJ_STAGES);

        const float* Ws = Wbase + st * PROJ_MAT;
        const float* Xs = Xbase + st * PROJ_MAT;

        #pragma unroll
        for (int ks = 0; ks < 4; ks++) {
            const int k = ks * 8;
            uint32_t a[4][4], bf[4][2];
            #pragma unroll
            for (int i = 0; i < 4; i++) {
                int d = wd + i * 16 + g;
                a[i][0] = __float_as_uint(Ws[(d    ) * PROJ_KP + k + tg    ]);
                a[i][1] = __float_as_uint(Ws[(d + 8) * PROJ_KP + k + tg    ]);
                a[i][2] = __float_as_uint(Ws[(d    ) * PROJ_KP + k + tg + 4]);
                a[i][3] = __float_as_uint(Ws[(d + 8) * PROJ_KP + k + tg + 4]);
            }
            #pragma unroll
            for (int j = 0; j < 4; j++) {
                int n = wn + j * 8 + g;
                bf[j][0] = __float_as_uint(Xs[n * PROJ_KP + k + tg    ]);
                bf[j][1] = __float_as_uint(Xs[n * PROJ_KP + k + tg + 4]);
            }
            #pragma unroll
            for (int i = 0; i < 4; i++)
                #pragma unroll
                for (int j = 0; j < 4; j++) {
                    asm volatile(
                        "mma.sync.aligned.m16n8k8.row.col.f32.tf32.tf32.f32 "
                        "{%0,%1,%2,%3},{%4,%5,%6,%7},{%8,%9},{%0,%1,%2,%3};"
                        : "+f"(acc[i][j][0]), "+f"(acc[i][j][1]),
                          "+f"(acc[i][j][2]), "+f"(acc[i][j][3])
                        : "r"(a[i][0]), "r"(a[i][1]), "r"(a[i][2]), "r"(a[i][3]),
                          "r"(bf[j][0]), "r"(bf[j][1]));
                }
        }
        __syncthreads();
    }

    #pragma unroll
    for (int i = 0; i < 4; i++) {
        int d0 = wd + i * 16 + g;
        float bv0 = bi[d0], bv1 = bi[d0 + 8];
        #pragma unroll
        for (int j = 0; j < 4; j++) {
            int gl = l0 + wn + j * 8 + 2 * tg;
            int b  = gl >> 12;
            int l  = gl & 4095;
            float* o0 = dst + (size_t)((b << 7) + d0    ) * LSEQ + l;
            float* o1 = dst + (size_t)((b << 7) + d0 + 8) * LSEQ + l;
            *(float2*)o0 = make_float2(acc[i][j][0] + bv0, acc[i][j][1] + bv0);
            *(float2*)o1 = make_float2(acc[i][j][2] + bv1, acc[i][j][3] + bv1);
        }
    }
}

// ---------------- radix-4 4096-pt FFT ----------------
#define FFT_NT 512
__device__ __forceinline__ void fill_tw(float2* tw, int tid)
{
    for (int j = tid; j < 1024; j += FFT_NT) {
        float ang = -PI_F * (float)j / 2048.0f;
        float s, c;
        __sincosf(ang, &s, &c);
        tw[j] = make_float2(c, s);
    }
}

__device__ __forceinline__ float2 cmul(float2 a, float2 b) {
    return make_float2(a.x*b.x - a.y*b.y, a.x*b.y + a.y*b.x);
}

__device__ __forceinline__ int dr12(int i) {
    unsigned y = __brev((unsigned)i) >> 20;
    return (int)(((y & 0x555u) << 1) | ((y >> 1) & 0x555u));
}

__device__ __forceinline__ void fft4096_r4(float2* s, const float2* tw, int tid, bool inv)
{
    #pragma unroll 1
    for (int st = 0; st < 6; st++) {
        const int twoSt = 2 * st;
        const int L = 1 << twoSt;
        const int shift = 10 - twoSt;
        #pragma unroll
        for (int tt = 0; tt < 1024 / FFT_NT; tt++) {
            int t = tid + tt * FFT_NT;
            int j  = t & (L - 1);
            int i0 = ((t >> twoSt) << (twoSt + 2)) + j;
            int e  = j << shift;
            float2 w1 = tw[e];
            if (inv) w1.y = -w1.y;
            float2 w2 = cmul(w1, w1);
            float2 w3 = cmul(w1, w2);

            float2 u0 = s[i0];
            float2 u1 = cmul(s[i0 + L],   w1);
            float2 u2 = cmul(s[i0 + 2*L], w2);
            float2 u3 = cmul(s[i0 + 3*L], w3);

            float2 v0 = make_float2(u0.x + u2.x, u0.y + u2.y);
            float2 v1 = make_float2(u0.x - u2.x, u0.y - u2.y);
            float2 v2 = make_float2(u1.x + u3.x, u1.y + u3.y);
            float2 v3 = make_float2(u1.x - u3.x, u1.y - u3.y);

            s[i0]       = make_float2(v0.x + v2.x, v0.y + v2.y);
            s[i0 + 2*L] = make_float2(v0.x - v2.x, v0.y - v2.y);
            if (!inv) {
                s[i0 + L]   = make_float2(v1.x + v3.y, v1.y - v3.x);
                s[i0 + 3*L] = make_float2(v1.x - v3.y, v1.y + v3.x);
            } else {
                s[i0 + L]   = make_float2(v1.x - v3.y, v1.y + v3.x);
                s[i0 + 3*L] = make_float2(v1.x + v3.y, v1.y - v3.x);
            }
        }
        __syncthreads();
    }
}

// forward FFT + zero rowsums (first 16 blocks) + freq-major real parts
__global__ __launch_bounds__(FFT_NT) void fft_fwd_kernel()
{
    __shared__ float2 s[4096];
    __shared__ float2 tw[1024];
    const int blk = blockIdx.x;
    const int tensor = blk >> 7;
    const int pr = blk & 127;
    const int b = pr >> 6;
    const int j = pr & 63;
    const int row0 = b * 128 + 2 * j;
    const float* src0 = (tensor ? g_k : g_q) + (size_t)row0 * LSEQ;
    const float* src1 = src0 + LSEQ;
    float2* dst0 = (tensor ? g_Kf : g_Qf) + (size_t)row0 * FLEN;
    float2* dst1 = dst0 + FLEN;
    float* rt = g_ReT + ((size_t)(tensor * BATCH + b) * FLEN) * HDIM;
    const int tid = threadIdx.x;

    if (blk < 16) g_rowsum[blk * FFT_NT + tid] = 0.f;

    fill_tw(tw, tid);
    for (int i = tid; i < 4096; i += FFT_NT) {
        s[dr12(i)] = make_float2(src0[i], src1[i]);
    }
    __syncthreads();
    fft4096_r4(s, tw, tid, false);

    for (int f = tid; f < FLEN; f += FFT_NT) {
        float2 cf = s[f];
        float2 cn = s[(4096 - f) & 4095];
        float re0 = 0.5f * (cf.x + cn.x);
        float re1 = 0.5f * (cf.y + cn.y);
        dst0[f] = make_float2(re0, 0.5f * (cf.y - cn.y));
        dst1[f] = make_float2(re1, 0.5f * (cn.x - cf.x));
        rt[(size_t)f * HDIM + 2 * j    ] = re0;
        rt[(size_t)f * HDIM + 2 * j + 1] = re1;
    }
}

// ---------------- selector: tf32 tensor-core MLP ----------------
#define SELG_KP 132
#define SELG_AS (64 * SELG_KP)
#define SELG_BS (64 * SELG_KP)
#define SELG_SMEM_BYTES ((SELG_AS + SELG_BS) * 4)

__global__ __launch_bounds__(256) void selector_tc(
    const float* __restrict__ qW1, const float* __restrict__ qb1,
    const float* __restrict__ qW2, const float* __restrict__ qb2,
    const float* __restrict__ kW1, const float* __restrict__ kb1,
    const float* __restrict__ kW2, const float* __restrict__ kb2,
    const float* __restrict__ q_noise, const float* __restrict__ k_noise)
{
    extern __shared__ float ssm[];
    float* As  = ssm;
    float* Bs  = ssm + SELG_AS;
    float* h1s = ssm;
    __shared__ float lgs[64][2];

    const int tile = blockIdx.x;
    const int b = blockIdx.y;
    const int tensor = blockIdx.z;
    const int f0 = tile * 64;
    const float* ReT = g_ReT + ((size_t)(tensor * BATCH + b) * FLEN) * HDIM;
    const float* W1 = tensor ? kW1 : qW1;
    const float* b1 = tensor ? kb1 : qb1;
    const float* W2 = tensor ? kW2 : qW2;
    const float* b2 = tensor ? kb2 : qb2;
    const float* nz = tensor ? k_noise : q_noise;
    float* z = tensor ? g_zk : g_zq;

    const int tid  = threadIdx.x;
    const int warp = tid >> 5, lane = tid & 31;
    const int g = lane >> 2, tg = lane & 3;
    const int wu = (warp & 1) * 32;
    const int wf = (warp >> 1) * 16;

    #pragma unroll
    for (int it = 0; it < 8; it++) {
        int idx = tid + 256 * it;
        int row = idx >> 5;
        int seg = (idx & 31) << 2;
        cp16(As + row * SELG_KP + seg, W1 + row * 128 + seg);
        int f = f0 + row;
        if (f < FLEN) {
            cp16(Bs + row * SELG_KP + seg, ReT + (size_t)f * HDIM + seg);
        } else {
            *(float4*)(Bs + row * SELG_KP + seg) = make_float4(0.f, 0.f, 0.f, 0.f);
        }
    }
    asm volatile("cp.async.commit_group;");
    asm volatile("cp.async.wait_group 0;");
    __syncthreads();

    float acc[2][2][4];
    #pragma unroll
    for (int i = 0; i < 2; i++)
        #pragma unroll
        for (int j = 0; j < 2; j++)
            #pragma unroll
            for (int c = 0; c < 4; c++) acc[i][j][c] = 0.f;

    #pragma unroll
    for (int ks = 0; ks < 16; ks++) {
        const int k = ks * 8;
        uint32_t a[2][4], bf[2][2];
        #pragma unroll
        for (int i = 0; i < 2; i++) {
            int u = wu + i * 16 + g;
            a[i][0] = __float_as_uint(As[(u    ) * SELG_KP + k + tg    ]);
            a[i][1] = __float_as_uint(As[(u + 8) * SELG_KP + k + tg    ]);
            a[i][2] = __float_as_uint(As[(u    ) * SELG_KP + k + tg + 4]);
            a[i][3] = __float_as_uint(As[(u + 8) * SELG_KP + k + tg + 4]);
        }
        #pragma unroll
        for (int j = 0; j < 2; j++) {
            int n = wf + j * 8 + g;
            bf[j][0] = __float_as_uint(Bs[n * SELG_KP + k + tg    ]);
            bf[j][1] = __float_as_uint(Bs[n * SELG_KP + k + tg + 4]);
        }
        #pragma unroll
        for (int i = 0; i < 2; i++)
            #pragma unroll
            for (int j = 0; j < 2; j++) {
                asm volatile(
                    "mma.sync.aligned.m16n8k8.row.col.f32.tf32.tf32.f32 "
                    "{%0,%1,%2,%3},{%4,%5,%6,%7},{%8,%9},{%0,%1,%2,%3};"
                    : "+f"(acc[i][j][0]), "+f"(acc[i][j][1]),
                      "+f"(acc[i][j][2]), "+f"(acc[i][j][3])
                    : "r"(a[i][0]), "r"(a[i][1]), "r"(a[i][2]), "r"(a[i][3]),
                      "r"(bf[j][0]), "r"(bf[j][1]));
            }
    }
    __syncthreads();

    #pragma unroll
    for (int i = 0; i < 2; i++) {
        int u0 = wu + i * 16 + g;
        float bv0 = b1[u0], bv1 = b1[u0 + 8];
        #pragma unroll
        for (int j = 0; j < 2; j++) {
            int f = wf + j * 8 + 2 * tg;
            h1s[(f    ) * 65 + u0    ] = fmaxf(acc[i][j][0] + bv0, 0.f);
            h1s[(f + 1) * 65 + u0    ] = fmaxf(acc[i][j][1] + bv0, 0.f);
            h1s[(f    ) * 65 + u0 + 8] = fmaxf(acc[i][j][2] + bv1, 0.f);
            h1s[(f + 1) * 65 + u0 + 8] = fmaxf(acc[i][j][3] + bv1, 0.f);
        }
    }
    __syncthreads();

    if (tid < 128) {
        int fl = tid >> 1, c = tid & 1;
        int f = f0 + fl;
        if (f < FLEN) {
            float acc2 = b2[c];
            const float* w2 = W2 + c * 64;
            const float* h = h1s + fl * 65;
            #pragma unroll 16
            for (int u = 0; u < 64; u++) acc2 = fmaf(h[u], w2[u], acc2);
            float n = nz[((size_t)b * FLEN + f) * 2 + c];
            lgs[fl][c] = acc2 + (-logf(-logf(n + GEPS) + GEPS));
        }
    }
    __syncthreads();
    if (tid < 64) {
        int f = f0 + tid;
        if (f < FLEN) z[b * FLEN + f] = 1.f / (1.f + expf(lgs[tid][0] - lgs[tid][1]));
    }
}

// inverse FFT; store bf16.
__global__ __launch_bounds__(FFT_NT) void fft_inv_kernel()
{
    __shared__ float2 s[4096];
    __shared__ float2 tw[1024];
    const int blk = blockIdx.x;
    const int tensor = blk >> 7;
    const int pr = blk & 127;
    const int b = pr >> 6;
    const int j = pr & 63;
    const int row0 = b * 128 + 2 * j;
    const float2* src0 = (tensor ? g_Kf : g_Qf) + (size_t)row0 * FLEN;
    const float2* src1 = src0 + FLEN;
    const float* z = (tensor ? g_zk : g_zq) + (size_t)b * FLEN;
    __nv_bfloat16* dst0 = (tensor ? g_kf_bf : g_qf_bf) + (size_t)row0 * LSEQ;
    __nv_bfloat16* dst1 = dst0 + LSEQ;
    const int tid = threadIdx.x;

    fill_tw(tw, tid);
    for (int i = tid; i < 4096; i += FFT_NT) {
        int f = (i <= 2048) ? i : (4096 - i);
        float zz = z[f];
        float2 a = src0[f];
        float2 bb = src1[f];
        if (i > 2048) { a.y = -a.y; bb.y = -bb.y; }
        a.x *= zz; a.y *= zz; bb.x *= zz; bb.y *= zz;
        s[dr12(i)] = make_float2(a.x - bb.y, a.y + bb.x);
    }
    __syncthreads();
    fft4096_r4(s, tw, tid, true);
    const float inv = 1.f / 4096.f;
    for (int i = tid; i < 4096; i += FFT_NT) {
        float2 v = s[i];
        dst0[i] = __float2bfloat16(v.x * inv);
        dst1[i] = __float2bfloat16(v.y * inv);
    }
}

// ---------------- scores GEMM: single-stage full-K smem ----------------
// Pass 1 (WRITE=0): 4 m-tiles per block, A staged once, rowsums only.
// Pass 2 (WRITE=1): 1 m-tile per block, normalized write (identical to R13).
#define GSK 136
#define GS_Q 0
#define GS_K (128 * GSK)
#define GEMM_SMEM_BYTES (2 * 128 * GSK * 2)

template<int WRITE>
__global__ __launch_bounds__(256) void gemm_scores_bf16(float* __restrict__ out,
                                                        const int* __restrict__ mask)
{
    extern __shared__ __nv_bfloat16 gsm[];
    __nv_bfloat16* Qs = gsm + GS_Q;   // [k][l] stride 136
    __nv_bfloat16* Ks = gsm + GS_K;   // [k][m] stride 136

    const int NMT = WRITE ? 1 : 4;

    const int b  = blockIdx.z;
    const int l0 = blockIdx.y * 128;
    const __nv_bfloat16* A  = g_qf_bf + (size_t)b * HDIM * LSEQ;
    const __nv_bfloat16* Bm = g_kf_bf + (size_t)b * HDIM * LSEQ;
    const int* mrow = mask + (size_t)b * LSEQ;

    const int tid  = threadIdx.x;
    const int warp = tid >> 5, lane = tid & 31;
    const int g = lane >> 2, tg = lane & 3;
    const int wl = (warp & 1) * 64;
    const int wn = (warp >> 1) * 32;

    const int lr   = lane & 7;
    const int koff = lr + ((lane & 16) ? 8 : 0);
    const int coff = (lane & 8) ? 8 : 0;
    const int kb   = lr + ((lane & 8) ? 8 : 0);
    const int cb   = (lane & 16) ? 8 : 0;

    // stage A once (depends only on l0)
    #pragma unroll
    for (int it = 0; it < 8; it++) {
        int idx = tid + 256 * it;           // 0..2047
        int k  = idx >> 4;                  // 0..127
        int c8 = (idx & 15) << 3;           // 0..120
        cp16(Qs + k * GSK + c8, A + (size_t)k * LSEQ + l0 + c8);
    }

    float rs[4][2];
    #pragma unroll
    for (int i = 0; i < 4; i++) { rs[i][0] = 0.f; rs[i][1] = 0.f; }

    #pragma unroll 1
    for (int mt = 0; mt < NMT; mt++) {
        const int m0 = (blockIdx.x * NMT + mt) * 128;

        // stage B tile for this m0
        #pragma unroll
        for (int it = 0; it < 8; it++) {
            int idx = tid + 256 * it;
            int k  = idx >> 4;
            int c8 = (idx & 15) << 3;
            cp16(Ks + k * GSK + c8, Bm + (size_t)k * LSEQ + m0 + c8);
        }
        asm volatile("cp.async.commit_group;");
        asm volatile("cp.async.wait_group 0;");
        __syncthreads();

        float acc[4][4][4];
        #pragma unroll
        for (int i = 0; i < 4; i++)
            #pragma unroll
            for (int j = 0; j < 4; j++)
                #pragma unroll
                for (int c = 0; c < 4; c++) acc[i][j][c] = 0.f;

        #pragma unroll
        for (int ks = 0; ks < 8; ks++) {
            const int k0 = ks * 16;
            uint32_t a[4][4];
            #pragma unroll
            for (int i = 0; i < 4; i++) {
                uint32_t addr = sptr(Qs + (k0 + koff) * GSK + wl + 16 * i + coff);
                asm volatile(
                    "ldmatrix.sync.aligned.m8n8.x4.trans.shared.b16 {%0,%1,%2,%3}, [%4];"
                    : "=r"(a[i][0]), "=r"(a[i][1]), "=r"(a[i][2]), "=r"(a[i][3])
                    : "r"(addr));
            }
            uint32_t bfr[2][4];
            #pragma unroll
            for (int jj = 0; jj < 2; jj++) {
                uint32_t addr = sptr(Ks + (k0 + kb) * GSK + wn + 16 * jj + cb);
                asm volatile(
                    "ldmatrix.sync.aligned.m8n8.x4.trans.shared.b16 {%0,%1,%2,%3}, [%4];"
                    : "=r"(bfr[jj][0]), "=r"(bfr[jj][1]), "=r"(bfr[jj][2]), "=r"(bfr[jj][3])
                    : "r"(addr));
            }
            #pragma unroll
            for (int i = 0; i < 4; i++)
                #pragma unroll
                for (int j = 0; j < 4; j++) {
                    uint32_t b0 = bfr[j >> 1][2 * (j & 1)];
                    uint32_t b1 = bfr[j >> 1][2 * (j & 1) + 1];
                    asm volatile(
                        "mma.sync.aligned.m16n8k16.row.col.f32.bf16.bf16.f32 "
                        "{%0,%1,%2,%3},{%4,%5,%6,%7},{%8,%9},{%0,%1,%2,%3};"
                        : "+f"(acc[i][j][0]), "+f"(acc[i][j][1]),
                          "+f"(acc[i][j][2]), "+f"(acc[i][j][3])
                        : "r"(a[i][0]), "r"(a[i][1]), "r"(a[i][2]), "r"(a[i][3]),
                          "r"(b0), "r"(b1));
                }
        }

        #pragma unroll
        for (int i = 0; i < 4; i++) {
            int row0 = l0 + wl + i * 16 + g;
            if (WRITE) {
                float inv0 = 1.f / g_rowsum[b * LSEQ + row0    ];
                float inv1 = 1.f / g_rowsum[b * LSEQ + row0 + 8];
                #pragma unroll
                for (int j = 0; j < 4; j++) {
                    int col = m0 + wn + j * 8 + 2 * tg;
                    int mv0 = mrow[col], mv1 = mrow[col + 1];
                    float p00 = mv0 ? __expf(acc[i][j][0] * INV_SQRT_DK) : 0.f;
                    float p01 = mv1 ? __expf(acc[i][j][1] * INV_SQRT_DK) : 0.f;
                    float p10 = mv0 ? __expf(acc[i][j][2] * INV_SQRT_DK) : 0.f;
                    float p11 = mv1 ? __expf(acc[i][j][3] * INV_SQRT_DK) : 0.f;
                    *(float2*)(out + ((size_t)b * LSEQ + row0    ) * LSEQ + col) =
                        make_float2(p00 * inv0, p01 * inv0);
                    *(float2*)(out + ((size_t)b * LSEQ + row0 + 8) * LSEQ + col) =
                        make_float2(p10 * inv1, p11 * inv1);
                }
            } else {
                #pragma unroll
                for (int j = 0; j < 4; j++) {
                    int col = m0 + wn + j * 8 + 2 * tg;
                    int mv0 = mrow[col], mv1 = mrow[col + 1];
                    float p00 = mv0 ? __expf(acc[i][j][0] * INV_SQRT_DK) : 0.f;
                    float p01 = mv1 ? __expf(acc[i][j][1] * INV_SQRT_DK) : 0.f;
                    float p10 = mv0 ? __expf(acc[i][j][2] * INV_SQRT_DK) : 0.f;
                    float p11 = mv1 ? __expf(acc[i][j][3] * INV_SQRT_DK) : 0.f;
                    rs[i][0] += p00 + p01;
                    rs[i][1] += p10 + p11;
                }
            }
        }
        if (!WRITE && mt + 1 < NMT) __syncthreads();   // Ks reads done before restage
    }

    if (!WRITE) {
        #pragma unroll
        for (int i = 0; i < 4; i++) {
            int row0 = l0 + wl + i * 16 + g;
            float rs0 = rs[i][0], rs1 = rs[i][1];
            rs0 += __shfl_xor_sync(0xffffffffu, rs0, 1);
            rs0 += __shfl_xor_sync(0xffffffffu, rs0, 2);
            rs1 += __shfl_xor_sync(0xffffffffu, rs1, 1);
            rs1 += __shfl_xor_sync(0xffffffffu, rs1, 2);
            if (tg == 0) {
                atomicAdd(&g_rowsum[b * LSEQ + row0    ], rs0);
                atomicAdd(&g_rowsum[b * LSEQ + row0 + 8], rs1);
            }
        }
    }
}

// ---------------- launch ----------------
extern "C" void kernel_launch(void* const* d_in, const int* in_sizes, int n_in,
                              void* d_out, int out_size)
{
    const float* query   = (const float*)d_in[0];
    const float* key     = (const float*)d_in[1];
    const int*   mask    = (const int*)  d_in[2];
    const float* Wq      = (const float*)d_in[3];
    const float* bq      = (const float*)d_in[4];
    const float* Wk      = (const float*)d_in[5];
    const float* bk      = (const float*)d_in[6];
    const float* qW1     = (const float*)d_in[7];
    const float* qb1     = (const float*)d_in[8];
    const float* qW2     = (const float*)d_in[9];
    const float* qb2     = (const float*)d_in[10];
    const float* kW1     = (const float*)d_in[11];
    const float* kb1     = (const float*)d_in[12];
    const float* kW2     = (const float*)d_in[13];
    const float* kb2     = (const float*)d_in[14];
    const float* q_noise = (const float*)d_in[15];
    const float* k_noise = (const float*)d_in[16];
    float* out = (float*)d_out;

    cudaFuncSetAttribute(proj_tc, cudaFuncAttributeMaxDynamicSharedMemorySize,
                         PROJ_SMEM_BYTES);
    cudaFuncSetAttribute(selector_tc, cudaFuncAttributeMaxDynamicSharedMemorySize,
                         SELG_SMEM_BYTES);
    cudaFuncSetAttribute(gemm_scores_bf16<0>, cudaFuncAttributeMaxDynamicSharedMemorySize,
                         GEMM_SMEM_BYTES);
    cudaFuncSetAttribute(gemm_scores_bf16<1>, cudaFuncAttributeMaxDynamicSharedMemorySize,
                         GEMM_SMEM_BYTES);

    proj_tc<<<dim3(64, 2), 256, PROJ_SMEM_BYTES>>>(query, key, Wq, bq, Wk, bk);
    fft_fwd_kernel<<<256, FFT_NT>>>();
    selector_tc<<<dim3((FLEN + 63) / 64, BATCH, 2), 256, SELG_SMEM_BYTES>>>(
        qW1, qb1, qW2, qb2, kW1, kb1, kW2, kb2, q_noise, k_noise);
    fft_inv_kernel<<<256, FFT_NT>>>();
    gemm_scores_bf16<0><<<dim3(8, 32, BATCH), 256, GEMM_SMEM_BYTES>>>(out, mask);
    gemm_scores_bf16<1><<<dim3(32, 32, BATCH), 256, GEMM_SMEM_BYTES>>>(out, mask);
}

// round 16
// speedup vs baseline: 6.8500x; 1.0760x over previous
#include <cuda_runtime.h>
#include <cuda_bf16.h>
#include <cstdint>

#define BATCH 2
#define LSEQ 4096
#define DMODEL 768
#define HDIM 128
#define FLEN 2049
#define INV_SQRT_DK 0.08838834764831845f
#define GEPS 1e-9f
#define PI_F 3.14159265358979323846f

// ---------------- scratch ----------------
__device__ float  g_q [BATCH*HDIM*LSEQ];
__device__ float  g_k [BATCH*HDIM*LSEQ];
__device__ float2 g_Qf[BATCH*HDIM*FLEN];
__device__ float2 g_Kf[BATCH*HDIM*FLEN];
__device__ float  g_ReT[2*BATCH*FLEN*HDIM];
__device__ float  g_zq[BATCH*FLEN];
__device__ float  g_zk[BATCH*FLEN];
__device__ __nv_bfloat16 g_qf_bf[BATCH*HDIM*LSEQ];
__device__ __nv_bfloat16 g_kf_bf[BATCH*HDIM*LSEQ];
__device__ __nv_bfloat16 g_kfc [BATCH*HDIM*LSEQ];   // mask-compacted kf
__device__ int    g_colidx[BATCH*LSEQ];
__device__ int    g_ncols[BATCH];
__device__ float  g_rowsum[BATCH*LSEQ];

__device__ __forceinline__ uint32_t sptr(const void* p) {
    return (uint32_t)__cvta_generic_to_shared(p);
}
__device__ __forceinline__ void cp16(void* smem_dst, const void* gmem_src) {
    asm volatile("cp.async.ca.shared.global [%0], [%1], 16;"
                 :: "r"(sptr(smem_dst)), "l"(gmem_src));
}

// ---------------- mask compaction (deterministic block scan) ----------------
__global__ __launch_bounds__(1024) void compact_mask(const int* __restrict__ mask)
{
    __shared__ int sums[1024];
    const int b = blockIdx.x;
    const int tid = threadIdx.x;
    const int* m = mask + (size_t)b * LSEQ;

    int loc[4], s = 0;
    #pragma unroll
    for (int i = 0; i < 4; i++) {
        loc[i] = (m[tid * 4 + i] != 0);
        s += loc[i];
    }
    sums[tid] = s;
    __syncthreads();
    for (int off = 1; off < 1024; off <<= 1) {
        int v = (tid >= off) ? sums[tid - off] : 0;
        __syncthreads();
        sums[tid] += v;
        __syncthreads();
    }
    int pos = sums[tid] - s;
    #pragma unroll
    for (int i = 0; i < 4; i++) {
        if (loc[i]) g_colidx[b * LSEQ + pos++] = tid * 4 + i;
    }
    if (tid == 1023) g_ncols[b] = sums[1023];
}

// ---------------- gather compacted kf columns ----------------
__global__ __launch_bounds__(256) void gather_kfc()
{
    const int b = blockIdx.z;
    const int d = blockIdx.y;
    const int i0 = blockIdx.x * 256 + threadIdx.x;
    const int nc = g_ncols[b];
    __nv_bfloat16 v = __float2bfloat16(0.f);
    if (i0 < nc) v = g_kf_bf[((size_t)(b * HDIM + d)) * LSEQ + g_colidx[b * LSEQ + i0]];
    g_kfc[((size_t)(b * HDIM + d)) * LSEQ + i0] = v;
}

// ---------------- projection GEMM: tf32 mma + 3-stage cp.async ----------------
#define PROJ_STAGES 3
#define PROJ_BK 32
#define PROJ_KP 36
#define PROJ_MAT (128 * PROJ_KP)
#define PROJ_SMEM_FLOATS (PROJ_STAGES * PROJ_MAT * 2)
#define PROJ_SMEM_BYTES (PROJ_SMEM_FLOATS * 4)

__global__ __launch_bounds__(256) void proj_tc(
    const float* __restrict__ query, const float* __restrict__ key,
    const float* __restrict__ Wq, const float* __restrict__ bq,
    const float* __restrict__ Wk, const float* __restrict__ bk)
{
    extern __shared__ float dsm[];
    float* Wbase = dsm;
    float* Xbase = dsm + PROJ_STAGES * PROJ_MAT;

    const int tensor = blockIdx.y;
    const float* X  = tensor ? key : query;
    const float* W  = tensor ? Wk  : Wq;
    const float* bi = tensor ? bk  : bq;
    float* dst = tensor ? g_k : g_q;

    const int l0 = blockIdx.x * 128;
    const int tid  = threadIdx.x;
    const int warp = tid >> 5, lane = tid & 31;
    const int g = lane >> 2, tg = lane & 3;
    const int wd = (warp & 1) * 64;
    const int wn = (warp >> 1) * 32;

    float acc[4][4][4];
    #pragma unroll
    for (int i = 0; i < 4; i++)
        #pragma unroll
        for (int j = 0; j < 4; j++)
            #pragma unroll
            for (int c = 0; c < 4; c++) acc[i][j][c] = 0.f;

    auto load_stage = [&](int kc, int st) {
        const int k0 = kc * PROJ_BK;
        float* Ws = Wbase + st * PROJ_MAT;
        float* Xs = Xbase + st * PROJ_MAT;
        #pragma unroll
        for (int it = 0; it < 4; it++) {
            int idx = tid + 256 * it;
            int row = idx >> 3;
            int seg = (idx & 7) << 2;
            cp16(Ws + row * PROJ_KP + seg, W + (size_t)row * DMODEL + k0 + seg);
            cp16(Xs + row * PROJ_KP + seg, X + (size_t)(l0 + row) * DMODEL + k0 + seg);
        }
        asm volatile("cp.async.commit_group;");
    };

    load_stage(0, 0);
    load_stage(1, 1);

    const int NCHUNK = DMODEL / PROJ_BK;
    #pragma unroll 1
    for (int kc = 0; kc < NCHUNK; kc++) {
        const int st = kc % PROJ_STAGES;
        asm volatile("cp.async.wait_group 1;");
        __syncthreads();
        if (kc + 2 < NCHUNK) load_stage(kc + 2, (kc + 2) % PROJ_STAGES);

        const float* Ws = Wbase + st * PROJ_MAT;
        const float* Xs = Xbase + st * PROJ_MAT;

        #pragma unroll
        for (int ks = 0; ks < 4; ks++) {
            const int k = ks * 8;
            uint32_t a[4][4], bf[4][2];
            #pragma unroll
            for (int i = 0; i < 4; i++) {
                int d = wd + i * 16 + g;
                a[i][0] = __float_as_uint(Ws[(d    ) * PROJ_KP + k + tg    ]);
                a[i][1] = __float_as_uint(Ws[(d + 8) * PROJ_KP + k + tg    ]);
                a[i][2] = __float_as_uint(Ws[(d    ) * PROJ_KP + k + tg + 4]);
                a[i][3] = __float_as_uint(Ws[(d + 8) * PROJ_KP + k + tg + 4]);
            }
            #pragma unroll
            for (int j = 0; j < 4; j++) {
                int n = wn + j * 8 + g;
                bf[j][0] = __float_as_uint(Xs[n * PROJ_KP + k + tg    ]);
                bf[j][1] = __float_as_uint(Xs[n * PROJ_KP + k + tg + 4]);
            }
            #pragma unroll
            for (int i = 0; i < 4; i++)
                #pragma unroll
                for (int j = 0; j < 4; j++) {
                    asm volatile(
                        "mma.sync.aligned.m16n8k8.row.col.f32.tf32.tf32.f32 "
                        "{%0,%1,%2,%3},{%4,%5,%6,%7},{%8,%9},{%0,%1,%2,%3};"
                        : "+f"(acc[i][j][0]), "+f"(acc[i][j][1]),
                          "+f"(acc[i][j][2]), "+f"(acc[i][j][3])
                        : "r"(a[i][0]), "r"(a[i][1]), "r"(a[i][2]), "r"(a[i][3]),
                          "r"(bf[j][0]), "r"(bf[j][1]));
                }
        }
        __syncthreads();
    }

    #pragma unroll
    for (int i = 0; i < 4; i++) {
        int d0 = wd + i * 16 + g;
        float bv0 = bi[d0], bv1 = bi[d0 + 8];
        #pragma unroll
        for (int j = 0; j < 4; j++) {
            int gl = l0 + wn + j * 8 + 2 * tg;
            int b  = gl >> 12;
            int l  = gl & 4095;
            float* o0 = dst + (size_t)((b << 7) + d0    ) * LSEQ + l;
            float* o1 = dst + (size_t)((b << 7) + d0 + 8) * LSEQ + l;
            *(float2*)o0 = make_float2(acc[i][j][0] + bv0, acc[i][j][1] + bv0);
            *(float2*)o1 = make_float2(acc[i][j][2] + bv1, acc[i][j][3] + bv1);
        }
    }
}

// ---------------- radix-4 4096-pt FFT ----------------
#define FFT_NT 512
__device__ __forceinline__ void fill_tw(float2* tw, int tid)
{
    for (int j = tid; j < 1024; j += FFT_NT) {
        float ang = -PI_F * (float)j / 2048.0f;
        float s, c;
        __sincosf(ang, &s, &c);
        tw[j] = make_float2(c, s);
    }
}

__device__ __forceinline__ float2 cmul(float2 a, float2 b) {
    return make_float2(a.x*b.x - a.y*b.y, a.x*b.y + a.y*b.x);
}

__device__ __forceinline__ int dr12(int i) {
    unsigned y = __brev((unsigned)i) >> 20;
    return (int)(((y & 0x555u) << 1) | ((y >> 1) & 0x555u));
}

__device__ __forceinline__ void fft4096_r4(float2* s, const float2* tw, int tid, bool inv)
{
    #pragma unroll 1
    for (int st = 0; st < 6; st++) {
        const int twoSt = 2 * st;
        const int L = 1 << twoSt;
        const int shift = 10 - twoSt;
        #pragma unroll
        for (int tt = 0; tt < 1024 / FFT_NT; tt++) {
            int t = tid + tt * FFT_NT;
            int j  = t & (L - 1);
            int i0 = ((t >> twoSt) << (twoSt + 2)) + j;
            int e  = j << shift;
            float2 w1 = tw[e];
            if (inv) w1.y = -w1.y;
            float2 w2 = cmul(w1, w1);
            float2 w3 = cmul(w1, w2);

            float2 u0 = s[i0];
            float2 u1 = cmul(s[i0 + L],   w1);
            float2 u2 = cmul(s[i0 + 2*L], w2);
            float2 u3 = cmul(s[i0 + 3*L], w3);

            float2 v0 = make_float2(u0.x + u2.x, u0.y + u2.y);
            float2 v1 = make_float2(u0.x - u2.x, u0.y - u2.y);
            float2 v2 = make_float2(u1.x + u3.x, u1.y + u3.y);
            float2 v3 = make_float2(u1.x - u3.x, u1.y - u3.y);

            s[i0]       = make_float2(v0.x + v2.x, v0.y + v2.y);
            s[i0 + 2*L] = make_float2(v0.x - v2.x, v0.y - v2.y);
            if (!inv) {
                s[i0 + L]   = make_float2(v1.x + v3.y, v1.y - v3.x);
                s[i0 + 3*L] = make_float2(v1.x - v3.y, v1.y + v3.x);
            } else {
                s[i0 + L]   = make_float2(v1.x - v3.y, v1.y + v3.x);
                s[i0 + 3*L] = make_float2(v1.x + v3.y, v1.y - v3.x);
            }
        }
        __syncthreads();
    }
}

// forward FFT + zero rowsums (first 16 blocks) + freq-major real parts
__global__ __launch_bounds__(FFT_NT) void fft_fwd_kernel()
{
    __shared__ float2 s[4096];
    __shared__ float2 tw[1024];
    const int blk = blockIdx.x;
    const int tensor = blk >> 7;
    const int pr = blk & 127;
    const int b = pr >> 6;
    const int j = pr & 63;
    const int row0 = b * 128 + 2 * j;
    const float* src0 = (tensor ? g_k : g_q) + (size_t)row0 * LSEQ;
    const float* src1 = src0 + LSEQ;
    float2* dst0 = (tensor ? g_Kf : g_Qf) + (size_t)row0 * FLEN;
    float2* dst1 = dst0 + FLEN;
    float* rt = g_ReT + ((size_t)(tensor * BATCH + b) * FLEN) * HDIM;
    const int tid = threadIdx.x;

    if (blk < 16) g_rowsum[blk * FFT_NT + tid] = 0.f;

    fill_tw(tw, tid);
    for (int i = tid; i < 4096; i += FFT_NT) {
        s[dr12(i)] = make_float2(src0[i], src1[i]);
    }
    __syncthreads();
    fft4096_r4(s, tw, tid, false);

    for (int f = tid; f < FLEN; f += FFT_NT) {
        float2 cf = s[f];
        float2 cn = s[(4096 - f) & 4095];
        float re0 = 0.5f * (cf.x + cn.x);
        float re1 = 0.5f * (cf.y + cn.y);
        dst0[f] = make_float2(re0, 0.5f * (cf.y - cn.y));
        dst1[f] = make_float2(re1, 0.5f * (cn.x - cf.x));
        rt[(size_t)f * HDIM + 2 * j    ] = re0;
        rt[(size_t)f * HDIM + 2 * j + 1] = re1;
    }
}

// ---------------- selector: tf32 tensor-core MLP ----------------
#define SELG_KP 132
#define SELG_AS (64 * SELG_KP)
#define SELG_BS (64 * SELG_KP)
#define SELG_SMEM_BYTES ((SELG_AS + SELG_BS) * 4)

__global__ __launch_bounds__(256) void selector_tc(
    const float* __restrict__ qW1, const float* __restrict__ qb1,
    const float* __restrict__ qW2, const float* __restrict__ qb2,
    const float* __restrict__ kW1, const float* __restrict__ kb1,
    const float* __restrict__ kW2, const float* __restrict__ kb2,
    const float* __restrict__ q_noise, const float* __restrict__ k_noise)
{
    extern __shared__ float ssm[];
    float* As  = ssm;
    float* Bs  = ssm + SELG_AS;
    float* h1s = ssm;
    __shared__ float lgs[64][2];

    const int tile = blockIdx.x;
    const int b = blockIdx.y;
    const int tensor = blockIdx.z;
    const int f0 = tile * 64;
    const float* ReT = g_ReT + ((size_t)(tensor * BATCH + b) * FLEN) * HDIM;
    const float* W1 = tensor ? kW1 : qW1;
    const float* b1 = tensor ? kb1 : qb1;
    const float* W2 = tensor ? kW2 : qW2;
    const float* b2 = tensor ? kb2 : qb2;
    const float* nz = tensor ? k_noise : q_noise;
    float* z = tensor ? g_zk : g_zq;

    const int tid  = threadIdx.x;
    const int warp = tid >> 5, lane = tid & 31;
    const int g = lane >> 2, tg = lane & 3;
    const int wu = (warp & 1) * 32;
    const int wf = (warp >> 1) * 16;

    #pragma unroll
    for (int it = 0; it < 8; it++) {
        int idx = tid + 256 * it;
        int row = idx >> 5;
        int seg = (idx & 31) << 2;
        cp16(As + row * SELG_KP + seg, W1 + row * 128 + seg);
        int f = f0 + row;
        if (f < FLEN) {
            cp16(Bs + row * SELG_KP + seg, ReT + (size_t)f * HDIM + seg);
        } else {
            *(float4*)(Bs + row * SELG_KP + seg) = make_float4(0.f, 0.f, 0.f, 0.f);
        }
    }
    asm volatile("cp.async.commit_group;");
    asm volatile("cp.async.wait_group 0;");
    __syncthreads();

    float acc[2][2][4];
    #pragma unroll
    for (int i = 0; i < 2; i++)
        #pragma unroll
        for (int j = 0; j < 2; j++)
            #pragma unroll
            for (int c = 0; c < 4; c++) acc[i][j][c] = 0.f;

    #pragma unroll
    for (int ks = 0; ks < 16; ks++) {
        const int k = ks * 8;
        uint32_t a[2][4], bf[2][2];
        #pragma unroll
        for (int i = 0; i < 2; i++) {
            int u = wu + i * 16 + g;
            a[i][0] = __float_as_uint(As[(u    ) * SELG_KP + k + tg    ]);
            a[i][1] = __float_as_uint(As[(u + 8) * SELG_KP + k + tg    ]);
            a[i][2] = __float_as_uint(As[(u    ) * SELG_KP + k + tg + 4]);
            a[i][3] = __float_as_uint(As[(u + 8) * SELG_KP + k + tg + 4]);
        }
        #pragma unroll
        for (int j = 0; j < 2; j++) {
            int n = wf + j * 8 + g;
            bf[j][0] = __float_as_uint(Bs[n * SELG_KP + k + tg    ]);
            bf[j][1] = __float_as_uint(Bs[n * SELG_KP + k + tg + 4]);
        }
        #pragma unroll
        for (int i = 0; i < 2; i++)
            #pragma unroll
            for (int j = 0; j < 2; j++) {
                asm volatile(
                    "mma.sync.aligned.m16n8k8.row.col.f32.tf32.tf32.f32 "
                    "{%0,%1,%2,%3},{%4,%5,%6,%7},{%8,%9},{%0,%1,%2,%3};"
                    : "+f"(acc[i][j][0]), "+f"(acc[i][j][1]),
                      "+f"(acc[i][j][2]), "+f"(acc[i][j][3])
                    : "r"(a[i][0]), "r"(a[i][1]), "r"(a[i][2]), "r"(a[i][3]),
                      "r"(bf[j][0]), "r"(bf[j][1]));
            }
    }
    __syncthreads();

    #pragma unroll
    for (int i = 0; i < 2; i++) {
        int u0 = wu + i * 16 + g;
        float bv0 = b1[u0], bv1 = b1[u0 + 8];
        #pragma unroll
        for (int j = 0; j < 2; j++) {
            int f = wf + j * 8 + 2 * tg;
            h1s[(f    ) * 65 + u0    ] = fmaxf(acc[i][j][0] + bv0, 0.f);
            h1s[(f + 1) * 65 + u0    ] = fmaxf(acc[i][j][1] + bv0, 0.f);
            h1s[(f    ) * 65 + u0 + 8] = fmaxf(acc[i][j][2] + bv1, 0.f);
            h1s[(f + 1) * 65 + u0 + 8] = fmaxf(acc[i][j][3] + bv1, 0.f);
        }
    }
    __syncthreads();

    if (tid < 128) {
        int fl = tid >> 1, c = tid & 1;
        int f = f0 + fl;
        if (f < FLEN) {
            float acc2 = b2[c];
            const float* w2 = W2 + c * 64;
            const float* h = h1s + fl * 65;
            #pragma unroll 16
            for (int u = 0; u < 64; u++) acc2 = fmaf(h[u], w2[u], acc2);
            float n = nz[((size_t)b * FLEN + f) * 2 + c];
            lgs[fl][c] = acc2 + (-logf(-logf(n + GEPS) + GEPS));
        }
    }
    __syncthreads();
    if (tid < 64) {
        int f = f0 + tid;
        if (f < FLEN) z[b * FLEN + f] = 1.f / (1.f + expf(lgs[tid][0] - lgs[tid][1]));
    }
}

// inverse FFT; store bf16.
__global__ __launch_bounds__(FFT_NT) void fft_inv_kernel()
{
    __shared__ float2 s[4096];
    __shared__ float2 tw[1024];
    const int blk = blockIdx.x;
    const int tensor = blk >> 7;
    const int pr = blk & 127;
    const int b = pr >> 6;
    const int j = pr & 63;
    const int row0 = b * 128 + 2 * j;
    const float2* src0 = (tensor ? g_Kf : g_Qf) + (size_t)row0 * FLEN;
    const float2* src1 = src0 + FLEN;
    const float* z = (tensor ? g_zk : g_zq) + (size_t)b * FLEN;
    __nv_bfloat16* dst0 = (tensor ? g_kf_bf : g_qf_bf) + (size_t)row0 * LSEQ;
    __nv_bfloat16* dst1 = dst0 + LSEQ;
    const int tid = threadIdx.x;

    fill_tw(tw, tid);
    for (int i = tid; i < 4096; i += FFT_NT) {
        int f = (i <= 2048) ? i : (4096 - i);
        float zz = z[f];
        float2 a = src0[f];
        float2 bb = src1[f];
        if (i > 2048) { a.y = -a.y; bb.y = -bb.y; }
        a.x *= zz; a.y *= zz; bb.x *= zz; bb.y *= zz;
        s[dr12(i)] = make_float2(a.x - bb.y, a.y + bb.x);
    }
    __syncthreads();
    fft4096_r4(s, tw, tid, true);
    const float inv = 1.f / 4096.f;
    for (int i = tid; i < 4096; i += FFT_NT) {
        float2 v = s[i];
        dst0[i] = __float2bfloat16(v.x * inv);
        dst1[i] = __float2bfloat16(v.y * inv);
    }
}

// ---------------- scores GEMM: single-stage full-K smem ----------------
// Pass 1 (WRITE=0): compacted columns only, 4 m-tiles per block, rowsums.
// Pass 2 (WRITE=1): full columns, normalized write.
#define GSK 136
#define GS_Q 0
#define GS_K (128 * GSK)
#define GEMM_SMEM_BYTES (2 * 128 * GSK * 2)

template<int WRITE>
__global__ __launch_bounds__(256) void gemm_scores_bf16(float* __restrict__ out,
                                                        const int* __restrict__ mask)
{
    extern __shared__ __nv_bfloat16 gsm[];
    __nv_bfloat16* Qs = gsm + GS_Q;
    __nv_bfloat16* Ks = gsm + GS_K;

    const int NMT = WRITE ? 1 : 4;

    const int b  = blockIdx.z;
    const int l0 = blockIdx.y * 128;
    const __nv_bfloat16* A  = g_qf_bf + (size_t)b * HDIM * LSEQ;
    const __nv_bfloat16* Bm = (WRITE ? g_kf_bf : g_kfc) + (size_t)b * HDIM * LSEQ;
    const int* mrow = mask + (size_t)b * LSEQ;
    const int nc = WRITE ? LSEQ : g_ncols[b];

    if (!WRITE && blockIdx.x * NMT * 128 >= nc) return;

    const int tid  = threadIdx.x;
    const int warp = tid >> 5, lane = tid & 31;
    const int g = lane >> 2, tg = lane & 3;
    const int wl = (warp & 1) * 64;
    const int wn = (warp >> 1) * 32;

    const int lr   = lane & 7;
    const int koff = lr + ((lane & 16) ? 8 : 0);
    const int coff = (lane & 8) ? 8 : 0;
    const int kb   = lr + ((lane & 8) ? 8 : 0);
    const int cb   = (lane & 16) ? 8 : 0;

    // stage A once
    #pragma unroll
    for (int it = 0; it < 8; it++) {
        int idx = tid + 256 * it;
        int k  = idx >> 4;
        int c8 = (idx & 15) << 3;
        cp16(Qs + k * GSK + c8, A + (size_t)k * LSEQ + l0 + c8);
    }

    float rs[4][2];
    #pragma unroll
    for (int i = 0; i < 4; i++) { rs[i][0] = 0.f; rs[i][1] = 0.f; }

    #pragma unroll 1
    for (int mt = 0; mt < NMT; mt++) {
        const int m0 = (blockIdx.x * NMT + mt) * 128;
        if (!WRITE && m0 >= nc) break;

        #pragma unroll
        for (int it = 0; it < 8; it++) {
            int idx = tid + 256 * it;
            int k  = idx >> 4;
            int c8 = (idx & 15) << 3;
            cp16(Ks + k * GSK + c8, Bm + (size_t)k * LSEQ + m0 + c8);
        }
        asm volatile("cp.async.commit_group;");
        asm volatile("cp.async.wait_group 0;");
        __syncthreads();

        float acc[4][4][4];
        #pragma unroll
        for (int i = 0; i < 4; i++)
            #pragma unroll
            for (int j = 0; j < 4; j++)
                #pragma unroll
                for (int c = 0; c < 4; c++) acc[i][j][c] = 0.f;

        #pragma unroll
        for (int ks = 0; ks < 8; ks++) {
            const int k0 = ks * 16;
            uint32_t a[4][4];
            #pragma unroll
            for (int i = 0; i < 4; i++) {
                uint32_t addr = sptr(Qs + (k0 + koff) * GSK + wl + 16 * i + coff);
                asm volatile(
                    "ldmatrix.sync.aligned.m8n8.x4.trans.shared.b16 {%0,%1,%2,%3}, [%4];"
                    : "=r"(a[i][0]), "=r"(a[i][1]), "=r"(a[i][2]), "=r"(a[i][3])
                    : "r"(addr));
            }
            uint32_t bfr[2][4];
            #pragma unroll
            for (int jj = 0; jj < 2; jj++) {
                uint32_t addr = sptr(Ks + (k0 + kb) * GSK + wn + 16 * jj + cb);
                asm volatile(
                    "ldmatrix.sync.aligned.m8n8.x4.trans.shared.b16 {%0,%1,%2,%3}, [%4];"
                    : "=r"(bfr[jj][0]), "=r"(bfr[jj][1]), "=r"(bfr[jj][2]), "=r"(bfr[jj][3])
                    : "r"(addr));
            }
            #pragma unroll
            for (int i = 0; i < 4; i++)
                #pragma unroll
                for (int j = 0; j < 4; j++) {
                    uint32_t b0 = bfr[j >> 1][2 * (j & 1)];
                    uint32_t b1 = bfr[j >> 1][2 * (j & 1) + 1];
                    asm volatile(
                        "mma.sync.aligned.m16n8k16.row.col.f32.bf16.bf16.f32 "
                        "{%0,%1,%2,%3},{%4,%5,%6,%7},{%8,%9},{%0,%1,%2,%3};"
                        : "+f"(acc[i][j][0]), "+f"(acc[i][j][1]),
                          "+f"(acc[i][j][2]), "+f"(acc[i][j][3])
                        : "r"(a[i][0]), "r"(a[i][1]), "r"(a[i][2]), "r"(a[i][3]),
                          "r"(b0), "r"(b1));
                }
        }

        #pragma unroll
        for (int i = 0; i < 4; i++) {
            int row0 = l0 + wl + i * 16 + g;
            if (WRITE) {
                float inv0 = 1.f / g_rowsum[b * LSEQ + row0    ];
                float inv1 = 1.f / g_rowsum[b * LSEQ + row0 + 8];
                #pragma unroll
                for (int j = 0; j < 4; j++) {
                    int col = m0 + wn + j * 8 + 2 * tg;
                    int mv0 = mrow[col], mv1 = mrow[col + 1];
                    float p00 = mv0 ? __expf(acc[i][j][0] * INV_SQRT_DK) : 0.f;
                    float p01 = mv1 ? __expf(acc[i][j][1] * INV_SQRT_DK) : 0.f;
                    float p10 = mv0 ? __expf(acc[i][j][2] * INV_SQRT_DK) : 0.f;
                    float p11 = mv1 ? __expf(acc[i][j][3] * INV_SQRT_DK) : 0.f;
                    *(float2*)(out + ((size_t)b * LSEQ + row0    ) * LSEQ + col) =
                        make_float2(p00 * inv0, p01 * inv0);
                    *(float2*)(out + ((size_t)b * LSEQ + row0 + 8) * LSEQ + col) =
                        make_float2(p10 * inv1, p11 * inv1);
                }
            } else {
                #pragma unroll
                for (int j = 0; j < 4; j++) {
                    int col = m0 + wn + j * 8 + 2 * tg;
                    float p00 = (col     < nc) ? __expf(acc[i][j][0] * INV_SQRT_DK) : 0.f;
                    float p01 = (col + 1 < nc) ? __expf(acc[i][j][1] * INV_SQRT_DK) : 0.f;
                    float p10 = (col     < nc) ? __expf(acc[i][j][2] * INV_SQRT_DK) : 0.f;
                    float p11 = (col + 1 < nc) ? __expf(acc[i][j][3] * INV_SQRT_DK) : 0.f;
                    rs[i][0] += p00 + p01;
                    rs[i][1] += p10 + p11;
                }
            }
        }
        if (!WRITE && mt + 1 < NMT) __syncthreads();
    }

    if (!WRITE) {
        #pragma unroll
        for (int i = 0; i < 4; i++) {
            int row0 = l0 + wl + i * 16 + g;
            float rs0 = rs[i][0], rs1 = rs[i][1];
            rs0 += __shfl_xor_sync(0xffffffffu, rs0, 1);
            rs0 += __shfl_xor_sync(0xffffffffu, rs0, 2);
            rs1 += __shfl_xor_sync(0xffffffffu, rs1, 1);
            rs1 += __shfl_xor_sync(0xffffffffu, rs1, 2);
            if (tg == 0) {
                atomicAdd(&g_rowsum[b * LSEQ + row0    ], rs0);
                atomicAdd(&g_rowsum[b * LSEQ + row0 + 8], rs1);
            }
        }
    }
}

// ---------------- launch ----------------
extern "C" void kernel_launch(void* const* d_in, const int* in_sizes, int n_in,
                              void* d_out, int out_size)
{
    const float* query   = (const float*)d_in[0];
    const float* key     = (const float*)d_in[1];
    const int*   mask    = (const int*)  d_in[2];
    const float* Wq      = (const float*)d_in[3];
    const float* bq      = (const float*)d_in[4];
    const float* Wk      = (const float*)d_in[5];
    const float* bk      = (const float*)d_in[6];
    const float* qW1     = (const float*)d_in[7];
    const float* qb1     = (const float*)d_in[8];
    const float* qW2     = (const float*)d_in[9];
    const float* qb2     = (const float*)d_in[10];
    const float* kW1     = (const float*)d_in[11];
    const float* kb1     = (const float*)d_in[12];
    const float* kW2     = (const float*)d_in[13];
    const float* kb2     = (const float*)d_in[14];
    const float* q_noise = (const float*)d_in[15];
    const float* k_noise = (const float*)d_in[16];
    float* out = (float*)d_out;

    cudaFuncSetAttribute(proj_tc, cudaFuncAttributeMaxDynamicSharedMemorySize,
                         PROJ_SMEM_BYTES);
    cudaFuncSetAttribute(selector_tc, cudaFuncAttributeMaxDynamicSharedMemorySize,
                         SELG_SMEM_BYTES);
    cudaFuncSetAttribute(gemm_scores_bf16<0>, cudaFuncAttributeMaxDynamicSharedMemorySize,
                         GEMM_SMEM_BYTES);
    cudaFuncSetAttribute(gemm_scores_bf16<1>, cudaFuncAttributeMaxDynamicSharedMemorySize,
                         GEMM_SMEM_BYTES);

    compact_mask<<<BATCH, 1024>>>(mask);
    proj_tc<<<dim3(64, 2), 256, PROJ_SMEM_BYTES>>>(query, key, Wq, bq, Wk, bk);
    fft_fwd_kernel<<<256, FFT_NT>>>();
    selector_tc<<<dim3((FLEN + 63) / 64, BATCH, 2), 256, SELG_SMEM_BYTES>>>(
        qW1, qb1, qW2, qb2, kW1, kb1, kW2, kb2, q_noise, k_noise);
    fft_inv_kernel<<<256, FFT_NT>>>();
    gather_kfc<<<dim3(LSEQ / 256, HDIM, BATCH), 256>>>();
    gemm_scores_bf16<0><<<dim3(8, 32, BATCH), 256, GEMM_SMEM_BYTES>>>(out, mask);
    gemm_scores_bf16<1><<<dim3(32, 32, BATCH), 256, GEMM_SMEM_BYTES>>>(out, mask);
}